// round 9
// baseline (speedup 1.0000x reference)
#include <cuda_runtime.h>
#include <cuda_bf16.h>
#include <math.h>

#define B_     2
#define S_     32
#define BS_    64
#define C_     128
#define HGT    24
#define WID    24
#define L_     576
#define HEADS_ 2
#define QKD_   64
#define VD_    128
#define HID_   256
#define OUTC_  128

// ---------------- scratch (static device globals; no allocation) ----------------
__device__ float g_bias[HEADS_ * L_ * L_];            // (head, i, j)  fp32, true order
__device__ float g_q[BS_ * HEADS_ * L_ * QKD_];       // [bs,h][l][d-interleaved], tf32
__device__ float g_k[BS_ * HEADS_ * L_ * QKD_];       // [bs,h][l][d-interleaved], tf32
__device__ float g_v[BS_ * HEADS_ * VD_ * L_];        // [bs,h][d][l-interleaved], tf32
__device__ float g_att[BS_ * L_ * HID_];              // [bs][l][ch-interleaved], tf32
// pre-permuted + tf32-rounded weights (k-dim interleaved within 8-blocks)
__device__ float g_wqk[2 * C_ * C_];                  // 256 x 128
__device__ float g_wv [HID_ * C_];                    // 256 x 128
__device__ float g_w1p[HID_ * HID_];                  // 256 x 256
__device__ float g_w2p[OUTC_ * HID_];                 // 128 x 256

// ---------------- helpers ----------------
__device__ __forceinline__ int perm8(int i) {
    return (i & ~7) | (((i & 3) << 1) | ((i >> 2) & 1));
}
__device__ __forceinline__ unsigned f2tf(float f) {
    unsigned r;
    asm("cvt.rna.tf32.f32 %0, %1;" : "=r"(r) : "f"(f));
    return r;
}
__device__ __forceinline__ float tfr(float f) { return __uint_as_float(f2tf(f)); }
__device__ __forceinline__ void mma_tf32(float c[4],
                                         float a0, float a1, float a2, float a3,
                                         float b0, float b1) {
    asm volatile(
        "mma.sync.aligned.m16n8k8.row.col.f32.tf32.tf32.f32 "
        "{%0,%1,%2,%3}, {%4,%5,%6,%7}, {%8,%9}, {%0,%1,%2,%3};"
        : "+f"(c[0]), "+f"(c[1]), "+f"(c[2]), "+f"(c[3])
        : "r"(__float_as_uint(a0)), "r"(__float_as_uint(a1)),
          "r"(__float_as_uint(a2)), "r"(__float_as_uint(a3)),
          "r"(__float_as_uint(b0)), "r"(__float_as_uint(b1)));
}

// ---------------- kernel 0: weight prep (permute k within 8-blocks + tf32 round) ----------------
__global__ void prep_kernel(const float* __restrict__ qk_w, const float* __restrict__ v_w,
                            const float* __restrict__ w1, const float* __restrict__ w2) {
    int idx = blockIdx.x * 256 + threadIdx.x;     // 0 .. 163839
    if (idx < 32768) {
        int o = idx >> 7, k = idx & 127;
        g_wqk[(o << 7) | perm8(k)] = tfr(qk_w[idx]);
    } else if (idx < 65536) {
        int j = idx - 32768; int o = j >> 7, k = j & 127;
        g_wv[(o << 7) | perm8(k)] = tfr(v_w[j]);
    } else if (idx < 131072) {
        int j = idx - 65536; int o = j >> 8, k = j & 255;
        g_w1p[(o << 8) | perm8(k)] = tfr(w1[j]);
    } else {
        int j = idx - 131072; int o = j >> 8, k = j & 255;
        g_w2p[(o << 8) | perm8(k)] = tfr(w2[j]);
    }
}

// ---------------- kernel 1: continuous relative position bias ----------------
__global__ void cpb_bias_kernel(const float* __restrict__ w1,
                                const float* __restrict__ b1,
                                const float* __restrict__ w2) {
    __shared__ float s_w1[256];
    __shared__ float s_b1[128];
    __shared__ float s_w2[256];
    int tid = threadIdx.x;
    s_w1[tid] = w1[tid];
    if (tid < 128) s_b1[tid] = b1[tid];
    s_w2[tid] = w2[tid];
    __syncthreads();

    int idx = blockIdx.x * 256 + tid;      // < 576*576
    int i = idx / L_, j = idx % L_;
    int yi = i / WID, xi = i % WID;
    int yj = j / WID, xj = j % WID;
    float ry = (float)(yi - yj) * (8.0f / 23.0f);
    float rx = (float)(xi - xj) * (8.0f / 23.0f);
    ry = copysignf(log2f(1.0f + fabsf(ry)) * (1.0f / 3.0f), ry);
    rx = copysignf(log2f(1.0f + fabsf(rx)) * (1.0f / 3.0f), rx);

    float acc0 = 0.f, acc1 = 0.f;
    #pragma unroll 4
    for (int k = 0; k < 128; k++) {
        float h = fmaxf(0.f, ry * s_w1[2 * k] + rx * s_w1[2 * k + 1] + s_b1[k]);
        acc0 += h * s_w2[k];
        acc1 += h * s_w2[128 + k];
    }
    g_bias[idx] = acc0;
    g_bias[L_ * L_ + idx] = acc1;
}

// ---------------- kernel 2: QKV projection, tf32 mma ----------------
// Block: (l-tile 64, bs). 256 threads = 8 warps.
__global__ void qkv_kernel(const float* __restrict__ x) {
    int bs = blockIdx.y;
    int l0 = blockIdx.x * 64;
    extern __shared__ float sm[];
    float* xs   = sm;                   // 128*72
    float* ws   = xs + 128 * 72;        // 64*136
    float* outs = ws + 64 * 136;        // 64*72

    int tid = threadIdx.x;
    const float* xb = x + (size_t)bs * C_ * L_;
    for (int idx = tid; idx < 128 * 16; idx += 256) {
        int c = idx >> 4, lv = idx & 15;
        float4 v4 = *(const float4*)(xb + (size_t)c * L_ + l0 + lv * 4);
        v4.x = tfr(v4.x); v4.y = tfr(v4.y); v4.z = tfr(v4.z); v4.w = tfr(v4.w);
        *(float4*)(xs + c * 72 + lv * 4) = v4;
    }

    int warp = tid >> 5, lane = tid & 31;
    int row = lane >> 2, quad = lane & 3;
    int m0 = (warp & 3) * 16;           // o within chunk
    int n0 = (warp >> 2) * 32;          // l within tile

    for (int ot = 0; ot < 8; ot++) {
        const float* wsrc = (ot < 4) ? g_wqk + (size_t)ot * 64 * C_
                                     : g_wv  + (size_t)(ot - 4) * 64 * C_;
        __syncthreads();
        for (int idx = tid; idx < 64 * 32; idx += 256) {
            int o = idx >> 5, kv = idx & 31;
            *(float4*)(ws + o * 136 + kv * 4) = *(const float4*)(wsrc + (size_t)o * C_ + kv * 4);
        }
        __syncthreads();

        float acc[4][4] = {};
        #pragma unroll
        for (int kk = 0; kk < 16; kk++) {
            int k0 = kk * 8;
            float2 aA = *(float2*)(ws + (m0 + row) * 136 + k0 + 2 * quad);      // a0,a2
            float2 aB = *(float2*)(ws + (m0 + row + 8) * 136 + k0 + 2 * quad);  // a1,a3
            #pragma unroll
            for (int nt = 0; nt < 4; nt++) {
                int n = n0 + nt * 8;
                float b0 = xs[(k0 + quad) * 72 + n + row];
                float b1 = xs[(k0 + quad + 4) * 72 + n + row];
                mma_tf32(acc[nt], aA.x, aB.x, aA.y, aB.y, b0, b1);
            }
        }

        if (ot < 4) {
            // Q/K: outs[l][perm(d)]
            int po0 = perm8(m0 + row), po1 = perm8(m0 + row + 8);
            #pragma unroll
            for (int nt = 0; nt < 4; nt++) {
                int n = n0 + nt * 8 + 2 * quad;
                outs[n * 72 + po0]       = tfr(acc[nt][0]);
                outs[(n + 1) * 72 + po0] = tfr(acc[nt][1]);
                outs[n * 72 + po1]       = tfr(acc[nt][2]);
                outs[(n + 1) * 72 + po1] = tfr(acc[nt][3]);
            }
            __syncthreads();
            float* dst = (ot < 2) ? g_q + (size_t)(bs * 2 + ot) * L_ * QKD_
                                  : g_k + (size_t)(bs * 2 + ot - 2) * L_ * QKD_;
            for (int idx = tid; idx < 64 * 16; idx += 256) {
                int l = idx >> 4, j = idx & 15;
                *(float4*)(dst + (size_t)(l0 + l) * QKD_ + j * 4) =
                    *(float4*)(outs + l * 72 + j * 4);
            }
        } else {
            // V: outs[d][perm(l)]  (transposed, l-interleaved)
            #pragma unroll
            for (int nt = 0; nt < 4; nt++) {
                int cl = n0 + nt * 8 + 2 * quad;
                int p0 = perm8(cl), p1 = perm8(cl + 1);
                outs[(m0 + row) * 72 + p0]     = tfr(acc[nt][0]);
                outs[(m0 + row) * 72 + p1]     = tfr(acc[nt][1]);
                outs[(m0 + row + 8) * 72 + p0] = tfr(acc[nt][2]);
                outs[(m0 + row + 8) * 72 + p1] = tfr(acc[nt][3]);
            }
            __syncthreads();
            int o2 = (ot - 4) * 64;
            int head = o2 >> 7, dof = o2 & 127;
            float* dst = g_v + (size_t)(bs * 2 + head) * VD_ * L_;
            for (int idx = tid; idx < 64 * 16; idx += 256) {
                int o = idx >> 4, j = idx & 15;
                *(float4*)(dst + (size_t)(dof + o) * L_ + l0 + j * 4) =
                    *(float4*)(outs + o * 72 + j * 4);
            }
        }
    }
}

// ---------------- kernel 3: flash attention, q128 x kt128, 1024 threads, 32 warps ----------------
// smem: qs[128][72], ks[128][72], vt[128][136], ps[128][136], mrow/lrow/arow[128]
__global__ void __launch_bounds__(1024, 1) attn_kernel(const float* __restrict__ sa_bias) {
    int qt = blockIdx.x;              // 0..4 (last tile half-valid)
    int bh = blockIdx.y;              // 0..127
    int bs = bh >> 1, head = bh & 1;
    int q0 = qt * 128;

    extern __shared__ float sm[];
    float* qs   = sm;                  // 128*72
    float* ks   = qs + 128 * 72;       // 128*72
    float* vt   = ks + 128 * 72;       // 128*136
    float* ps   = vt + 128 * 136;      // 128*136
    float* mrow = ps + 128 * 136;      // 128
    float* lrow = mrow + 128;          // 128
    float* arow = lrow + 128;          // 128

    const float* qg = g_q + (size_t)(bs * 2 + head) * L_ * QKD_;
    const float* kg = g_k + (size_t)(bs * 2 + head) * L_ * QKD_;
    const float* vg = g_v + (size_t)(bs * 2 + head) * VD_ * L_;
    const float* bg = g_bias + (size_t)head * L_ * L_;

    int tid = threadIdx.x;
    int warp = tid >> 5, lane = tid & 31;
    int row = lane >> 2, quad = lane & 3;
    int m0 = (warp & 7) * 16;          // 8 m-groups of 16 q-rows
    int n0 = (warp >> 3) * 32;         // 4 n-groups of 32 (S keys / AV d)

    // load q tile [128][64], zero-fill rows >= 576
    for (int idx = tid; idx < 128 * 16; idx += 1024) {
        int l = idx >> 4, dv = idx & 15;
        float4 v4 = make_float4(0.f, 0.f, 0.f, 0.f);
        if (q0 + l < L_)
            v4 = *(const float4*)(qg + (size_t)(q0 + l) * QKD_ + dv * 4);
        *(float4*)(qs + l * 72 + dv * 4) = v4;
    }
    if (tid < 128) { mrow[tid] = -1e30f; lrow[tid] = 0.f; }

    float oac[4][4] = {};

    for (int kt = 0; kt < 5; kt++) {
        int k0g = kt * 128;
        __syncthreads();
        // stage K tile [128 keys][64 d], zero-fill keys >= 576
        for (int idx = tid; idx < 128 * 16; idx += 1024) {
            int l = idx >> 4, dv = idx & 15;
            float4 v4 = make_float4(0.f, 0.f, 0.f, 0.f);
            if (k0g + l < L_)
                v4 = *(const float4*)(kg + (size_t)(k0g + l) * QKD_ + dv * 4);
            *(float4*)(ks + l * 72 + dv * 4) = v4;
        }
        // stage V tile [128 d][128 keys-interleaved], zero-fill OOB key blocks
        for (int idx = tid; idx < 128 * 32; idx += 1024) {
            int d = idx >> 5, j = idx & 31;
            float4 v4 = make_float4(0.f, 0.f, 0.f, 0.f);
            if (k0g + j * 4 < L_)
                v4 = *(const float4*)(vg + (size_t)d * L_ + k0g + j * 4);
            *(float4*)(vt + d * 136 + j * 4) = v4;
        }
        __syncthreads();

        // ---- S = Q K^T (warp m16 x n32) + bias, into ps (perm cols), mask OOB keys ----
        {
            float acc[4][4] = {};
            #pragma unroll
            for (int kk = 0; kk < 8; kk++) {
                int k0 = kk * 8;
                float2 aA = *(float2*)(qs + (m0 + row) * 72 + k0 + 2 * quad);
                float2 aB = *(float2*)(qs + (m0 + row + 8) * 72 + k0 + 2 * quad);
                #pragma unroll
                for (int nt = 0; nt < 4; nt++) {
                    float2 bv = *(float2*)(ks + (n0 + nt * 8 + row) * 72 + k0 + 2 * quad);
                    mma_tf32(acc[nt], aA.x, aB.x, aA.y, aB.y, bv.x, bv.y);
                }
            }
            int r0 = q0 + m0 + row;
            int rb0 = (r0 < L_) ? r0 : L_ - 1;
            int rb1 = (r0 + 8 < L_) ? r0 + 8 : L_ - 1;
            #pragma unroll
            for (int nt = 0; nt < 4; nt++) {
                int cl = n0 + nt * 8 + 2 * quad;      // local col (even)
                int p0 = perm8(cl), p1 = perm8(cl + 1);
                int ct = k0g + cl;                    // true key (even)
                if (ct < L_) {
                    ps[(m0 + row) * 136 + p0]       = acc[nt][0] * 0.125f + bg[(size_t)rb0 * L_ + ct];
                    ps[(m0 + row) * 136 + p1]       = acc[nt][1] * 0.125f + bg[(size_t)rb0 * L_ + ct + 1];
                    ps[(m0 + row + 8) * 136 + p0]   = acc[nt][2] * 0.125f + bg[(size_t)rb1 * L_ + ct];
                    ps[(m0 + row + 8) * 136 + p1]   = acc[nt][3] * 0.125f + bg[(size_t)rb1 * L_ + ct + 1];
                } else {
                    ps[(m0 + row) * 136 + p0]       = -1e30f;
                    ps[(m0 + row) * 136 + p1]       = -1e30f;
                    ps[(m0 + row + 8) * 136 + p0]   = -1e30f;
                    ps[(m0 + row + 8) * 136 + p1]   = -1e30f;
                }
            }
        }
        __syncthreads();

        // ---- online softmax: warp owns rows warp*4 .. warp*4+3 (128 cols) ----
        #pragma unroll
        for (int rr = 0; rr < 4; rr++) {
            int r = warp * 4 + rr;
            float2 pv0 = *(float2*)(ps + r * 136 + 2 * lane);
            float2 pv1 = *(float2*)(ps + r * 136 + 64 + 2 * lane);
            float tmax = fmaxf(fmaxf(pv0.x, pv0.y), fmaxf(pv1.x, pv1.y));
            #pragma unroll
            for (int off = 16; off > 0; off >>= 1)
                tmax = fmaxf(tmax, __shfl_xor_sync(0xffffffffu, tmax, off));
            float mo = mrow[r];
            float mn = fmaxf(mo, tmax);
            float e00 = __expf(pv0.x - mn);
            float e01 = __expf(pv0.y - mn);
            float e10 = __expf(pv1.x - mn);
            float e11 = __expf(pv1.y - mn);
            float2 pr0; pr0.x = tfr(e00); pr0.y = tfr(e01);
            float2 pr1; pr1.x = tfr(e10); pr1.y = tfr(e11);
            *(float2*)(ps + r * 136 + 2 * lane) = pr0;
            *(float2*)(ps + r * 136 + 64 + 2 * lane) = pr1;
            float ss = e00 + e01 + e10 + e11;
            #pragma unroll
            for (int off = 16; off > 0; off >>= 1)
                ss += __shfl_xor_sync(0xffffffffu, ss, off);
            if (lane == 0) {
                float al = __expf(mo - mn);
                arow[r] = al;
                mrow[r] = mn;
                lrow[r] = al * lrow[r] + ss;
            }
        }
        __syncthreads();

        // ---- AV: warp m16 x n32, k=128; rescale + accumulate ----
        float al0 = arow[m0 + row], al1 = arow[m0 + row + 8];
        #pragma unroll
        for (int nt = 0; nt < 4; nt++) {
            oac[nt][0] *= al0; oac[nt][1] *= al0;
            oac[nt][2] *= al1; oac[nt][3] *= al1;
        }
        #pragma unroll
        for (int kk = 0; kk < 16; kk++) {
            int kb = kk * 8;
            float2 aA = *(float2*)(ps + (m0 + row) * 136 + kb + 2 * quad);
            float2 aB = *(float2*)(ps + (m0 + row + 8) * 136 + kb + 2 * quad);
            #pragma unroll
            for (int nt = 0; nt < 4; nt++) {
                float2 bv = *(float2*)(vt + (n0 + nt * 8 + row) * 136 + kb + 2 * quad);
                mma_tf32(oac[nt], aA.x, aB.x, aA.y, aB.y, bv.x, bv.y);
            }
        }
    }

    // ---- epilogue: normalize, + sa_bias, ch-interleaved tf32 write (masked) ----
    float inv0 = 1.0f / lrow[m0 + row];
    float inv1 = 1.0f / lrow[m0 + row + 8];
    float* og = g_att + (size_t)bs * L_ * HID_;
    int l = q0 + m0 + row;
    #pragma unroll
    for (int nt = 0; nt < 4; nt++) {
        int ch = head * 128 + n0 + nt * 8 + 2 * quad;
        int pc0 = perm8(ch), pc1 = perm8(ch + 1);
        float sb0 = sa_bias[ch], sb1 = sa_bias[ch + 1];
        if (l < L_) {
            og[(size_t)l * HID_ + pc0] = tfr(oac[nt][0] * inv0 + sb0);
            og[(size_t)l * HID_ + pc1] = tfr(oac[nt][1] * inv0 + sb1);
        }
        if (l + 8 < L_) {
            og[(size_t)(l + 8) * HID_ + pc0] = tfr(oac[nt][2] * inv1 + sb0);
            og[(size_t)(l + 8) * HID_ + pc1] = tfr(oac[nt][3] * inv1 + sb1);
        }
    }
}

// ---------------- kernel 4: MLP (tf32 mma), l-tile 64, 512 threads = 16 warps (R6) ----------------
// smem: xsm[64][264], wts[256][72], y1s[64][264]
__global__ void mlp_kernel(const float* __restrict__ b1, const float* __restrict__ b2,
                           float* __restrict__ out) {
    int blk = blockIdx.x;                // 0..575
    int bs = blk / 9;
    int l0 = (blk % 9) * 64;
    extern __shared__ float sm[];
    float* xsm = sm;                     // 64*264
    float* wts = xsm + 64 * 264;         // 256*72
    float* y1s = wts + 256 * 72;         // 64*264

    int tid = threadIdx.x;
    int warp = tid >> 5, lane = tid & 31;
    int row = lane >> 2, quad = lane & 3;

    const float* ag = g_att + ((size_t)bs * L_ + l0) * HID_;
    for (int idx = tid; idx < 64 * 64; idx += 512) {
        int p = idx >> 6, iv = idx & 63;
        *(float4*)(xsm + p * 264 + iv * 4) = *(const float4*)(ag + (size_t)p * HID_ + iv * 4);
    }

    // ---- GEMM1: Y1(64x256) = X @ W1^T : warp tile m32 x n32 ----
    int m0 = (warp & 1) * 32;
    int n0 = (warp >> 1) * 32;
    float acc[2][4][4] = {};
    for (int it = 0; it < 4; it++) {
        __syncthreads();
        for (int idx = tid; idx < 256 * 16; idx += 512) {
            int o = idx >> 4, kv = idx & 15;
            *(float4*)(wts + o * 72 + kv * 4) = *(const float4*)(g_w1p + (size_t)o * HID_ + it * 64 + kv * 4);
        }
        __syncthreads();
        #pragma unroll
        for (int kk = 0; kk < 8; kk++) {
            int kg = it * 64 + kk * 8;
            int kb = kk * 8;
            float2 aA[2], aB[2];
            #pragma unroll
            for (int mt = 0; mt < 2; mt++) {
                aA[mt] = *(float2*)(xsm + (m0 + mt * 16 + row) * 264 + kg + 2 * quad);
                aB[mt] = *(float2*)(xsm + (m0 + mt * 16 + row + 8) * 264 + kg + 2 * quad);
            }
            #pragma unroll
            for (int nt = 0; nt < 4; nt++) {
                float2 bv = *(float2*)(wts + (n0 + nt * 8 + row) * 72 + kb + 2 * quad);
                mma_tf32(acc[0][nt], aA[0].x, aB[0].x, aA[0].y, aB[0].y, bv.x, bv.y);
                mma_tf32(acc[1][nt], aA[1].x, aB[1].x, aA[1].y, aB[1].y, bv.x, bv.y);
            }
        }
    }
    // bias + exact GELU -> y1s[p][perm(o)], tf32-rounded
    #pragma unroll
    for (int mt = 0; mt < 2; mt++) {
        #pragma unroll
        for (int nt = 0; nt < 4; nt++) {
            int col = n0 + nt * 8 + 2 * quad;
            int p0 = perm8(col), p1 = perm8(col + 1);
            float bb0 = b1[col], bb1 = b1[col + 1];
            int r = m0 + mt * 16 + row;
            float v0 = acc[mt][nt][0] + bb0;
            float v1 = acc[mt][nt][1] + bb1;
            float v2 = acc[mt][nt][2] + bb0;
            float v3 = acc[mt][nt][3] + bb1;
            y1s[r * 264 + p0]       = tfr(0.5f * v0 * (1.0f + erff(v0 * 0.70710678118654752f)));
            y1s[r * 264 + p1]       = tfr(0.5f * v1 * (1.0f + erff(v1 * 0.70710678118654752f)));
            y1s[(r + 8) * 264 + p0] = tfr(0.5f * v2 * (1.0f + erff(v2 * 0.70710678118654752f)));
            y1s[(r + 8) * 264 + p1] = tfr(0.5f * v3 * (1.0f + erff(v3 * 0.70710678118654752f)));
        }
    }
    __syncthreads();

    // ---- GEMM2: OUT(64x128) = Y1 @ W2^T : warp tile m16 x n32 ----
    int m0b = (warp & 3) * 16;
    int n0b = (warp >> 2) * 32;
    float ac2[4][4] = {};
    for (int it = 0; it < 4; it++) {
        for (int idx = tid; idx < 128 * 16; idx += 512) {
            int o = idx >> 4, kv = idx & 15;
            *(float4*)(wts + o * 72 + kv * 4) = *(const float4*)(g_w2p + (size_t)o * HID_ + it * 64 + kv * 4);
        }
        __syncthreads();
        #pragma unroll
        for (int kk = 0; kk < 8; kk++) {
            int kg = it * 64 + kk * 8;
            int kb = kk * 8;
            float2 aA = *(float2*)(y1s + (m0b + row) * 264 + kg + 2 * quad);
            float2 aB = *(float2*)(y1s + (m0b + row + 8) * 264 + kg + 2 * quad);
            #pragma unroll
            for (int nt = 0; nt < 4; nt++) {
                float2 bv = *(float2*)(wts + (n0b + nt * 8 + row) * 72 + kb + 2 * quad);
                mma_tf32(ac2[nt], aA.x, aB.x, aA.y, aB.y, bv.x, bv.y);
            }
        }
        __syncthreads();
    }

    // ---- epilogue: + b2, write (bs, o, l) ----
    float* og = out + (size_t)bs * OUTC_ * L_;
    int l = l0 + m0b + row;
    #pragma unroll
    for (int nt = 0; nt < 4; nt++) {
        int col = n0b + nt * 8 + 2 * quad;
        float bb0 = b2[col], bb1 = b2[col + 1];
        og[(size_t)col * L_ + l]           = ac2[nt][0] + bb0;
        og[(size_t)(col + 1) * L_ + l]     = ac2[nt][1] + bb1;
        og[(size_t)col * L_ + l + 8]       = ac2[nt][2] + bb0;
        og[(size_t)(col + 1) * L_ + l + 8] = ac2[nt][3] + bb1;
    }
}

// ---------------- launch ----------------
extern "C" void kernel_launch(void* const* d_in, const int* in_sizes, int n_in,
                              void* d_out, int out_size) {
    const float* x      = (const float*)d_in[0];
    const float* qk_w   = (const float*)d_in[1];
    const float* v_w    = (const float*)d_in[2];
    const float* cpb_w1 = (const float*)d_in[3];
    const float* cpb_b1 = (const float*)d_in[4];
    const float* cpb_w2 = (const float*)d_in[5];
    const float* sa_b   = (const float*)d_in[6];
    const float* mlp_b1 = (const float*)d_in[8];
    const float* mlp_b2 = (const float*)d_in[10];
    float* out = (float*)d_out;

    const int SMEM_QKV = (128 * 72 + 64 * 136 + 64 * 72) * 4;                  // 90112
    const int SMEM_ATT = (128 * 72 * 2 + 128 * 136 * 2 + 3 * 128) * 4;         // 214528
    const int SMEM_MLP = (64 * 264 * 2 + 256 * 72) * 4;                        // 208896

    cudaFuncSetAttribute(qkv_kernel,  cudaFuncAttributeMaxDynamicSharedMemorySize, SMEM_QKV);
    cudaFuncSetAttribute(attn_kernel, cudaFuncAttributeMaxDynamicSharedMemorySize, SMEM_ATT);
    cudaFuncSetAttribute(mlp_kernel,  cudaFuncAttributeMaxDynamicSharedMemorySize, SMEM_MLP);

    prep_kernel<<<640, 256>>>(qk_w, v_w, (const float*)d_in[7], (const float*)d_in[9]);
    cpb_bias_kernel<<<(L_ * L_) / 256, 256>>>(cpb_w1, cpb_b1, cpb_w2);
    qkv_kernel<<<dim3(9, BS_), 256, SMEM_QKV>>>(x);
    attn_kernel<<<dim3(5, BS_ * HEADS_), 1024, SMEM_ATT>>>(sa_b);
    mlp_kernel<<<BS_ * 9, 512, SMEM_MLP>>>(mlp_b1, mlp_b2, out);
}

// round 10
// speedup vs baseline: 1.2656x; 1.2656x over previous
#include <cuda_runtime.h>
#include <cuda_bf16.h>
#include <math.h>

#define B_     2
#define S_     32
#define BS_    64
#define C_     128
#define HGT    24
#define WID    24
#define L_     576
#define HEADS_ 2
#define QKD_   64
#define VD_    128
#define HID_   256
#define OUTC_  128

// ---------------- scratch (static device globals; no allocation) ----------------
__device__ float g_bias[HEADS_ * L_ * L_];            // (head, i, j)  fp32, true order
__device__ float g_q[BS_ * HEADS_ * L_ * QKD_];       // [bs,h][l][d-interleaved], tf32
__device__ float g_k[BS_ * HEADS_ * L_ * QKD_];       // [bs,h][l][d-interleaved], tf32
__device__ float g_v[BS_ * HEADS_ * VD_ * L_];        // [bs,h][d][l NATURAL], tf32
__device__ float g_att[BS_ * L_ * HID_];              // [bs][l][ch-interleaved], tf32
// pre-permuted + tf32-rounded weights (k-dim interleaved within 8-blocks)
__device__ float g_wqk[2 * C_ * C_];                  // 256 x 128
__device__ float g_wv [HID_ * C_];                    // 256 x 128
__device__ float g_w1p[HID_ * HID_];                  // 256 x 256
__device__ float g_w2p[OUTC_ * HID_];                 // 128 x 256

// ---------------- helpers ----------------
__device__ __forceinline__ int perm8(int i) {
    return (i & ~7) | (((i & 3) << 1) | ((i >> 2) & 1));
}
__device__ __forceinline__ unsigned f2tf(float f) {
    unsigned r;
    asm("cvt.rna.tf32.f32 %0, %1;" : "=r"(r) : "f"(f));
    return r;
}
__device__ __forceinline__ float tfr(float f) { return __uint_as_float(f2tf(f)); }
__device__ __forceinline__ void mma_tf32(float c[4],
                                         float a0, float a1, float a2, float a3,
                                         float b0, float b1) {
    asm volatile(
        "mma.sync.aligned.m16n8k8.row.col.f32.tf32.tf32.f32 "
        "{%0,%1,%2,%3}, {%4,%5,%6,%7}, {%8,%9}, {%0,%1,%2,%3};"
        : "+f"(c[0]), "+f"(c[1]), "+f"(c[2]), "+f"(c[3])
        : "r"(__float_as_uint(a0)), "r"(__float_as_uint(a1)),
          "r"(__float_as_uint(a2)), "r"(__float_as_uint(a3)),
          "r"(__float_as_uint(b0)), "r"(__float_as_uint(b1)));
}

// ---------------- kernel 0: weight prep (permute k within 8-blocks + tf32 round) ----------------
__global__ void prep_kernel(const float* __restrict__ qk_w, const float* __restrict__ v_w,
                            const float* __restrict__ w1, const float* __restrict__ w2) {
    int idx = blockIdx.x * 256 + threadIdx.x;     // 0 .. 163839
    if (idx < 32768) {
        int o = idx >> 7, k = idx & 127;
        g_wqk[(o << 7) | perm8(k)] = tfr(qk_w[idx]);
    } else if (idx < 65536) {
        int j = idx - 32768; int o = j >> 7, k = j & 127;
        g_wv[(o << 7) | perm8(k)] = tfr(v_w[j]);
    } else if (idx < 131072) {
        int j = idx - 65536; int o = j >> 8, k = j & 255;
        g_w1p[(o << 8) | perm8(k)] = tfr(w1[j]);
    } else {
        int j = idx - 131072; int o = j >> 8, k = j & 255;
        g_w2p[(o << 8) | perm8(k)] = tfr(w2[j]);
    }
}

// ---------------- kernel 1: continuous relative position bias ----------------
__global__ void cpb_bias_kernel(const float* __restrict__ w1,
                                const float* __restrict__ b1,
                                const float* __restrict__ w2) {
    __shared__ float s_w1[256];
    __shared__ float s_b1[128];
    __shared__ float s_w2[256];
    int tid = threadIdx.x;
    s_w1[tid] = w1[tid];
    if (tid < 128) s_b1[tid] = b1[tid];
    s_w2[tid] = w2[tid];
    __syncthreads();

    int idx = blockIdx.x * 256 + tid;      // < 576*576
    int i = idx / L_, j = idx % L_;
    int yi = i / WID, xi = i % WID;
    int yj = j / WID, xj = j % WID;
    float ry = (float)(yi - yj) * (8.0f / 23.0f);
    float rx = (float)(xi - xj) * (8.0f / 23.0f);
    ry = copysignf(log2f(1.0f + fabsf(ry)) * (1.0f / 3.0f), ry);
    rx = copysignf(log2f(1.0f + fabsf(rx)) * (1.0f / 3.0f), rx);

    float acc0 = 0.f, acc1 = 0.f;
    #pragma unroll 4
    for (int k = 0; k < 128; k++) {
        float h = fmaxf(0.f, ry * s_w1[2 * k] + rx * s_w1[2 * k + 1] + s_b1[k]);
        acc0 += h * s_w2[k];
        acc1 += h * s_w2[128 + k];
    }
    g_bias[idx] = acc0;
    g_bias[L_ * L_ + idx] = acc1;
}

// ---------------- kernel 2: QKV projection, tf32 mma ----------------
// Block: (l-tile 64, bs). 256 threads = 8 warps.
__global__ void qkv_kernel(const float* __restrict__ x) {
    int bs = blockIdx.y;
    int l0 = blockIdx.x * 64;
    extern __shared__ float sm[];
    float* xs   = sm;                   // 128*72
    float* ws   = xs + 128 * 72;        // 64*136
    float* outs = ws + 64 * 136;        // 64*72

    int tid = threadIdx.x;
    const float* xb = x + (size_t)bs * C_ * L_;
    for (int idx = tid; idx < 128 * 16; idx += 256) {
        int c = idx >> 4, lv = idx & 15;
        float4 v4 = *(const float4*)(xb + (size_t)c * L_ + l0 + lv * 4);
        v4.x = tfr(v4.x); v4.y = tfr(v4.y); v4.z = tfr(v4.z); v4.w = tfr(v4.w);
        *(float4*)(xs + c * 72 + lv * 4) = v4;
    }

    int warp = tid >> 5, lane = tid & 31;
    int row = lane >> 2, quad = lane & 3;
    int m0 = (warp & 3) * 16;           // o within chunk
    int n0 = (warp >> 2) * 32;          // l within tile

    for (int ot = 0; ot < 8; ot++) {
        const float* wsrc = (ot < 4) ? g_wqk + (size_t)ot * 64 * C_
                                     : g_wv  + (size_t)(ot - 4) * 64 * C_;
        __syncthreads();
        for (int idx = tid; idx < 64 * 32; idx += 256) {
            int o = idx >> 5, kv = idx & 31;
            *(float4*)(ws + o * 136 + kv * 4) = *(const float4*)(wsrc + (size_t)o * C_ + kv * 4);
        }
        __syncthreads();

        float acc[4][4] = {};
        #pragma unroll
        for (int kk = 0; kk < 16; kk++) {
            int k0 = kk * 8;
            float2 aA = *(float2*)(ws + (m0 + row) * 136 + k0 + 2 * quad);      // a0,a2
            float2 aB = *(float2*)(ws + (m0 + row + 8) * 136 + k0 + 2 * quad);  // a1,a3
            #pragma unroll
            for (int nt = 0; nt < 4; nt++) {
                int n = n0 + nt * 8;
                float b0 = xs[(k0 + quad) * 72 + n + row];
                float b1 = xs[(k0 + quad + 4) * 72 + n + row];
                mma_tf32(acc[nt], aA.x, aB.x, aA.y, aB.y, b0, b1);
            }
        }

        if (ot < 4) {
            // Q/K: outs[l][perm(d)]
            int po0 = perm8(m0 + row), po1 = perm8(m0 + row + 8);
            #pragma unroll
            for (int nt = 0; nt < 4; nt++) {
                int n = n0 + nt * 8 + 2 * quad;
                outs[n * 72 + po0]       = tfr(acc[nt][0]);
                outs[(n + 1) * 72 + po0] = tfr(acc[nt][1]);
                outs[n * 72 + po1]       = tfr(acc[nt][2]);
                outs[(n + 1) * 72 + po1] = tfr(acc[nt][3]);
            }
            __syncthreads();
            float* dst = (ot < 2) ? g_q + (size_t)(bs * 2 + ot) * L_ * QKD_
                                  : g_k + (size_t)(bs * 2 + ot - 2) * L_ * QKD_;
            for (int idx = tid; idx < 64 * 16; idx += 256) {
                int l = idx >> 4, j = idx & 15;
                *(float4*)(dst + (size_t)(l0 + l) * QKD_ + j * 4) =
                    *(float4*)(outs + l * 72 + j * 4);
            }
        } else {
            // V: outs[d][l]  (transposed, NATURAL l order)
            #pragma unroll
            for (int nt = 0; nt < 4; nt++) {
                int cl = n0 + nt * 8 + 2 * quad;
                outs[(m0 + row) * 72 + cl]         = tfr(acc[nt][0]);
                outs[(m0 + row) * 72 + cl + 1]     = tfr(acc[nt][1]);
                outs[(m0 + row + 8) * 72 + cl]     = tfr(acc[nt][2]);
                outs[(m0 + row + 8) * 72 + cl + 1] = tfr(acc[nt][3]);
            }
            __syncthreads();
            int o2 = (ot - 4) * 64;
            int head = o2 >> 7, dof = o2 & 127;
            float* dst = g_v + (size_t)(bs * 2 + head) * VD_ * L_;
            for (int idx = tid; idx < 64 * 16; idx += 256) {
                int o = idx >> 4, j = idx & 15;
                *(float4*)(dst + (size_t)(dof + o) * L_ + l0 + j * 4) =
                    *(float4*)(outs + o * 72 + j * 4);
            }
        }
    }
}

// ---------------- kernel 3: flash attention, register-resident P ----------------
// 256 threads = 8 warps; warp owns 16 q-rows x all 64 keys. 2 CTAs/SM.
// smem: qs[128][72], ks[64][72], vt[128][72] (natural keys)
__global__ void __launch_bounds__(256, 2) attn_kernel(const float* __restrict__ sa_bias) {
    int qt = blockIdx.x;              // 0..4 (last tile half-valid)
    int bh = blockIdx.y;              // 0..127
    int bs = bh >> 1, head = bh & 1;
    int q0 = qt * 128;

    extern __shared__ float sm[];
    float* qs = sm;                    // 128*72
    float* ks = qs + 128 * 72;         // 64*72
    float* vt = ks + 64 * 72;          // 128*72

    const float* qg = g_q + (size_t)(bs * 2 + head) * L_ * QKD_;
    const float* kg = g_k + (size_t)(bs * 2 + head) * L_ * QKD_;
    const float* vg = g_v + (size_t)(bs * 2 + head) * VD_ * L_;
    const float* bg = g_bias + (size_t)head * L_ * L_;

    int tid = threadIdx.x;
    int warp = tid >> 5, lane = tid & 31;
    int row = lane >> 2, quad = lane & 3;
    int m0 = warp * 16;

    // load q tile [128][64] (d-interleaved), zero-fill rows >= 576
    for (int idx = tid; idx < 128 * 16; idx += 256) {
        int l = idx >> 4, dv = idx & 15;
        float4 v4 = make_float4(0.f, 0.f, 0.f, 0.f);
        if (q0 + l < L_)
            v4 = *(const float4*)(qg + (size_t)(q0 + l) * QKD_ + dv * 4);
        *(float4*)(qs + l * 72 + dv * 4) = v4;
    }

    float oac[16][4] = {};
    float mr0 = -1e30f, mr1 = -1e30f;
    float lr0 = 0.f, lr1 = 0.f;

    int r0g = q0 + m0 + row;
    int rb0 = (r0g < L_) ? r0g : L_ - 1;
    int rb1 = (r0g + 8 < L_) ? r0g + 8 : L_ - 1;
    const float* bgr0 = bg + (size_t)rb0 * L_;
    const float* bgr1 = bg + (size_t)rb1 * L_;

    for (int kt = 0; kt < 9; kt++) {
        int k0g = kt * 64;
        __syncthreads();                  // prev AV done with vt; kt=0: qs visible after this? (qs written pre-loop by all, barrier covers it)
        // stage K tile [64 keys][64 d] (d-interleaved)
        for (int idx = tid; idx < 64 * 16; idx += 256) {
            int l = idx >> 4, dv = idx & 15;
            *(float4*)(ks + l * 72 + dv * 4) =
                *(const float4*)(kg + (size_t)(k0g + l) * QKD_ + dv * 4);
        }
        // stage V tile [128 d][64 keys NATURAL]
        for (int idx = tid; idx < 128 * 16; idx += 256) {
            int d = idx >> 4, j = idx & 15;
            *(float4*)(vt + d * 72 + j * 4) =
                *(const float4*)(vg + (size_t)d * L_ + k0g + j * 4);
        }
        __syncthreads();

        // ---- S = Q K^T : warp m16 x n64 (8 n-tiles), accumulators in regs ----
        float p[8][4] = {};
        #pragma unroll
        for (int kk = 0; kk < 8; kk++) {
            int k0 = kk * 8;
            float2 aA = *(float2*)(qs + (m0 + row) * 72 + k0 + 2 * quad);
            float2 aB = *(float2*)(qs + (m0 + row + 8) * 72 + k0 + 2 * quad);
            #pragma unroll
            for (int nt = 0; nt < 8; nt++) {
                float2 bv = *(float2*)(ks + (nt * 8 + row) * 72 + k0 + 2 * quad);
                mma_tf32(p[nt], aA.x, aB.x, aA.y, aB.y, bv.x, bv.y);
            }
        }
        // scale + bias (keys natural: c-pair = cols nt*8+2q, +1)
        #pragma unroll
        for (int nt = 0; nt < 8; nt++) {
            int ct = k0g + nt * 8 + 2 * quad;
            p[nt][0] = p[nt][0] * 0.125f + bgr0[ct];
            p[nt][1] = p[nt][1] * 0.125f + bgr0[ct + 1];
            p[nt][2] = p[nt][2] * 0.125f + bgr1[ct];
            p[nt][3] = p[nt][3] * 0.125f + bgr1[ct + 1];
        }

        // ---- online softmax in registers (row owned by quad: shuffle xor 1,2) ----
        float tm0 = -1e30f, tm1 = -1e30f;
        #pragma unroll
        for (int nt = 0; nt < 8; nt++) {
            tm0 = fmaxf(tm0, fmaxf(p[nt][0], p[nt][1]));
            tm1 = fmaxf(tm1, fmaxf(p[nt][2], p[nt][3]));
        }
        tm0 = fmaxf(tm0, __shfl_xor_sync(0xffffffffu, tm0, 1));
        tm0 = fmaxf(tm0, __shfl_xor_sync(0xffffffffu, tm0, 2));
        tm1 = fmaxf(tm1, __shfl_xor_sync(0xffffffffu, tm1, 1));
        tm1 = fmaxf(tm1, __shfl_xor_sync(0xffffffffu, tm1, 2));
        float mn0 = fmaxf(mr0, tm0), mn1 = fmaxf(mr1, tm1);
        float al0 = __expf(mr0 - mn0), al1 = __expf(mr1 - mn1);
        mr0 = mn0; mr1 = mn1;

        float s0 = 0.f, s1 = 0.f;
        #pragma unroll
        for (int nt = 0; nt < 8; nt++) {
            float e0 = __expf(p[nt][0] - mn0);
            float e1 = __expf(p[nt][1] - mn0);
            float e2 = __expf(p[nt][2] - mn1);
            float e3 = __expf(p[nt][3] - mn1);
            s0 += e0 + e1; s1 += e2 + e3;
            p[nt][0] = tfr(e0); p[nt][1] = tfr(e1);
            p[nt][2] = tfr(e2); p[nt][3] = tfr(e3);
        }
        s0 += __shfl_xor_sync(0xffffffffu, s0, 1);
        s0 += __shfl_xor_sync(0xffffffffu, s0, 2);
        s1 += __shfl_xor_sync(0xffffffffu, s1, 1);
        s1 += __shfl_xor_sync(0xffffffffu, s1, 2);
        lr0 = al0 * lr0 + s0;
        lr1 = al1 * lr1 + s1;

        // ---- AV: P (regs) x V (smem, natural keys); rescale then accumulate ----
        #pragma unroll
        for (int dt = 0; dt < 16; dt++) {
            oac[dt][0] *= al0; oac[dt][1] *= al0;
            oac[dt][2] *= al1; oac[dt][3] *= al1;
        }
        #pragma unroll
        for (int kb = 0; kb < 8; kb++) {
            int kc = kb * 8 + 2 * quad;
            #pragma unroll
            for (int dt = 0; dt < 16; dt++) {
                float2 bv = *(float2*)(vt + (dt * 8 + row) * 72 + kc);
                // A slots (quad, quad+4) fed with keys (kb*8+2q, kb*8+2q+1) = C pair order
                mma_tf32(oac[dt], p[kb][0], p[kb][2], p[kb][1], p[kb][3], bv.x, bv.y);
            }
        }
    }

    // ---- epilogue: normalize, + sa_bias, ch-interleaved tf32 write (masked) ----
    float inv0 = 1.0f / lr0;
    float inv1 = 1.0f / lr1;
    float* og = g_att + (size_t)bs * L_ * HID_;
    int l = q0 + m0 + row;
    #pragma unroll
    for (int dt = 0; dt < 16; dt++) {
        int ch = head * 128 + dt * 8 + 2 * quad;
        int pc0 = perm8(ch), pc1 = perm8(ch + 1);
        float sb0 = sa_bias[ch], sb1 = sa_bias[ch + 1];
        if (l < L_) {
            og[(size_t)l * HID_ + pc0] = tfr(oac[dt][0] * inv0 + sb0);
            og[(size_t)l * HID_ + pc1] = tfr(oac[dt][1] * inv0 + sb1);
        }
        if (l + 8 < L_) {
            og[(size_t)(l + 8) * HID_ + pc0] = tfr(oac[dt][2] * inv1 + sb0);
            og[(size_t)(l + 8) * HID_ + pc1] = tfr(oac[dt][3] * inv1 + sb1);
        }
    }
}

// ---------------- kernel 4: MLP (tf32 mma), l-tile 64, 512 threads = 16 warps (R6) ----------------
// smem: xsm[64][264], wts[256][72], y1s[64][264]
__global__ void mlp_kernel(const float* __restrict__ b1, const float* __restrict__ b2,
                           float* __restrict__ out) {
    int blk = blockIdx.x;                // 0..575
    int bs = blk / 9;
    int l0 = (blk % 9) * 64;
    extern __shared__ float sm[];
    float* xsm = sm;                     // 64*264
    float* wts = xsm + 64 * 264;         // 256*72
    float* y1s = wts + 256 * 72;         // 64*264

    int tid = threadIdx.x;
    int warp = tid >> 5, lane = tid & 31;
    int row = lane >> 2, quad = lane & 3;

    const float* ag = g_att + ((size_t)bs * L_ + l0) * HID_;
    for (int idx = tid; idx < 64 * 64; idx += 512) {
        int p = idx >> 6, iv = idx & 63;
        *(float4*)(xsm + p * 264 + iv * 4) = *(const float4*)(ag + (size_t)p * HID_ + iv * 4);
    }

    // ---- GEMM1: Y1(64x256) = X @ W1^T : warp tile m32 x n32 ----
    int m0 = (warp & 1) * 32;
    int n0 = (warp >> 1) * 32;
    float acc[2][4][4] = {};
    for (int it = 0; it < 4; it++) {
        __syncthreads();
        for (int idx = tid; idx < 256 * 16; idx += 512) {
            int o = idx >> 4, kv = idx & 15;
            *(float4*)(wts + o * 72 + kv * 4) = *(const float4*)(g_w1p + (size_t)o * HID_ + it * 64 + kv * 4);
        }
        __syncthreads();
        #pragma unroll
        for (int kk = 0; kk < 8; kk++) {
            int kg = it * 64 + kk * 8;
            int kb = kk * 8;
            float2 aA[2], aB[2];
            #pragma unroll
            for (int mt = 0; mt < 2; mt++) {
                aA[mt] = *(float2*)(xsm + (m0 + mt * 16 + row) * 264 + kg + 2 * quad);
                aB[mt] = *(float2*)(xsm + (m0 + mt * 16 + row + 8) * 264 + kg + 2 * quad);
            }
            #pragma unroll
            for (int nt = 0; nt < 4; nt++) {
                float2 bv = *(float2*)(wts + (n0 + nt * 8 + row) * 72 + kb + 2 * quad);
                mma_tf32(acc[0][nt], aA[0].x, aB[0].x, aA[0].y, aB[0].y, bv.x, bv.y);
                mma_tf32(acc[1][nt], aA[1].x, aB[1].x, aA[1].y, aB[1].y, bv.x, bv.y);
            }
        }
    }
    // bias + exact GELU -> y1s[p][perm(o)], tf32-rounded
    #pragma unroll
    for (int mt = 0; mt < 2; mt++) {
        #pragma unroll
        for (int nt = 0; nt < 4; nt++) {
            int col = n0 + nt * 8 + 2 * quad;
            int p0 = perm8(col), p1 = perm8(col + 1);
            float bb0 = b1[col], bb1 = b1[col + 1];
            int r = m0 + mt * 16 + row;
            float v0 = acc[mt][nt][0] + bb0;
            float v1 = acc[mt][nt][1] + bb1;
            float v2 = acc[mt][nt][2] + bb0;
            float v3 = acc[mt][nt][3] + bb1;
            y1s[r * 264 + p0]       = tfr(0.5f * v0 * (1.0f + erff(v0 * 0.70710678118654752f)));
            y1s[r * 264 + p1]       = tfr(0.5f * v1 * (1.0f + erff(v1 * 0.70710678118654752f)));
            y1s[(r + 8) * 264 + p0] = tfr(0.5f * v2 * (1.0f + erff(v2 * 0.70710678118654752f)));
            y1s[(r + 8) * 264 + p1] = tfr(0.5f * v3 * (1.0f + erff(v3 * 0.70710678118654752f)));
        }
    }
    __syncthreads();

    // ---- GEMM2: OUT(64x128) = Y1 @ W2^T : warp tile m16 x n32 ----
    int m0b = (warp & 3) * 16;
    int n0b = (warp >> 2) * 32;
    float ac2[4][4] = {};
    for (int it = 0; it < 4; it++) {
        for (int idx = tid; idx < 128 * 16; idx += 512) {
            int o = idx >> 4, kv = idx & 15;
            *(float4*)(wts + o * 72 + kv * 4) = *(const float4*)(g_w2p + (size_t)o * HID_ + it * 64 + kv * 4);
        }
        __syncthreads();
        #pragma unroll
        for (int kk = 0; kk < 8; kk++) {
            int kg = it * 64 + kk * 8;
            int kb = kk * 8;
            float2 aA = *(float2*)(y1s + (m0b + row) * 264 + kg + 2 * quad);
            float2 aB = *(float2*)(y1s + (m0b + row + 8) * 264 + kg + 2 * quad);
            #pragma unroll
            for (int nt = 0; nt < 4; nt++) {
                float2 bv = *(float2*)(wts + (n0b + nt * 8 + row) * 72 + kb + 2 * quad);
                mma_tf32(ac2[nt], aA.x, aB.x, aA.y, aB.y, bv.x, bv.y);
            }
        }
        __syncthreads();
    }

    // ---- epilogue: + b2, write (bs, o, l) ----
    float* og = out + (size_t)bs * OUTC_ * L_;
    int l = l0 + m0b + row;
    #pragma unroll
    for (int nt = 0; nt < 4; nt++) {
        int col = n0b + nt * 8 + 2 * quad;
        float bb0 = b2[col], bb1 = b2[col + 1];
        og[(size_t)col * L_ + l]           = ac2[nt][0] + bb0;
        og[(size_t)(col + 1) * L_ + l]     = ac2[nt][1] + bb1;
        og[(size_t)col * L_ + l + 8]       = ac2[nt][2] + bb0;
        og[(size_t)(col + 1) * L_ + l + 8] = ac2[nt][3] + bb1;
    }
}

// ---------------- launch ----------------
extern "C" void kernel_launch(void* const* d_in, const int* in_sizes, int n_in,
                              void* d_out, int out_size) {
    const float* x      = (const float*)d_in[0];
    const float* qk_w   = (const float*)d_in[1];
    const float* v_w    = (const float*)d_in[2];
    const float* cpb_w1 = (const float*)d_in[3];
    const float* cpb_b1 = (const float*)d_in[4];
    const float* cpb_w2 = (const float*)d_in[5];
    const float* sa_b   = (const float*)d_in[6];
    const float* mlp_b1 = (const float*)d_in[8];
    const float* mlp_b2 = (const float*)d_in[10];
    float* out = (float*)d_out;

    const int SMEM_QKV = (128 * 72 + 64 * 136 + 64 * 72) * 4;                  // 90112
    const int SMEM_ATT = (128 * 72 + 64 * 72 + 128 * 72) * 4;                  // 92160
    const int SMEM_MLP = (64 * 264 * 2 + 256 * 72) * 4;                        // 208896

    cudaFuncSetAttribute(qkv_kernel,  cudaFuncAttributeMaxDynamicSharedMemorySize, SMEM_QKV);
    cudaFuncSetAttribute(attn_kernel, cudaFuncAttributeMaxDynamicSharedMemorySize, SMEM_ATT);
    cudaFuncSetAttribute(mlp_kernel,  cudaFuncAttributeMaxDynamicSharedMemorySize, SMEM_MLP);

    prep_kernel<<<640, 256>>>(qk_w, v_w, (const float*)d_in[7], (const float*)d_in[9]);
    cpb_bias_kernel<<<(L_ * L_) / 256, 256>>>(cpb_w1, cpb_b1, cpb_w2);
    qkv_kernel<<<dim3(9, BS_), 256, SMEM_QKV>>>(x);
    attn_kernel<<<dim3(5, BS_ * HEADS_), 256, SMEM_ATT>>>(sa_b);
    mlp_kernel<<<BS_ * 9, 512, SMEM_MLP>>>(mlp_b1, mlp_b2, out);
}

// round 11
// speedup vs baseline: 1.4292x; 1.1293x over previous
#include <cuda_runtime.h>
#include <cuda_bf16.h>
#include <math.h>

#define B_     2
#define S_     32
#define BS_    64
#define C_     128
#define HGT    24
#define WID    24
#define L_     576
#define HEADS_ 2
#define QKD_   64
#define VD_    128
#define HID_   256
#define OUTC_  128

// ---------------- scratch (static device globals; no allocation) ----------------
__device__ float g_bias[HEADS_ * L_ * L_];            // (head, i, j)  fp32, true order
__device__ float g_q[BS_ * HEADS_ * L_ * QKD_];       // [bs,h][l][d-interleaved], tf32
__device__ float g_k[BS_ * HEADS_ * L_ * QKD_];       // [bs,h][l][d-interleaved], tf32
__device__ float g_v[BS_ * HEADS_ * VD_ * L_];        // [bs,h][d][l NATURAL], tf32
__device__ float g_att[BS_ * L_ * HID_];              // [bs][l][ch-interleaved], tf32
// pre-permuted + tf32-rounded weights (k-dim interleaved within 8-blocks)
__device__ float g_wqk[2 * C_ * C_];                  // 256 x 128
__device__ float g_wv [HID_ * C_];                    // 256 x 128
__device__ float g_w1p[HID_ * HID_];                  // 256 x 256
__device__ float g_w2p[OUTC_ * HID_];                 // 128 x 256

// ---------------- helpers ----------------
__device__ __forceinline__ int perm8(int i) {
    return (i & ~7) | (((i & 3) << 1) | ((i >> 2) & 1));
}
__device__ __forceinline__ unsigned f2tf(float f) {
    unsigned r;
    asm("cvt.rna.tf32.f32 %0, %1;" : "=r"(r) : "f"(f));
    return r;
}
__device__ __forceinline__ float tfr(float f) { return __uint_as_float(f2tf(f)); }
__device__ __forceinline__ void mma_tf32(float c[4],
                                         float a0, float a1, float a2, float a3,
                                         float b0, float b1) {
    asm volatile(
        "mma.sync.aligned.m16n8k8.row.col.f32.tf32.tf32.f32 "
        "{%0,%1,%2,%3}, {%4,%5,%6,%7}, {%8,%9}, {%0,%1,%2,%3};"
        : "+f"(c[0]), "+f"(c[1]), "+f"(c[2]), "+f"(c[3])
        : "r"(__float_as_uint(a0)), "r"(__float_as_uint(a1)),
          "r"(__float_as_uint(a2)), "r"(__float_as_uint(a3)),
          "r"(__float_as_uint(b0)), "r"(__float_as_uint(b1)));
}
__device__ __forceinline__ void cp16(unsigned dst, const void* src) {
    asm volatile("cp.async.cg.shared.global [%0], [%1], 16;" :: "r"(dst), "l"(src) : "memory");
}
#define CP_COMMIT() asm volatile("cp.async.commit_group;" ::: "memory")
#define CP_WAIT0()  asm volatile("cp.async.wait_group 0;" ::: "memory")

// ---------------- kernel 0: weight prep (permute k within 8-blocks + tf32 round) ----------------
__global__ void prep_kernel(const float* __restrict__ qk_w, const float* __restrict__ v_w,
                            const float* __restrict__ w1, const float* __restrict__ w2) {
    int idx = blockIdx.x * 256 + threadIdx.x;     // 0 .. 163839
    if (idx < 32768) {
        int o = idx >> 7, k = idx & 127;
        g_wqk[(o << 7) | perm8(k)] = tfr(qk_w[idx]);
    } else if (idx < 65536) {
        int j = idx - 32768; int o = j >> 7, k = j & 127;
        g_wv[(o << 7) | perm8(k)] = tfr(v_w[j]);
    } else if (idx < 131072) {
        int j = idx - 65536; int o = j >> 8, k = j & 255;
        g_w1p[(o << 8) | perm8(k)] = tfr(w1[j]);
    } else {
        int j = idx - 131072; int o = j >> 8, k = j & 255;
        g_w2p[(o << 8) | perm8(k)] = tfr(w2[j]);
    }
}

// ---------------- kernel 1: continuous relative position bias ----------------
__global__ void cpb_bias_kernel(const float* __restrict__ w1,
                                const float* __restrict__ b1,
                                const float* __restrict__ w2) {
    __shared__ float s_w1[256];
    __shared__ float s_b1[128];
    __shared__ float s_w2[256];
    int tid = threadIdx.x;
    s_w1[tid] = w1[tid];
    if (tid < 128) s_b1[tid] = b1[tid];
    s_w2[tid] = w2[tid];
    __syncthreads();

    int idx = blockIdx.x * 256 + tid;      // < 576*576
    int i = idx / L_, j = idx % L_;
    int yi = i / WID, xi = i % WID;
    int yj = j / WID, xj = j % WID;
    float ry = (float)(yi - yj) * (8.0f / 23.0f);
    float rx = (float)(xi - xj) * (8.0f / 23.0f);
    ry = copysignf(log2f(1.0f + fabsf(ry)) * (1.0f / 3.0f), ry);
    rx = copysignf(log2f(1.0f + fabsf(rx)) * (1.0f / 3.0f), rx);

    float acc0 = 0.f, acc1 = 0.f;
    #pragma unroll 4
    for (int k = 0; k < 128; k++) {
        float h = fmaxf(0.f, ry * s_w1[2 * k] + rx * s_w1[2 * k + 1] + s_b1[k]);
        acc0 += h * s_w2[k];
        acc1 += h * s_w2[128 + k];
    }
    g_bias[idx] = acc0;
    g_bias[L_ * L_ + idx] = acc1;
}

// ---------------- kernel 2: QKV projection, tf32 mma ----------------
// Block: (l-tile 64, bs). 256 threads = 8 warps.
__global__ void qkv_kernel(const float* __restrict__ x) {
    int bs = blockIdx.y;
    int l0 = blockIdx.x * 64;
    extern __shared__ float sm[];
    float* xs   = sm;                   // 128*72
    float* ws   = xs + 128 * 72;        // 64*136
    float* outs = ws + 64 * 136;        // 64*72

    int tid = threadIdx.x;
    const float* xb = x + (size_t)bs * C_ * L_;
    for (int idx = tid; idx < 128 * 16; idx += 256) {
        int c = idx >> 4, lv = idx & 15;
        float4 v4 = *(const float4*)(xb + (size_t)c * L_ + l0 + lv * 4);
        v4.x = tfr(v4.x); v4.y = tfr(v4.y); v4.z = tfr(v4.z); v4.w = tfr(v4.w);
        *(float4*)(xs + c * 72 + lv * 4) = v4;
    }

    int warp = tid >> 5, lane = tid & 31;
    int row = lane >> 2, quad = lane & 3;
    int m0 = (warp & 3) * 16;           // o within chunk
    int n0 = (warp >> 2) * 32;          // l within tile

    for (int ot = 0; ot < 8; ot++) {
        const float* wsrc = (ot < 4) ? g_wqk + (size_t)ot * 64 * C_
                                     : g_wv  + (size_t)(ot - 4) * 64 * C_;
        __syncthreads();
        for (int idx = tid; idx < 64 * 32; idx += 256) {
            int o = idx >> 5, kv = idx & 31;
            *(float4*)(ws + o * 136 + kv * 4) = *(const float4*)(wsrc + (size_t)o * C_ + kv * 4);
        }
        __syncthreads();

        float acc[4][4] = {};
        #pragma unroll
        for (int kk = 0; kk < 16; kk++) {
            int k0 = kk * 8;
            float2 aA = *(float2*)(ws + (m0 + row) * 136 + k0 + 2 * quad);      // a0,a2
            float2 aB = *(float2*)(ws + (m0 + row + 8) * 136 + k0 + 2 * quad);  // a1,a3
            #pragma unroll
            for (int nt = 0; nt < 4; nt++) {
                int n = n0 + nt * 8;
                float b0 = xs[(k0 + quad) * 72 + n + row];
                float b1 = xs[(k0 + quad + 4) * 72 + n + row];
                mma_tf32(acc[nt], aA.x, aB.x, aA.y, aB.y, b0, b1);
            }
        }

        if (ot < 4) {
            // Q/K: outs[l][perm(d)]
            int po0 = perm8(m0 + row), po1 = perm8(m0 + row + 8);
            #pragma unroll
            for (int nt = 0; nt < 4; nt++) {
                int n = n0 + nt * 8 + 2 * quad;
                outs[n * 72 + po0]       = tfr(acc[nt][0]);
                outs[(n + 1) * 72 + po0] = tfr(acc[nt][1]);
                outs[n * 72 + po1]       = tfr(acc[nt][2]);
                outs[(n + 1) * 72 + po1] = tfr(acc[nt][3]);
            }
            __syncthreads();
            float* dst = (ot < 2) ? g_q + (size_t)(bs * 2 + ot) * L_ * QKD_
                                  : g_k + (size_t)(bs * 2 + ot - 2) * L_ * QKD_;
            for (int idx = tid; idx < 64 * 16; idx += 256) {
                int l = idx >> 4, j = idx & 15;
                *(float4*)(dst + (size_t)(l0 + l) * QKD_ + j * 4) =
                    *(float4*)(outs + l * 72 + j * 4);
            }
        } else {
            // V: outs[d][l]  (transposed, NATURAL l order)
            #pragma unroll
            for (int nt = 0; nt < 4; nt++) {
                int cl = n0 + nt * 8 + 2 * quad;
                outs[(m0 + row) * 72 + cl]         = tfr(acc[nt][0]);
                outs[(m0 + row) * 72 + cl + 1]     = tfr(acc[nt][1]);
                outs[(m0 + row + 8) * 72 + cl]     = tfr(acc[nt][2]);
                outs[(m0 + row + 8) * 72 + cl + 1] = tfr(acc[nt][3]);
            }
            __syncthreads();
            int o2 = (ot - 4) * 64;
            int head = o2 >> 7, dof = o2 & 127;
            float* dst = g_v + (size_t)(bs * 2 + head) * VD_ * L_;
            for (int idx = tid; idx < 64 * 16; idx += 256) {
                int o = idx >> 4, j = idx & 15;
                *(float4*)(dst + (size_t)(dof + o) * L_ + l0 + j * 4) =
                    *(float4*)(outs + o * 72 + j * 4);
            }
        }
    }
}

// ---------------- kernel 3: flash attention, register-resident P, wave-balanced ----------------
// Full tile: NDT=16, warp owns 16 q-rows x 128 d. Pair tile: NDT=8, warp owns 16 rows x 64-d half.
template<int NDT>
__device__ __forceinline__ void attn_tile(int bs, int head, int q0, int m0, int n0v,
                                          float* qs, float* ks, float* vt,
                                          const float* __restrict__ sa_bias) {
    const float* qg = g_q + (size_t)(bs * 2 + head) * L_ * QKD_;
    const float* kg = g_k + (size_t)(bs * 2 + head) * L_ * QKD_;
    const float* vg = g_v + (size_t)(bs * 2 + head) * VD_ * L_;
    const float* bg = g_bias + (size_t)head * L_ * L_;

    int tid = threadIdx.x;
    int lane = tid & 31;
    int row = lane >> 2, quad = lane & 3;

    __syncthreads();   // protect qs/ks/vt from previous tile's readers
    // load q tile [128][64] (d-interleaved), zero-fill rows >= 576
    for (int idx = tid; idx < 128 * 16; idx += 256) {
        int l = idx >> 4, dv = idx & 15;
        float4 v4 = make_float4(0.f, 0.f, 0.f, 0.f);
        if (q0 + l < L_)
            v4 = *(const float4*)(qg + (size_t)(q0 + l) * QKD_ + dv * 4);
        *(float4*)(qs + l * 72 + dv * 4) = v4;
    }

    float oac[NDT][4] = {};
    float mr0 = -1e30f, mr1 = -1e30f;
    float lr0 = 0.f, lr1 = 0.f;

    int r0g = q0 + m0 + row;
    int rb0 = (r0g < L_) ? r0g : L_ - 1;
    int rb1 = (r0g + 8 < L_) ? r0g + 8 : L_ - 1;
    const float* bgr0 = bg + (size_t)rb0 * L_;
    const float* bgr1 = bg + (size_t)rb1 * L_;

    for (int kt = 0; kt < 9; kt++) {
        int k0g = kt * 64;
        __syncthreads();
        for (int idx = tid; idx < 64 * 16; idx += 256) {
            int l = idx >> 4, dv = idx & 15;
            *(float4*)(ks + l * 72 + dv * 4) =
                *(const float4*)(kg + (size_t)(k0g + l) * QKD_ + dv * 4);
        }
        for (int idx = tid; idx < 128 * 16; idx += 256) {
            int d = idx >> 4, j = idx & 15;
            *(float4*)(vt + d * 72 + j * 4) =
                *(const float4*)(vg + (size_t)d * L_ + k0g + j * 4);
        }
        __syncthreads();

        // ---- S = Q K^T : warp m16 x n64 (8 n-tiles), accumulators in regs ----
        float p[8][4] = {};
        #pragma unroll
        for (int kk = 0; kk < 8; kk++) {
            int k0 = kk * 8;
            float2 aA = *(float2*)(qs + (m0 + row) * 72 + k0 + 2 * quad);
            float2 aB = *(float2*)(qs + (m0 + row + 8) * 72 + k0 + 2 * quad);
            #pragma unroll
            for (int nt = 0; nt < 8; nt++) {
                float2 bv = *(float2*)(ks + (nt * 8 + row) * 72 + k0 + 2 * quad);
                mma_tf32(p[nt], aA.x, aB.x, aA.y, aB.y, bv.x, bv.y);
            }
        }
        #pragma unroll
        for (int nt = 0; nt < 8; nt++) {
            int ct = k0g + nt * 8 + 2 * quad;
            p[nt][0] = p[nt][0] * 0.125f + bgr0[ct];
            p[nt][1] = p[nt][1] * 0.125f + bgr0[ct + 1];
            p[nt][2] = p[nt][2] * 0.125f + bgr1[ct];
            p[nt][3] = p[nt][3] * 0.125f + bgr1[ct + 1];
        }

        // ---- online softmax in registers (row owned by quad: shuffle xor 1,2) ----
        float tm0 = -1e30f, tm1 = -1e30f;
        #pragma unroll
        for (int nt = 0; nt < 8; nt++) {
            tm0 = fmaxf(tm0, fmaxf(p[nt][0], p[nt][1]));
            tm1 = fmaxf(tm1, fmaxf(p[nt][2], p[nt][3]));
        }
        tm0 = fmaxf(tm0, __shfl_xor_sync(0xffffffffu, tm0, 1));
        tm0 = fmaxf(tm0, __shfl_xor_sync(0xffffffffu, tm0, 2));
        tm1 = fmaxf(tm1, __shfl_xor_sync(0xffffffffu, tm1, 1));
        tm1 = fmaxf(tm1, __shfl_xor_sync(0xffffffffu, tm1, 2));
        float mn0 = fmaxf(mr0, tm0), mn1 = fmaxf(mr1, tm1);
        float al0 = __expf(mr0 - mn0), al1 = __expf(mr1 - mn1);
        mr0 = mn0; mr1 = mn1;

        float s0 = 0.f, s1 = 0.f;
        #pragma unroll
        for (int nt = 0; nt < 8; nt++) {
            float e0 = __expf(p[nt][0] - mn0);
            float e1 = __expf(p[nt][1] - mn0);
            float e2 = __expf(p[nt][2] - mn1);
            float e3 = __expf(p[nt][3] - mn1);
            s0 += e0 + e1; s1 += e2 + e3;
            p[nt][0] = tfr(e0); p[nt][1] = tfr(e1);
            p[nt][2] = tfr(e2); p[nt][3] = tfr(e3);
        }
        s0 += __shfl_xor_sync(0xffffffffu, s0, 1);
        s0 += __shfl_xor_sync(0xffffffffu, s0, 2);
        s1 += __shfl_xor_sync(0xffffffffu, s1, 1);
        s1 += __shfl_xor_sync(0xffffffffu, s1, 2);
        lr0 = al0 * lr0 + s0;
        lr1 = al1 * lr1 + s1;

        // ---- AV: P (regs) x V (smem, natural keys); rescale then accumulate ----
        #pragma unroll
        for (int dt = 0; dt < NDT; dt++) {
            oac[dt][0] *= al0; oac[dt][1] *= al0;
            oac[dt][2] *= al1; oac[dt][3] *= al1;
        }
        #pragma unroll
        for (int kb = 0; kb < 8; kb++) {
            int kc = kb * 8 + 2 * quad;
            #pragma unroll
            for (int dt = 0; dt < NDT; dt++) {
                float2 bv = *(float2*)(vt + (n0v + dt * 8 + row) * 72 + kc);
                mma_tf32(oac[dt], p[kb][0], p[kb][2], p[kb][1], p[kb][3], bv.x, bv.y);
            }
        }
    }

    // ---- epilogue: normalize, + sa_bias, ch-interleaved tf32 write (masked) ----
    float inv0 = 1.0f / lr0;
    float inv1 = 1.0f / lr1;
    float* og = g_att + (size_t)bs * L_ * HID_;
    int l = q0 + m0 + row;
    #pragma unroll
    for (int dt = 0; dt < NDT; dt++) {
        int ch = head * 128 + n0v + dt * 8 + 2 * quad;
        int pc0 = perm8(ch), pc1 = perm8(ch + 1);
        float sb0 = sa_bias[ch], sb1 = sa_bias[ch + 1];
        if (l < L_) {
            og[(size_t)l * HID_ + pc0] = tfr(oac[dt][0] * inv0 + sb0);
            og[(size_t)l * HID_ + pc1] = tfr(oac[dt][1] * inv0 + sb1);
        }
        if (l + 8 < L_) {
            og[(size_t)(l + 8) * HID_ + pc0] = tfr(oac[dt][2] * inv1 + sb0);
            og[(size_t)(l + 8) * HID_ + pc1] = tfr(oac[dt][3] * inv1 + sb1);
        }
    }
}

// grid.x = 576: idx 0..63 pair tiles (both heads' qt4 tails, slow-first), 64..575 full tiles
__global__ void __launch_bounds__(256, 2) attn_kernel(const float* __restrict__ sa_bias) {
    extern __shared__ float sm[];
    float* qs = sm;                    // 128*72
    float* ks = qs + 128 * 72;         // 64*72
    float* vt = ks + 64 * 72;          // 128*72

    int warp = threadIdx.x >> 5;
    int idx = blockIdx.x;
    if (idx < 64) {
        int m0  = (warp & 3) * 16;
        int n0v = (warp >> 2) * 64;
        attn_tile<8>(idx, 0, 512, m0, n0v, qs, ks, vt, sa_bias);
        attn_tile<8>(idx, 1, 512, m0, n0v, qs, ks, vt, sa_bias);
    } else {
        int t = idx - 64;
        int bh = t >> 2, qt = t & 3;
        attn_tile<16>(bh >> 1, bh & 1, qt * 128, warp * 16, 0, qs, ks, vt, sa_bias);
    }
}

// ---------------- kernel 4: MLP, cp.async double-buffered weights, 512 threads ----------------
// smem: xsm[64][264], y1s[64][264], wts 2 x [256][40]
__global__ void mlp_kernel(const float* __restrict__ b1, const float* __restrict__ b2,
                           float* __restrict__ out) {
    int blk = blockIdx.x;                // 0..575
    int bs = blk / 9;
    int l0 = (blk % 9) * 64;
    extern __shared__ float sm[];
    float* xsm = sm;                     // 64*264 = 16896
    float* y1s = xsm + 64 * 264;         // 16896
    float* wts = y1s + 64 * 264;         // 2 x 10240

    unsigned wts_u = (unsigned)__cvta_generic_to_shared(wts);

    int tid = threadIdx.x;
    int warp = tid >> 5, lane = tid & 31;
    int row = lane >> 2, quad = lane & 3;

    const float* ag = g_att + ((size_t)bs * L_ + l0) * HID_;
    for (int idx = tid; idx < 64 * 64; idx += 512) {
        int p = idx >> 6, iv = idx & 63;
        *(float4*)(xsm + p * 264 + iv * 4) = *(const float4*)(ag + (size_t)p * HID_ + iv * 4);
    }

    // ---- GEMM1: Y1(64x256) = X @ W1^T : warp tile m32 x n32, k-chunks of 32, double-buffered ----
    int m0 = (warp & 1) * 32;
    int n0 = (warp >> 1) * 32;
    // prologue: issue chunk 0
    for (int j = tid; j < 2048; j += 512) {
        int o = j >> 3, kv = j & 7;
        cp16(wts_u + (unsigned)(o * 40 + kv * 4) * 4,
             g_w1p + (size_t)o * HID_ + kv * 4);
    }
    CP_COMMIT();

    float acc[2][4][4] = {};
    for (int c = 0; c < 8; c++) {
        CP_WAIT0();
        __syncthreads();
        if (c < 7) {
            int b = (c + 1) & 1;
            for (int j = tid; j < 2048; j += 512) {
                int o = j >> 3, kv = j & 7;
                cp16(wts_u + (unsigned)(b * 10240 + o * 40 + kv * 4) * 4,
                     g_w1p + (size_t)o * HID_ + (c + 1) * 32 + kv * 4);
            }
            CP_COMMIT();
        }
        const float* wb = wts + (c & 1) * 10240;
        #pragma unroll
        for (int kk = 0; kk < 4; kk++) {
            int kg = c * 32 + kk * 8;
            int kb = kk * 8;
            float2 aA[2], aB[2];
            #pragma unroll
            for (int mt = 0; mt < 2; mt++) {
                aA[mt] = *(float2*)(xsm + (m0 + mt * 16 + row) * 264 + kg + 2 * quad);
                aB[mt] = *(float2*)(xsm + (m0 + mt * 16 + row + 8) * 264 + kg + 2 * quad);
            }
            #pragma unroll
            for (int nt = 0; nt < 4; nt++) {
                float2 bv = *(float2*)(wb + (n0 + nt * 8 + row) * 40 + kb + 2 * quad);
                mma_tf32(acc[0][nt], aA[0].x, aB[0].x, aA[0].y, aB[0].y, bv.x, bv.y);
                mma_tf32(acc[1][nt], aA[1].x, aB[1].x, aA[1].y, aB[1].y, bv.x, bv.y);
            }
        }
    }
    // bias + exact GELU -> y1s[p][perm(o)], tf32-rounded
    #pragma unroll
    for (int mt = 0; mt < 2; mt++) {
        #pragma unroll
        for (int nt = 0; nt < 4; nt++) {
            int col = n0 + nt * 8 + 2 * quad;
            int p0 = perm8(col), p1 = perm8(col + 1);
            float bb0 = b1[col], bb1 = b1[col + 1];
            int r = m0 + mt * 16 + row;
            float v0 = acc[mt][nt][0] + bb0;
            float v1 = acc[mt][nt][1] + bb1;
            float v2 = acc[mt][nt][2] + bb0;
            float v3 = acc[mt][nt][3] + bb1;
            y1s[r * 264 + p0]       = tfr(0.5f * v0 * (1.0f + erff(v0 * 0.70710678118654752f)));
            y1s[r * 264 + p1]       = tfr(0.5f * v1 * (1.0f + erff(v1 * 0.70710678118654752f)));
            y1s[(r + 8) * 264 + p0] = tfr(0.5f * v2 * (1.0f + erff(v2 * 0.70710678118654752f)));
            y1s[(r + 8) * 264 + p1] = tfr(0.5f * v3 * (1.0f + erff(v3 * 0.70710678118654752f)));
        }
    }
    __syncthreads();

    // ---- GEMM2: OUT(64x128) = Y1 @ W2^T : warp tile m16 x n32, k-chunks of 32, double-buffered ----
    int m0b = (warp & 3) * 16;
    int n0b = (warp >> 2) * 32;
    for (int j = tid; j < 1024; j += 512) {
        int o = j >> 3, kv = j & 7;
        cp16(wts_u + (unsigned)(o * 40 + kv * 4) * 4,
             g_w2p + (size_t)o * HID_ + kv * 4);
    }
    CP_COMMIT();

    float ac2[4][4] = {};
    for (int c = 0; c < 8; c++) {
        CP_WAIT0();
        __syncthreads();
        if (c < 7) {
            int b = (c + 1) & 1;
            for (int j = tid; j < 1024; j += 512) {
                int o = j >> 3, kv = j & 7;
                cp16(wts_u + (unsigned)(b * 10240 + o * 40 + kv * 4) * 4,
                     g_w2p + (size_t)o * HID_ + (c + 1) * 32 + kv * 4);
            }
            CP_COMMIT();
        }
        const float* wb = wts + (c & 1) * 10240;
        #pragma unroll
        for (int kk = 0; kk < 4; kk++) {
            int kg = c * 32 + kk * 8;
            int kb = kk * 8;
            float2 aA = *(float2*)(y1s + (m0b + row) * 264 + kg + 2 * quad);
            float2 aB = *(float2*)(y1s + (m0b + row + 8) * 264 + kg + 2 * quad);
            #pragma unroll
            for (int nt = 0; nt < 4; nt++) {
                float2 bv = *(float2*)(wb + (n0b + nt * 8 + row) * 40 + kb + 2 * quad);
                mma_tf32(ac2[nt], aA.x, aB.x, aA.y, aB.y, bv.x, bv.y);
            }
        }
    }

    // ---- epilogue: + b2, write (bs, o, l) ----
    float* og = out + (size_t)bs * OUTC_ * L_;
    int l = l0 + m0b + row;
    #pragma unroll
    for (int nt = 0; nt < 4; nt++) {
        int col = n0b + nt * 8 + 2 * quad;
        float bb0 = b2[col], bb1 = b2[col + 1];
        og[(size_t)col * L_ + l]           = ac2[nt][0] + bb0;
        og[(size_t)(col + 1) * L_ + l]     = ac2[nt][1] + bb1;
        og[(size_t)col * L_ + l + 8]       = ac2[nt][2] + bb0;
        og[(size_t)(col + 1) * L_ + l + 8] = ac2[nt][3] + bb1;
    }
}

// ---------------- launch ----------------
extern "C" void kernel_launch(void* const* d_in, const int* in_sizes, int n_in,
                              void* d_out, int out_size) {
    const float* x      = (const float*)d_in[0];
    const float* qk_w   = (const float*)d_in[1];
    const float* v_w    = (const float*)d_in[2];
    const float* cpb_w1 = (const float*)d_in[3];
    const float* cpb_b1 = (const float*)d_in[4];
    const float* cpb_w2 = (const float*)d_in[5];
    const float* sa_b   = (const float*)d_in[6];
    const float* mlp_b1 = (const float*)d_in[8];
    const float* mlp_b2 = (const float*)d_in[10];
    float* out = (float*)d_out;

    const int SMEM_QKV = (128 * 72 + 64 * 136 + 64 * 72) * 4;                  // 90112
    const int SMEM_ATT = (128 * 72 + 64 * 72 + 128 * 72) * 4;                  // 92160
    const int SMEM_MLP = (64 * 264 * 2 + 2 * 256 * 40) * 4;                    // 217088

    cudaFuncSetAttribute(qkv_kernel,  cudaFuncAttributeMaxDynamicSharedMemorySize, SMEM_QKV);
    cudaFuncSetAttribute(attn_kernel, cudaFuncAttributeMaxDynamicSharedMemorySize, SMEM_ATT);
    cudaFuncSetAttribute(mlp_kernel,  cudaFuncAttributeMaxDynamicSharedMemorySize, SMEM_MLP);

    prep_kernel<<<640, 256>>>(qk_w, v_w, (const float*)d_in[7], (const float*)d_in[9]);
    cpb_bias_kernel<<<(L_ * L_) / 256, 256>>>(cpb_w1, cpb_b1, cpb_w2);
    qkv_kernel<<<dim3(9, BS_), 256, SMEM_QKV>>>(x);
    attn_kernel<<<576, 256, SMEM_ATT>>>(sa_b);
    mlp_kernel<<<BS_ * 9, 512, SMEM_MLP>>>(mlp_b1, mlp_b2, out);
}

// round 12
// speedup vs baseline: 1.6142x; 1.1295x over previous
#include <cuda_runtime.h>
#include <cuda_bf16.h>
#include <math.h>

#define B_     2
#define S_     32
#define BS_    64
#define C_     128
#define HGT    24
#define WID    24
#define L_     576
#define HEADS_ 2
#define QKD_   64
#define VD_    128
#define HID_   256
#define OUTC_  128

// ---------------- scratch (static device globals; no allocation) ----------------
__device__ float g_bias[HEADS_ * L_ * L_];            // (head, i, j)  fp32, true order
__device__ float2 g_lut[47 * 47];                     // cpb values by (dy+23, dx+23)
__device__ float g_q[BS_ * HEADS_ * L_ * QKD_];       // [bs,h][l][d-interleaved], tf32
__device__ float g_k[BS_ * HEADS_ * L_ * QKD_];       // [bs,h][l][d-interleaved], tf32
__device__ float g_v[BS_ * HEADS_ * VD_ * L_];        // [bs,h][d][l NATURAL], tf32
__device__ float g_att[BS_ * L_ * HID_];              // [bs][l][ch-interleaved], tf32
// pre-permuted + tf32-rounded weights (k-dim interleaved within 8-blocks)
__device__ float g_wqk[2 * C_ * C_];                  // 256 x 128
__device__ float g_wv [HID_ * C_];                    // 256 x 128
__device__ float g_w1p[HID_ * HID_];                  // 256 x 256
__device__ float g_w2p[OUTC_ * HID_];                 // 128 x 256

// ---------------- helpers ----------------
__device__ __forceinline__ int perm8(int i) {
    return (i & ~7) | (((i & 3) << 1) | ((i >> 2) & 1));
}
__device__ __forceinline__ unsigned f2tf(float f) {
    unsigned r;
    asm("cvt.rna.tf32.f32 %0, %1;" : "=r"(r) : "f"(f));
    return r;
}
__device__ __forceinline__ float tfr(float f) { return __uint_as_float(f2tf(f)); }
__device__ __forceinline__ void mma_tf32(float c[4],
                                         float a0, float a1, float a2, float a3,
                                         float b0, float b1) {
    asm volatile(
        "mma.sync.aligned.m16n8k8.row.col.f32.tf32.tf32.f32 "
        "{%0,%1,%2,%3}, {%4,%5,%6,%7}, {%8,%9}, {%0,%1,%2,%3};"
        : "+f"(c[0]), "+f"(c[1]), "+f"(c[2]), "+f"(c[3])
        : "r"(__float_as_uint(a0)), "r"(__float_as_uint(a1)),
          "r"(__float_as_uint(a2)), "r"(__float_as_uint(a3)),
          "r"(__float_as_uint(b0)), "r"(__float_as_uint(b1)));
}
__device__ __forceinline__ void cp16(unsigned dst, const void* src) {
    asm volatile("cp.async.cg.shared.global [%0], [%1], 16;" :: "r"(dst), "l"(src) : "memory");
}
#define CP_COMMIT() asm volatile("cp.async.commit_group;" ::: "memory")
#define CP_WAIT0()  asm volatile("cp.async.wait_group 0;" ::: "memory")
#define CP_WAIT1()  asm volatile("cp.async.wait_group 1;" ::: "memory")

// ---------------- kernel 0: weight prep (permute k within 8-blocks + tf32 round) ----------------
__global__ void prep_kernel(const float* __restrict__ qk_w, const float* __restrict__ v_w,
                            const float* __restrict__ w1, const float* __restrict__ w2) {
    int idx = blockIdx.x * 256 + threadIdx.x;     // 0 .. 163839
    if (idx < 32768) {
        int o = idx >> 7, k = idx & 127;
        g_wqk[(o << 7) | perm8(k)] = tfr(qk_w[idx]);
    } else if (idx < 65536) {
        int j = idx - 32768; int o = j >> 7, k = j & 127;
        g_wv[(o << 7) | perm8(k)] = tfr(v_w[j]);
    } else if (idx < 131072) {
        int j = idx - 65536; int o = j >> 8, k = j & 255;
        g_w1p[(o << 8) | perm8(k)] = tfr(w1[j]);
    } else {
        int j = idx - 131072; int o = j >> 8, k = j & 255;
        g_w2p[(o << 8) | perm8(k)] = tfr(w2[j]);
    }
}

// ---------------- kernel 1a: cpb LUT over the 47x47 distinct (dy,dx) offsets ----------------
__global__ void cpb_lut_kernel(const float* __restrict__ w1,
                               const float* __restrict__ b1,
                               const float* __restrict__ w2) {
    __shared__ float s_w1[256];
    __shared__ float s_b1[128];
    __shared__ float s_w2[256];
    int tid = threadIdx.x;
    s_w1[tid] = w1[tid];
    if (tid < 128) s_b1[tid] = b1[tid];
    s_w2[tid] = w2[tid];
    __syncthreads();

    int idx = blockIdx.x * 256 + tid;      // < 2209
    if (idx >= 47 * 47) return;
    int dy = idx / 47 - 23;
    int dx = idx % 47 - 23;
    float ry = (float)dy * (8.0f / 23.0f);
    float rx = (float)dx * (8.0f / 23.0f);
    ry = copysignf(log2f(1.0f + fabsf(ry)) * (1.0f / 3.0f), ry);
    rx = copysignf(log2f(1.0f + fabsf(rx)) * (1.0f / 3.0f), rx);

    float acc0 = 0.f, acc1 = 0.f;
    #pragma unroll 4
    for (int k = 0; k < 128; k++) {
        float h = fmaxf(0.f, ry * s_w1[2 * k] + rx * s_w1[2 * k + 1] + s_b1[k]);
        acc0 += h * s_w2[k];
        acc1 += h * s_w2[128 + k];
    }
    g_lut[idx] = make_float2(acc0, acc1);
}

// ---------------- kernel 1b: bias fill by gather ----------------
__global__ void cpb_fill_kernel() {
    int idx = blockIdx.x * 256 + threadIdx.x;      // < 576*576
    int i = idx / L_, j = idx % L_;
    int yi = i / WID, xi = i % WID;
    int yj = j / WID, xj = j % WID;
    float2 v = g_lut[(yi - yj + 23) * 47 + (xi - xj + 23)];
    g_bias[idx] = v.x;
    g_bias[L_ * L_ + idx] = v.y;
}

// ---------------- kernel 2: QKV projection, tf32 mma ----------------
// Block: (l-tile 64, bs). 256 threads = 8 warps.
__global__ void qkv_kernel(const float* __restrict__ x) {
    int bs = blockIdx.y;
    int l0 = blockIdx.x * 64;
    extern __shared__ float sm[];
    float* xs   = sm;                   // 128*72
    float* ws   = xs + 128 * 72;        // 64*136
    float* outs = ws + 64 * 136;        // 64*72

    int tid = threadIdx.x;
    const float* xb = x + (size_t)bs * C_ * L_;
    for (int idx = tid; idx < 128 * 16; idx += 256) {
        int c = idx >> 4, lv = idx & 15;
        float4 v4 = *(const float4*)(xb + (size_t)c * L_ + l0 + lv * 4);
        v4.x = tfr(v4.x); v4.y = tfr(v4.y); v4.z = tfr(v4.z); v4.w = tfr(v4.w);
        *(float4*)(xs + c * 72 + lv * 4) = v4;
    }

    int warp = tid >> 5, lane = tid & 31;
    int row = lane >> 2, quad = lane & 3;
    int m0 = (warp & 3) * 16;           // o within chunk
    int n0 = (warp >> 2) * 32;          // l within tile

    for (int ot = 0; ot < 8; ot++) {
        const float* wsrc = (ot < 4) ? g_wqk + (size_t)ot * 64 * C_
                                     : g_wv  + (size_t)(ot - 4) * 64 * C_;
        __syncthreads();
        for (int idx = tid; idx < 64 * 32; idx += 256) {
            int o = idx >> 5, kv = idx & 31;
            *(float4*)(ws + o * 136 + kv * 4) = *(const float4*)(wsrc + (size_t)o * C_ + kv * 4);
        }
        __syncthreads();

        float acc[4][4] = {};
        #pragma unroll
        for (int kk = 0; kk < 16; kk++) {
            int k0 = kk * 8;
            float2 aA = *(float2*)(ws + (m0 + row) * 136 + k0 + 2 * quad);      // a0,a2
            float2 aB = *(float2*)(ws + (m0 + row + 8) * 136 + k0 + 2 * quad);  // a1,a3
            #pragma unroll
            for (int nt = 0; nt < 4; nt++) {
                int n = n0 + nt * 8;
                float b0 = xs[(k0 + quad) * 72 + n + row];
                float b1 = xs[(k0 + quad + 4) * 72 + n + row];
                mma_tf32(acc[nt], aA.x, aB.x, aA.y, aB.y, b0, b1);
            }
        }

        if (ot < 4) {
            // Q/K: outs[l][perm(d)]
            int po0 = perm8(m0 + row), po1 = perm8(m0 + row + 8);
            #pragma unroll
            for (int nt = 0; nt < 4; nt++) {
                int n = n0 + nt * 8 + 2 * quad;
                outs[n * 72 + po0]       = tfr(acc[nt][0]);
                outs[(n + 1) * 72 + po0] = tfr(acc[nt][1]);
                outs[n * 72 + po1]       = tfr(acc[nt][2]);
                outs[(n + 1) * 72 + po1] = tfr(acc[nt][3]);
            }
            __syncthreads();
            float* dst = (ot < 2) ? g_q + (size_t)(bs * 2 + ot) * L_ * QKD_
                                  : g_k + (size_t)(bs * 2 + ot - 2) * L_ * QKD_;
            for (int idx = tid; idx < 64 * 16; idx += 256) {
                int l = idx >> 4, j = idx & 15;
                *(float4*)(dst + (size_t)(l0 + l) * QKD_ + j * 4) =
                    *(float4*)(outs + l * 72 + j * 4);
            }
        } else {
            // V: outs[d][l]  (transposed, NATURAL l order)
            #pragma unroll
            for (int nt = 0; nt < 4; nt++) {
                int cl = n0 + nt * 8 + 2 * quad;
                outs[(m0 + row) * 72 + cl]         = tfr(acc[nt][0]);
                outs[(m0 + row) * 72 + cl + 1]     = tfr(acc[nt][1]);
                outs[(m0 + row + 8) * 72 + cl]     = tfr(acc[nt][2]);
                outs[(m0 + row + 8) * 72 + cl + 1] = tfr(acc[nt][3]);
            }
            __syncthreads();
            int o2 = (ot - 4) * 64;
            int head = o2 >> 7, dof = o2 & 127;
            float* dst = g_v + (size_t)(bs * 2 + head) * VD_ * L_;
            for (int idx = tid; idx < 64 * 16; idx += 256) {
                int o = idx >> 4, j = idx & 15;
                *(float4*)(dst + (size_t)(dof + o) * L_ + l0 + j * 4) =
                    *(float4*)(outs + o * 72 + j * 4);
            }
        }
    }
}

// ---------------- kernel 3: flash attention, register P + cp.async K/V pipeline ----------------
// Full tile: NDT=16, warp owns 16 q-rows x 128 d. Pair tile: NDT=8, warp owns 16 rows x 64-d half.
// smem: qs[128][72], ks 2x[64][72] (double-buffered), vt[128][72]
template<int NDT>
__device__ __forceinline__ void attn_tile(int bs, int head, int q0, int m0, int n0v,
                                          float* qs, float* ks, float* vt,
                                          const float* __restrict__ sa_bias) {
    const float* qg = g_q + (size_t)(bs * 2 + head) * L_ * QKD_;
    const float* kg = g_k + (size_t)(bs * 2 + head) * L_ * QKD_;
    const float* vg = g_v + (size_t)(bs * 2 + head) * VD_ * L_;
    const float* bg = g_bias + (size_t)head * L_ * L_;

    unsigned ks_u = (unsigned)__cvta_generic_to_shared(ks);
    unsigned vt_u = (unsigned)__cvta_generic_to_shared(vt);

    int tid = threadIdx.x;
    int lane = tid & 31;
    int row = lane >> 2, quad = lane & 3;

    __syncthreads();   // protect qs/ks/vt from previous tile's readers
    // load q tile [128][64] (d-interleaved), zero-fill rows >= 576
    for (int idx = tid; idx < 128 * 16; idx += 256) {
        int l = idx >> 4, dv = idx & 15;
        float4 v4 = make_float4(0.f, 0.f, 0.f, 0.f);
        if (q0 + l < L_)
            v4 = *(const float4*)(qg + (size_t)(q0 + l) * QKD_ + dv * 4);
        *(float4*)(qs + l * 72 + dv * 4) = v4;
    }

    // prologue: K(0) into ks buf0, V(0) into vt
    for (int j = tid; j < 1024; j += 256) {
        int l = j >> 4, dv = j & 15;
        cp16(ks_u + (unsigned)(l * 72 + dv * 4) * 4, kg + (size_t)l * QKD_ + dv * 4);
    }
    CP_COMMIT();
    for (int j = tid; j < 2048; j += 256) {
        int d = j >> 4, jj = j & 15;
        cp16(vt_u + (unsigned)(d * 72 + jj * 4) * 4, vg + (size_t)d * L_ + jj * 4);
    }
    CP_COMMIT();

    float oac[NDT][4] = {};
    float mr0 = -1e30f, mr1 = -1e30f;
    float lr0 = 0.f, lr1 = 0.f;

    int r0g = q0 + m0 + row;
    int rb0 = (r0g < L_) ? r0g : L_ - 1;
    int rb1 = (r0g + 8 < L_) ? r0g + 8 : L_ - 1;
    const float* bgr0 = bg + (size_t)rb0 * L_;
    const float* bgr1 = bg + (size_t)rb1 * L_;

    for (int kt = 0; kt < 9; kt++) {
        int k0g = kt * 64;
        if (kt > 0) {
            __syncthreads();            // AV(kt-1) done reading vt
            for (int j = tid; j < 2048; j += 256) {
                int d = j >> 4, jj = j & 15;
                cp16(vt_u + (unsigned)(d * 72 + jj * 4) * 4,
                     vg + (size_t)d * L_ + k0g + jj * 4);
            }
            CP_COMMIT();
        }
        CP_WAIT1();                     // K(kt) landed (V(kt) may still fly)
        __syncthreads();

        const float* kb = ks + (kt & 1) * (64 * 72);

        // ---- S = Q K^T : warp m16 x n64 (8 n-tiles), accumulators in regs ----
        float p[8][4] = {};
        #pragma unroll
        for (int kk = 0; kk < 8; kk++) {
            int k0 = kk * 8;
            float2 aA = *(float2*)(qs + (m0 + row) * 72 + k0 + 2 * quad);
            float2 aB = *(float2*)(qs + (m0 + row + 8) * 72 + k0 + 2 * quad);
            #pragma unroll
            for (int nt = 0; nt < 8; nt++) {
                float2 bv = *(float2*)(kb + (nt * 8 + row) * 72 + k0 + 2 * quad);
                mma_tf32(p[nt], aA.x, aB.x, aA.y, aB.y, bv.x, bv.y);
            }
        }
        #pragma unroll
        for (int nt = 0; nt < 8; nt++) {
            int ct = k0g + nt * 8 + 2 * quad;
            p[nt][0] = p[nt][0] * 0.125f + bgr0[ct];
            p[nt][1] = p[nt][1] * 0.125f + bgr0[ct + 1];
            p[nt][2] = p[nt][2] * 0.125f + bgr1[ct];
            p[nt][3] = p[nt][3] * 0.125f + bgr1[ct + 1];
        }

        // ---- online softmax in registers (row owned by quad: shuffle xor 1,2) ----
        float tm0 = -1e30f, tm1 = -1e30f;
        #pragma unroll
        for (int nt = 0; nt < 8; nt++) {
            tm0 = fmaxf(tm0, fmaxf(p[nt][0], p[nt][1]));
            tm1 = fmaxf(tm1, fmaxf(p[nt][2], p[nt][3]));
        }
        tm0 = fmaxf(tm0, __shfl_xor_sync(0xffffffffu, tm0, 1));
        tm0 = fmaxf(tm0, __shfl_xor_sync(0xffffffffu, tm0, 2));
        tm1 = fmaxf(tm1, __shfl_xor_sync(0xffffffffu, tm1, 1));
        tm1 = fmaxf(tm1, __shfl_xor_sync(0xffffffffu, tm1, 2));
        float mn0 = fmaxf(mr0, tm0), mn1 = fmaxf(mr1, tm1);
        float al0 = __expf(mr0 - mn0), al1 = __expf(mr1 - mn1);
        mr0 = mn0; mr1 = mn1;

        float s0 = 0.f, s1 = 0.f;
        #pragma unroll
        for (int nt = 0; nt < 8; nt++) {
            float e0 = __expf(p[nt][0] - mn0);
            float e1 = __expf(p[nt][1] - mn0);
            float e2 = __expf(p[nt][2] - mn1);
            float e3 = __expf(p[nt][3] - mn1);
            s0 += e0 + e1; s1 += e2 + e3;
            p[nt][0] = tfr(e0); p[nt][1] = tfr(e1);
            p[nt][2] = tfr(e2); p[nt][3] = tfr(e3);
        }
        s0 += __shfl_xor_sync(0xffffffffu, s0, 1);
        s0 += __shfl_xor_sync(0xffffffffu, s0, 2);
        s1 += __shfl_xor_sync(0xffffffffu, s1, 1);
        s1 += __shfl_xor_sync(0xffffffffu, s1, 2);
        lr0 = al0 * lr0 + s0;
        lr1 = al1 * lr1 + s1;

        CP_WAIT0();                     // V(kt) landed
        __syncthreads();                // V visible; all warps past S(kt) (frees other ks buf)
        if (kt < 8) {                   // prefetch K(kt+1) under AV(kt)
            unsigned kdst = ks_u + (unsigned)(((kt + 1) & 1) * 64 * 72) * 4;
            const float* ksrc = kg + (size_t)(k0g + 64) * QKD_;
            for (int j = tid; j < 1024; j += 256) {
                int l = j >> 4, dv = j & 15;
                cp16(kdst + (unsigned)(l * 72 + dv * 4) * 4, ksrc + (size_t)l * QKD_ + dv * 4);
            }
            CP_COMMIT();
        }

        // ---- AV: P (regs) x V (smem, natural keys); rescale then accumulate ----
        #pragma unroll
        for (int dt = 0; dt < NDT; dt++) {
            oac[dt][0] *= al0; oac[dt][1] *= al0;
            oac[dt][2] *= al1; oac[dt][3] *= al1;
        }
        #pragma unroll
        for (int kb2 = 0; kb2 < 8; kb2++) {
            int kc = kb2 * 8 + 2 * quad;
            #pragma unroll
            for (int dt = 0; dt < NDT; dt++) {
                float2 bv = *(float2*)(vt + (n0v + dt * 8 + row) * 72 + kc);
                mma_tf32(oac[dt], p[kb2][0], p[kb2][2], p[kb2][1], p[kb2][3], bv.x, bv.y);
            }
        }
    }
    CP_WAIT0();                         // drain (no pending groups leak across tiles)

    // ---- epilogue: normalize, + sa_bias, ch-interleaved tf32 write (masked) ----
    float inv0 = 1.0f / lr0;
    float inv1 = 1.0f / lr1;
    float* og = g_att + (size_t)bs * L_ * HID_;
    int l = q0 + m0 + row;
    #pragma unroll
    for (int dt = 0; dt < NDT; dt++) {
        int ch = head * 128 + n0v + dt * 8 + 2 * quad;
        int pc0 = perm8(ch), pc1 = perm8(ch + 1);
        float sb0 = sa_bias[ch], sb1 = sa_bias[ch + 1];
        if (l < L_) {
            og[(size_t)l * HID_ + pc0] = tfr(oac[dt][0] * inv0 + sb0);
            og[(size_t)l * HID_ + pc1] = tfr(oac[dt][1] * inv0 + sb1);
        }
        if (l + 8 < L_) {
            og[(size_t)(l + 8) * HID_ + pc0] = tfr(oac[dt][2] * inv1 + sb0);
            og[(size_t)(l + 8) * HID_ + pc1] = tfr(oac[dt][3] * inv1 + sb1);
        }
    }
}

// grid.x = 576: idx 0..63 pair tiles (both heads' qt4 tails, slow-first), 64..575 full tiles
__global__ void __launch_bounds__(256, 2) attn_kernel(const float* __restrict__ sa_bias) {
    extern __shared__ float sm[];
    float* qs = sm;                    // 128*72
    float* ks = qs + 128 * 72;         // 2 x 64*72
    float* vt = ks + 2 * 64 * 72;      // 128*72

    int warp = threadIdx.x >> 5;
    int idx = blockIdx.x;
    if (idx < 64) {
        int m0  = (warp & 3) * 16;
        int n0v = (warp >> 2) * 64;
        attn_tile<8>(idx, 0, 512, m0, n0v, qs, ks, vt, sa_bias);
        attn_tile<8>(idx, 1, 512, m0, n0v, qs, ks, vt, sa_bias);
    } else {
        int t = idx - 64;
        int bh = t >> 2, qt = t & 3;
        attn_tile<16>(bh >> 1, bh & 1, qt * 128, warp * 16, 0, qs, ks, vt, sa_bias);
    }
}

// ---------------- kernel 4: MLP, cp.async double-buffered weights, 512 threads ----------------
// smem: xsm[64][264], y1s[64][264], wts 2 x [256][40]
__global__ void mlp_kernel(const float* __restrict__ b1, const float* __restrict__ b2,
                           float* __restrict__ out) {
    int blk = blockIdx.x;                // 0..575
    int bs = blk / 9;
    int l0 = (blk % 9) * 64;
    extern __shared__ float sm[];
    float* xsm = sm;                     // 64*264 = 16896
    float* y1s = xsm + 64 * 264;         // 16896
    float* wts = y1s + 64 * 264;         // 2 x 10240

    unsigned wts_u = (unsigned)__cvta_generic_to_shared(wts);

    int tid = threadIdx.x;
    int warp = tid >> 5, lane = tid & 31;
    int row = lane >> 2, quad = lane & 3;

    const float* ag = g_att + ((size_t)bs * L_ + l0) * HID_;
    for (int idx = tid; idx < 64 * 64; idx += 512) {
        int p = idx >> 6, iv = idx & 63;
        *(float4*)(xsm + p * 264 + iv * 4) = *(const float4*)(ag + (size_t)p * HID_ + iv * 4);
    }

    // ---- GEMM1: Y1(64x256) = X @ W1^T : warp tile m32 x n32, k-chunks of 32, double-buffered ----
    int m0 = (warp & 1) * 32;
    int n0 = (warp >> 1) * 32;
    for (int j = tid; j < 2048; j += 512) {
        int o = j >> 3, kv = j & 7;
        cp16(wts_u + (unsigned)(o * 40 + kv * 4) * 4,
             g_w1p + (size_t)o * HID_ + kv * 4);
    }
    CP_COMMIT();

    float acc[2][4][4] = {};
    for (int c = 0; c < 8; c++) {
        CP_WAIT0();
        __syncthreads();
        if (c < 7) {
            int b = (c + 1) & 1;
            for (int j = tid; j < 2048; j += 512) {
                int o = j >> 3, kv = j & 7;
                cp16(wts_u + (unsigned)(b * 10240 + o * 40 + kv * 4) * 4,
                     g_w1p + (size_t)o * HID_ + (c + 1) * 32 + kv * 4);
            }
            CP_COMMIT();
        }
        const float* wb = wts + (c & 1) * 10240;
        #pragma unroll
        for (int kk = 0; kk < 4; kk++) {
            int kg = c * 32 + kk * 8;
            int kb = kk * 8;
            float2 aA[2], aB[2];
            #pragma unroll
            for (int mt = 0; mt < 2; mt++) {
                aA[mt] = *(float2*)(xsm + (m0 + mt * 16 + row) * 264 + kg + 2 * quad);
                aB[mt] = *(float2*)(xsm + (m0 + mt * 16 + row + 8) * 264 + kg + 2 * quad);
            }
            #pragma unroll
            for (int nt = 0; nt < 4; nt++) {
                float2 bv = *(float2*)(wb + (n0 + nt * 8 + row) * 40 + kb + 2 * quad);
                mma_tf32(acc[0][nt], aA[0].x, aB[0].x, aA[0].y, aB[0].y, bv.x, bv.y);
                mma_tf32(acc[1][nt], aA[1].x, aB[1].x, aA[1].y, aB[1].y, bv.x, bv.y);
            }
        }
    }
    // bias + exact GELU -> y1s[p][perm(o)], tf32-rounded
    #pragma unroll
    for (int mt = 0; mt < 2; mt++) {
        #pragma unroll
        for (int nt = 0; nt < 4; nt++) {
            int col = n0 + nt * 8 + 2 * quad;
            int p0 = perm8(col), p1 = perm8(col + 1);
            float bb0 = b1[col], bb1 = b1[col + 1];
            int r = m0 + mt * 16 + row;
            float v0 = acc[mt][nt][0] + bb0;
            float v1 = acc[mt][nt][1] + bb1;
            float v2 = acc[mt][nt][2] + bb0;
            float v3 = acc[mt][nt][3] + bb1;
            y1s[r * 264 + p0]       = tfr(0.5f * v0 * (1.0f + erff(v0 * 0.70710678118654752f)));
            y1s[r * 264 + p1]       = tfr(0.5f * v1 * (1.0f + erff(v1 * 0.70710678118654752f)));
            y1s[(r + 8) * 264 + p0] = tfr(0.5f * v2 * (1.0f + erff(v2 * 0.70710678118654752f)));
            y1s[(r + 8) * 264 + p1] = tfr(0.5f * v3 * (1.0f + erff(v3 * 0.70710678118654752f)));
        }
    }
    __syncthreads();

    // ---- GEMM2: OUT(64x128) = Y1 @ W2^T : warp tile m16 x n32, k-chunks of 32, double-buffered ----
    int m0b = (warp & 3) * 16;
    int n0b = (warp >> 2) * 32;
    for (int j = tid; j < 1024; j += 512) {
        int o = j >> 3, kv = j & 7;
        cp16(wts_u + (unsigned)(o * 40 + kv * 4) * 4,
             g_w2p + (size_t)o * HID_ + kv * 4);
    }
    CP_COMMIT();

    float ac2[4][4] = {};
    for (int c = 0; c < 8; c++) {
        CP_WAIT0();
        __syncthreads();
        if (c < 7) {
            int b = (c + 1) & 1;
            for (int j = tid; j < 1024; j += 512) {
                int o = j >> 3, kv = j & 7;
                cp16(wts_u + (unsigned)(b * 10240 + o * 40 + kv * 4) * 4,
                     g_w2p + (size_t)o * HID_ + (c + 1) * 32 + kv * 4);
            }
            CP_COMMIT();
        }
        const float* wb = wts + (c & 1) * 10240;
        #pragma unroll
        for (int kk = 0; kk < 4; kk++) {
            int kg = c * 32 + kk * 8;
            int kb = kk * 8;
            float2 aA = *(float2*)(y1s + (m0b + row) * 264 + kg + 2 * quad);
            float2 aB = *(float2*)(y1s + (m0b + row + 8) * 264 + kg + 2 * quad);
            #pragma unroll
            for (int nt = 0; nt < 4; nt++) {
                float2 bv = *(float2*)(wb + (n0b + nt * 8 + row) * 40 + kb + 2 * quad);
                mma_tf32(ac2[nt], aA.x, aB.x, aA.y, aB.y, bv.x, bv.y);
            }
        }
    }

    // ---- epilogue: + b2, write (bs, o, l) ----
    float* og = out + (size_t)bs * OUTC_ * L_;
    int l = l0 + m0b + row;
    #pragma unroll
    for (int nt = 0; nt < 4; nt++) {
        int col = n0b + nt * 8 + 2 * quad;
        float bb0 = b2[col], bb1 = b2[col + 1];
        og[(size_t)col * L_ + l]           = ac2[nt][0] + bb0;
        og[(size_t)(col + 1) * L_ + l]     = ac2[nt][1] + bb1;
        og[(size_t)col * L_ + l + 8]       = ac2[nt][2] + bb0;
        og[(size_t)(col + 1) * L_ + l + 8] = ac2[nt][3] + bb1;
    }
}

// ---------------- launch ----------------
extern "C" void kernel_launch(void* const* d_in, const int* in_sizes, int n_in,
                              void* d_out, int out_size) {
    const float* x      = (const float*)d_in[0];
    const float* qk_w   = (const float*)d_in[1];
    const float* v_w    = (const float*)d_in[2];
    const float* cpb_w1 = (const float*)d_in[3];
    const float* cpb_b1 = (const float*)d_in[4];
    const float* cpb_w2 = (const float*)d_in[5];
    const float* sa_b   = (const float*)d_in[6];
    const float* mlp_b1 = (const float*)d_in[8];
    const float* mlp_b2 = (const float*)d_in[10];
    float* out = (float*)d_out;

    const int SMEM_QKV = (128 * 72 + 64 * 136 + 64 * 72) * 4;                  // 90112
    const int SMEM_ATT = (128 * 72 + 2 * 64 * 72 + 128 * 72) * 4;              // 110592
    const int SMEM_MLP = (64 * 264 * 2 + 2 * 256 * 40) * 4;                    // 217088

    cudaFuncSetAttribute(qkv_kernel,  cudaFuncAttributeMaxDynamicSharedMemorySize, SMEM_QKV);
    cudaFuncSetAttribute(attn_kernel, cudaFuncAttributeMaxDynamicSharedMemorySize, SMEM_ATT);
    cudaFuncSetAttribute(mlp_kernel,  cudaFuncAttributeMaxDynamicSharedMemorySize, SMEM_MLP);

    prep_kernel<<<640, 256>>>(qk_w, v_w, (const float*)d_in[7], (const float*)d_in[9]);
    cpb_lut_kernel<<<9, 256>>>(cpb_w1, cpb_b1, cpb_w2);
    cpb_fill_kernel<<<(L_ * L_) / 256, 256>>>();
    qkv_kernel<<<dim3(9, BS_), 256, SMEM_QKV>>>(x);
    attn_kernel<<<576, 256, SMEM_ATT>>>(sa_b);
    mlp_kernel<<<BS_ * 9, 512, SMEM_MLP>>>(mlp_b1, mlp_b2, out);
}

// round 14
// speedup vs baseline: 1.6248x; 1.0066x over previous
#include <cuda_runtime.h>
#include <cuda_bf16.h>
#include <math.h>

#define B_     2
#define S_     32
#define BS_    64
#define C_     128
#define HGT    24
#define WID    24
#define L_     576
#define HEADS_ 2
#define QKD_   64
#define VD_    128
#define HID_   256
#define OUTC_  128

// ---------------- scratch (static device globals; no allocation) ----------------
__device__ float g_bias[HEADS_ * L_ * L_];            // (head, i, j)  fp32, true order
__device__ float2 g_lut[47 * 47];                     // cpb values by (dy+23, dx+23)
__device__ float g_q[BS_ * HEADS_ * L_ * QKD_];       // [bs,h][l][d-interleaved], tf32
__device__ float g_k[BS_ * HEADS_ * L_ * QKD_];       // [bs,h][l][d-interleaved], tf32
__device__ float g_v[BS_ * HEADS_ * VD_ * L_];        // [bs,h][d][l NATURAL], tf32
__device__ float g_att[BS_ * L_ * HID_];              // [bs][l][ch-interleaved], tf32
// pre-permuted + tf32-rounded weights (k-dim interleaved within 8-blocks)
__device__ float g_wqk[2 * C_ * C_];                  // 256 x 128
__device__ float g_wv [HID_ * C_];                    // 256 x 128
__device__ float g_w1p[HID_ * HID_];                  // 256 x 256
__device__ float g_w2p[OUTC_ * HID_];                 // 128 x 256

// ---------------- helpers ----------------
__device__ __forceinline__ int perm8(int i) {
    return (i & ~7) | (((i & 3) << 1) | ((i >> 2) & 1));
}
__device__ __forceinline__ unsigned f2tf(float f) {
    unsigned r;
    asm("cvt.rna.tf32.f32 %0, %1;" : "=r"(r) : "f"(f));
    return r;
}
__device__ __forceinline__ float tfr(float f) { return __uint_as_float(f2tf(f)); }
__device__ __forceinline__ void mma_tf32(float c[4],
                                         float a0, float a1, float a2, float a3,
                                         float b0, float b1) {
    asm volatile(
        "mma.sync.aligned.m16n8k8.row.col.f32.tf32.tf32.f32 "
        "{%0,%1,%2,%3}, {%4,%5,%6,%7}, {%8,%9}, {%0,%1,%2,%3};"
        : "+f"(c[0]), "+f"(c[1]), "+f"(c[2]), "+f"(c[3])
        : "r"(__float_as_uint(a0)), "r"(__float_as_uint(a1)),
          "r"(__float_as_uint(a2)), "r"(__float_as_uint(a3)),
          "r"(__float_as_uint(b0)), "r"(__float_as_uint(b1)));
}
__device__ __forceinline__ void cp16(unsigned dst, const void* src) {
    asm volatile("cp.async.cg.shared.global [%0], [%1], 16;" :: "r"(dst), "l"(src) : "memory");
}
#define CP_COMMIT() asm volatile("cp.async.commit_group;" ::: "memory")
#define CP_WAIT0()  asm volatile("cp.async.wait_group 0;" ::: "memory")
#define CP_WAIT1()  asm volatile("cp.async.wait_group 1;" ::: "memory")

// ---------------- kernel 0: weight prep (permute k within 8-blocks + tf32 round) ----------------
__global__ void prep_kernel(const float* __restrict__ qk_w, const float* __restrict__ v_w,
                            const float* __restrict__ w1, const float* __restrict__ w2) {
    int idx = blockIdx.x * 256 + threadIdx.x;     // 0 .. 163839
    if (idx < 32768) {
        int o = idx >> 7, k = idx & 127;
        g_wqk[(o << 7) | perm8(k)] = tfr(qk_w[idx]);
    } else if (idx < 65536) {
        int j = idx - 32768; int o = j >> 7, k = j & 127;
        g_wv[(o << 7) | perm8(k)] = tfr(v_w[j]);
    } else if (idx < 131072) {
        int j = idx - 65536; int o = j >> 8, k = j & 255;
        g_w1p[(o << 8) | perm8(k)] = tfr(w1[j]);
    } else {
        int j = idx - 131072; int o = j >> 8, k = j & 255;
        g_w2p[(o << 8) | perm8(k)] = tfr(w2[j]);
    }
}

// ---------------- kernel 1a: cpb LUT over the 47x47 distinct (dy,dx) offsets ----------------
__global__ void cpb_lut_kernel(const float* __restrict__ w1,
                               const float* __restrict__ b1,
                               const float* __restrict__ w2) {
    __shared__ float s_w1[256];
    __shared__ float s_b1[128];
    __shared__ float s_w2[256];
    int tid = threadIdx.x;
    s_w1[tid] = w1[tid];
    if (tid < 128) s_b1[tid] = b1[tid];
    s_w2[tid] = w2[tid];
    __syncthreads();

    int idx = blockIdx.x * 256 + tid;      // < 2209
    if (idx >= 47 * 47) return;
    int dy = idx / 47 - 23;
    int dx = idx % 47 - 23;
    float ry = (float)dy * (8.0f / 23.0f);
    float rx = (float)dx * (8.0f / 23.0f);
    ry = copysignf(log2f(1.0f + fabsf(ry)) * (1.0f / 3.0f), ry);
    rx = copysignf(log2f(1.0f + fabsf(rx)) * (1.0f / 3.0f), rx);

    float acc0 = 0.f, acc1 = 0.f;
    #pragma unroll 4
    for (int k = 0; k < 128; k++) {
        float h = fmaxf(0.f, ry * s_w1[2 * k] + rx * s_w1[2 * k + 1] + s_b1[k]);
        acc0 += h * s_w2[k];
        acc1 += h * s_w2[128 + k];
    }
    g_lut[idx] = make_float2(acc0, acc1);
}

// ---------------- kernel 1b: bias fill by gather ----------------
__global__ void cpb_fill_kernel() {
    int idx = blockIdx.x * 256 + threadIdx.x;      // < 576*576
    int i = idx / L_, j = idx % L_;
    int yi = i / WID, xi = i % WID;
    int yj = j / WID, xj = j % WID;
    float2 v = g_lut[(yi - yj + 23) * 47 + (xi - xj + 23)];
    g_bias[idx] = v.x;
    g_bias[L_ * L_ + idx] = v.y;
}

// ---------------- kernel 2: QKV projection, A = X^T, cp.async weights ----------------
// Block: (l-tile 64, bs). 256 threads = 8 warps. Warp tile m16(l) x n32(o).
// smem: xs[64][136] (l rows, c-interleaved), ws 2x[64][72] (o rows, c-chunk), outs[64][72]
__global__ void __launch_bounds__(256, 2) qkv_kernel(const float* __restrict__ x) {
    int bs = blockIdx.y;
    int l0 = blockIdx.x * 64;
    extern __shared__ float sm[];
    float* xs   = sm;                   // 64*136
    float* ws   = xs + 64 * 136;        // 2 x 64*72
    float* outs = ws + 2 * 64 * 72;     // 64*72

    unsigned ws_u = (unsigned)__cvta_generic_to_shared(ws);

    int tid = threadIdx.x;
    int warp = tid >> 5, lane = tid & 31;
    int row = lane >> 2, quad = lane & 3;
    int m0 = (warp & 3) * 16;           // l rows
    int n0 = (warp >> 2) * 32;          // o cols

    // stage xs[l][perm8(c)]: c across warp (conflict-free STS), tf32-rounded
    const float* xb = x + (size_t)bs * C_ * L_;
    for (int idx = tid; idx < 128 * 16; idx += 256) {
        int c = idx & 127, lv = idx >> 7;
        float4 v4 = *(const float4*)(xb + (size_t)c * L_ + l0 + lv * 4);
        int pc = perm8(c);
        xs[(lv * 4 + 0) * 136 + pc] = tfr(v4.x);
        xs[(lv * 4 + 1) * 136 + pc] = tfr(v4.y);
        xs[(lv * 4 + 2) * 136 + pc] = tfr(v4.z);
        xs[(lv * 4 + 3) * 136 + pc] = tfr(v4.w);
    }

    // weight stage s = ot*2 + kc: 64 o-rows x 64 c-cols into buf (s&1)
    auto issue_w = [&](int s) {
        int ot = s >> 1, kc = s & 1;
        const float* wsrc = (ot < 4) ? g_wqk + (size_t)ot * 64 * C_
                                     : g_wv  + (size_t)(ot - 4) * 64 * C_;
        unsigned dst = ws_u + (unsigned)((s & 1) * 64 * 72) * 4;
        for (int j = tid; j < 1024; j += 256) {
            int o = j >> 4, kv = j & 15;
            cp16(dst + (unsigned)(o * 72 + kv * 4) * 4,
                 wsrc + (size_t)o * C_ + kc * 64 + kv * 4);
        }
    };

    issue_w(0);
    CP_COMMIT();

    float acc[4][4];
    for (int s = 0; s < 16; s++) {
        int ot = s >> 1, kc = s & 1;
        CP_WAIT0();
        __syncthreads();                 // weights landed; xs ready (s=0); prev buf free
        if (s < 15) { issue_w(s + 1); CP_COMMIT(); }

        if (kc == 0) {
            #pragma unroll
            for (int i = 0; i < 4; i++)
                #pragma unroll
                for (int j = 0; j < 4; j++) acc[i][j] = 0.f;
        }
        const float* wb = ws + (s & 1) * (64 * 72);
        #pragma unroll
        for (int kk = 0; kk < 8; kk++) {
            int kg = kc * 64 + kk * 8;
            int kb = kk * 8;
            float2 aA = *(float2*)(xs + (m0 + row) * 136 + kg + 2 * quad);
            float2 aB = *(float2*)(xs + (m0 + row + 8) * 136 + kg + 2 * quad);
            #pragma unroll
            for (int nt = 0; nt < 4; nt++) {
                float2 bv = *(float2*)(wb + (n0 + nt * 8 + row) * 72 + kb + 2 * quad);
                mma_tf32(acc[nt], aA.x, aB.x, aA.y, aB.y, bv.x, bv.y);
            }
        }

        if (kc == 1) {
            if (ot < 4) {
                // Q/K: direct gmem write [l][perm(d)] (C rows are l)
                float* dst = (ot < 2) ? g_q + (size_t)(bs * 2 + ot) * L_ * QKD_
                                      : g_k + (size_t)(bs * 2 + ot - 2) * L_ * QKD_;
                int l = l0 + m0 + row;
                #pragma unroll
                for (int nt = 0; nt < 4; nt++) {
                    int dc = n0 + nt * 8 + 2 * quad;
                    int p0 = perm8(dc), p1 = perm8(dc + 1);
                    dst[(size_t)l * QKD_ + p0]       = tfr(acc[nt][0]);
                    dst[(size_t)l * QKD_ + p1]       = tfr(acc[nt][1]);
                    dst[(size_t)(l + 8) * QKD_ + p0] = tfr(acc[nt][2]);
                    dst[(size_t)(l + 8) * QKD_ + p1] = tfr(acc[nt][3]);
                }
            } else {
                // V: transpose via outs[d][l] (natural l), then coalesced copy
                #pragma unroll
                for (int nt = 0; nt < 4; nt++) {
                    int dc = n0 + nt * 8 + 2 * quad;
                    outs[dc * 72 + m0 + row]           = tfr(acc[nt][0]);
                    outs[(dc + 1) * 72 + m0 + row]     = tfr(acc[nt][1]);
                    outs[dc * 72 + m0 + row + 8]       = tfr(acc[nt][2]);
                    outs[(dc + 1) * 72 + m0 + row + 8] = tfr(acc[nt][3]);
                }
                __syncthreads();
                int o2 = (ot - 4) * 64;
                int head = o2 >> 7, dof = o2 & 127;
                float* dst = g_v + (size_t)(bs * 2 + head) * VD_ * L_;
                for (int idx = tid; idx < 64 * 16; idx += 256) {
                    int o = idx >> 4, j = idx & 15;
                    *(float4*)(dst + (size_t)(dof + o) * L_ + l0 + j * 4) =
                        *(float4*)(outs + o * 72 + j * 4);
                }
            }
        }
    }
}

// ---------------- kernel 3: flash attention, register P + cp.async K/V pipeline ----------------
// Full tile: NDT=16, warp owns 16 q-rows x 128 d. Pair tile: NDT=8, warp owns 16 rows x 64-d half.
// smem: qs[128][72], ks 2x[64][72] (double-buffered), vt[128][72]
template<int NDT>
__device__ __forceinline__ void attn_tile(int bs, int head, int q0, int m0, int n0v,
                                          float* qs, float* ks, float* vt,
                                          const float* __restrict__ sa_bias) {
    const float* qg = g_q + (size_t)(bs * 2 + head) * L_ * QKD_;
    const float* kg = g_k + (size_t)(bs * 2 + head) * L_ * QKD_;
    const float* vg = g_v + (size_t)(bs * 2 + head) * VD_ * L_;
    const float* bg = g_bias + (size_t)head * L_ * L_;

    unsigned ks_u = (unsigned)__cvta_generic_to_shared(ks);
    unsigned vt_u = (unsigned)__cvta_generic_to_shared(vt);

    int tid = threadIdx.x;
    int lane = tid & 31;
    int row = lane >> 2, quad = lane & 3;

    __syncthreads();   // protect qs/ks/vt from previous tile's readers
    // load q tile [128][64] (d-interleaved), zero-fill rows >= 576
    for (int idx = tid; idx < 128 * 16; idx += 256) {
        int l = idx >> 4, dv = idx & 15;
        float4 v4 = make_float4(0.f, 0.f, 0.f, 0.f);
        if (q0 + l < L_)
            v4 = *(const float4*)(qg + (size_t)(q0 + l) * QKD_ + dv * 4);
        *(float4*)(qs + l * 72 + dv * 4) = v4;
    }

    // prologue: K(0) into ks buf0, V(0) into vt
    for (int j = tid; j < 1024; j += 256) {
        int l = j >> 4, dv = j & 15;
        cp16(ks_u + (unsigned)(l * 72 + dv * 4) * 4, kg + (size_t)l * QKD_ + dv * 4);
    }
    CP_COMMIT();
    for (int j = tid; j < 2048; j += 256) {
        int d = j >> 4, jj = j & 15;
        cp16(vt_u + (unsigned)(d * 72 + jj * 4) * 4, vg + (size_t)d * L_ + jj * 4);
    }
    CP_COMMIT();

    float oac[NDT][4] = {};
    float mr0 = -1e30f, mr1 = -1e30f;
    float lr0 = 0.f, lr1 = 0.f;

    int r0g = q0 + m0 + row;
    int rb0 = (r0g < L_) ? r0g : L_ - 1;
    int rb1 = (r0g + 8 < L_) ? r0g + 8 : L_ - 1;
    const float* bgr0 = bg + (size_t)rb0 * L_;
    const float* bgr1 = bg + (size_t)rb1 * L_;

    for (int kt = 0; kt < 9; kt++) {
        int k0g = kt * 64;
        if (kt > 0) {
            __syncthreads();            // AV(kt-1) done reading vt
            for (int j = tid; j < 2048; j += 256) {
                int d = j >> 4, jj = j & 15;
                cp16(vt_u + (unsigned)(d * 72 + jj * 4) * 4,
                     vg + (size_t)d * L_ + k0g + jj * 4);
            }
            CP_COMMIT();
        }
        CP_WAIT1();                     // K(kt) landed (V(kt) may still fly)
        __syncthreads();

        const float* kb = ks + (kt & 1) * (64 * 72);

        // ---- S = Q K^T : warp m16 x n64 (8 n-tiles), accumulators in regs ----
        float p[8][4] = {};
        #pragma unroll
        for (int kk = 0; kk < 8; kk++) {
            int k0 = kk * 8;
            float2 aA = *(float2*)(qs + (m0 + row) * 72 + k0 + 2 * quad);
            float2 aB = *(float2*)(qs + (m0 + row + 8) * 72 + k0 + 2 * quad);
            #pragma unroll
            for (int nt = 0; nt < 8; nt++) {
                float2 bv = *(float2*)(kb + (nt * 8 + row) * 72 + k0 + 2 * quad);
                mma_tf32(p[nt], aA.x, aB.x, aA.y, aB.y, bv.x, bv.y);
            }
        }
        #pragma unroll
        for (int nt = 0; nt < 8; nt++) {
            int ct = k0g + nt * 8 + 2 * quad;
            p[nt][0] = p[nt][0] * 0.125f + bgr0[ct];
            p[nt][1] = p[nt][1] * 0.125f + bgr0[ct + 1];
            p[nt][2] = p[nt][2] * 0.125f + bgr1[ct];
            p[nt][3] = p[nt][3] * 0.125f + bgr1[ct + 1];
        }

        // ---- online softmax in registers (row owned by quad: shuffle xor 1,2) ----
        float tm0 = -1e30f, tm1 = -1e30f;
        #pragma unroll
        for (int nt = 0; nt < 8; nt++) {
            tm0 = fmaxf(tm0, fmaxf(p[nt][0], p[nt][1]));
            tm1 = fmaxf(tm1, fmaxf(p[nt][2], p[nt][3]));
        }
        tm0 = fmaxf(tm0, __shfl_xor_sync(0xffffffffu, tm0, 1));
        tm0 = fmaxf(tm0, __shfl_xor_sync(0xffffffffu, tm0, 2));
        tm1 = fmaxf(tm1, __shfl_xor_sync(0xffffffffu, tm1, 1));
        tm1 = fmaxf(tm1, __shfl_xor_sync(0xffffffffu, tm1, 2));
        float mn0 = fmaxf(mr0, tm0), mn1 = fmaxf(mr1, tm1);
        float al0 = __expf(mr0 - mn0), al1 = __expf(mr1 - mn1);
        mr0 = mn0; mr1 = mn1;

        float s0 = 0.f, s1 = 0.f;
        #pragma unroll
        for (int nt = 0; nt < 8; nt++) {
            float e0 = __expf(p[nt][0] - mn0);
            float e1 = __expf(p[nt][1] - mn0);
            float e2 = __expf(p[nt][2] - mn1);
            float e3 = __expf(p[nt][3] - mn1);
            s0 += e0 + e1; s1 += e2 + e3;
            p[nt][0] = tfr(e0); p[nt][1] = tfr(e1);
            p[nt][2] = tfr(e2); p[nt][3] = tfr(e3);
        }
        s0 += __shfl_xor_sync(0xffffffffu, s0, 1);
        s0 += __shfl_xor_sync(0xffffffffu, s0, 2);
        s1 += __shfl_xor_sync(0xffffffffu, s1, 1);
        s1 += __shfl_xor_sync(0xffffffffu, s1, 2);
        lr0 = al0 * lr0 + s0;
        lr1 = al1 * lr1 + s1;

        CP_WAIT0();                     // V(kt) landed
        __syncthreads();                // V visible; all warps past S(kt) (frees other ks buf)
        if (kt < 8) {                   // prefetch K(kt+1) under AV(kt)
            unsigned kdst = ks_u + (unsigned)(((kt + 1) & 1) * 64 * 72) * 4;
            const float* ksrc = kg + (size_t)(k0g + 64) * QKD_;
            for (int j = tid; j < 1024; j += 256) {
                int l = j >> 4, dv = j & 15;
                cp16(kdst + (unsigned)(l * 72 + dv * 4) * 4, ksrc + (size_t)l * QKD_ + dv * 4);
            }
            CP_COMMIT();
        }

        // ---- AV: P (regs) x V (smem, natural keys); rescale then accumulate ----
        #pragma unroll
        for (int dt = 0; dt < NDT; dt++) {
            oac[dt][0] *= al0; oac[dt][1] *= al0;
            oac[dt][2] *= al1; oac[dt][3] *= al1;
        }
        #pragma unroll
        for (int kb2 = 0; kb2 < 8; kb2++) {
            int kc = kb2 * 8 + 2 * quad;
            #pragma unroll
            for (int dt = 0; dt < NDT; dt++) {
                float2 bv = *(float2*)(vt + (n0v + dt * 8 + row) * 72 + kc);
                mma_tf32(oac[dt], p[kb2][0], p[kb2][2], p[kb2][1], p[kb2][3], bv.x, bv.y);
            }
        }
    }
    CP_WAIT0();                         // drain (no pending groups leak across tiles)

    // ---- epilogue: normalize, + sa_bias, ch-interleaved tf32 write (masked) ----
    float inv0 = 1.0f / lr0;
    float inv1 = 1.0f / lr1;
    float* og = g_att + (size_t)bs * L_ * HID_;
    int l = q0 + m0 + row;
    #pragma unroll
    for (int dt = 0; dt < NDT; dt++) {
        int ch = head * 128 + n0v + dt * 8 + 2 * quad;
        int pc0 = perm8(ch), pc1 = perm8(ch + 1);
        float sb0 = sa_bias[ch], sb1 = sa_bias[ch + 1];
        if (l < L_) {
            og[(size_t)l * HID_ + pc0] = tfr(oac[dt][0] * inv0 + sb0);
            og[(size_t)l * HID_ + pc1] = tfr(oac[dt][1] * inv0 + sb1);
        }
        if (l + 8 < L_) {
            og[(size_t)(l + 8) * HID_ + pc0] = tfr(oac[dt][2] * inv1 + sb0);
            og[(size_t)(l + 8) * HID_ + pc1] = tfr(oac[dt][3] * inv1 + sb1);
        }
    }
}

// grid.x = 576: idx 0..63 pair tiles (both heads' qt4 tails, slow-first), 64..575 full tiles
__global__ void __launch_bounds__(256, 2) attn_kernel(const float* __restrict__ sa_bias) {
    extern __shared__ float sm[];
    float* qs = sm;                    // 128*72
    float* ks = qs + 128 * 72;         // 2 x 64*72
    float* vt = ks + 2 * 64 * 72;      // 128*72

    int warp = threadIdx.x >> 5;
    int idx = blockIdx.x;
    if (idx < 64) {
        int m0  = (warp & 3) * 16;
        int n0v = (warp >> 2) * 64;
        attn_tile<8>(idx, 0, 512, m0, n0v, qs, ks, vt, sa_bias);
        attn_tile<8>(idx, 1, 512, m0, n0v, qs, ks, vt, sa_bias);
    } else {
        int t = idx - 64;
        int bh = t >> 2, qt = t & 3;
        attn_tile<16>(bh >> 1, bh & 1, qt * 128, warp * 16, 0, qs, ks, vt, sa_bias);
    }
}

// ---------------- kernel 4: MLP, cp.async double-buffered weights, 512 threads ----------------
// smem: xsm[64][264], y1s[64][264], wts 2 x [256][40]
__global__ void mlp_kernel(const float* __restrict__ b1, const float* __restrict__ b2,
                           float* __restrict__ out) {
    int blk = blockIdx.x;                // 0..575
    int bs = blk / 9;
    int l0 = (blk % 9) * 64;
    extern __shared__ float sm[];
    float* xsm = sm;                     // 64*264 = 16896
    float* y1s = xsm + 64 * 264;         // 16896
    float* wts = y1s + 64 * 264;         // 2 x 10240

    unsigned wts_u = (unsigned)__cvta_generic_to_shared(wts);

    int tid = threadIdx.x;
    int warp = tid >> 5, lane = tid & 31;
    int row = lane >> 2, quad = lane & 3;

    const float* ag = g_att + ((size_t)bs * L_ + l0) * HID_;
    for (int idx = tid; idx < 64 * 64; idx += 512) {
        int p = idx >> 6, iv = idx & 63;
        *(float4*)(xsm + p * 264 + iv * 4) = *(const float4*)(ag + (size_t)p * HID_ + iv * 4);
    }

    // ---- GEMM1: Y1(64x256) = X @ W1^T : warp tile m32 x n32, k-chunks of 32, double-buffered ----
    int m0 = (warp & 1) * 32;
    int n0 = (warp >> 1) * 32;
    for (int j = tid; j < 2048; j += 512) {
        int o = j >> 3, kv = j & 7;
        cp16(wts_u + (unsigned)(o * 40 + kv * 4) * 4,
             g_w1p + (size_t)o * HID_ + kv * 4);
    }
    CP_COMMIT();

    float acc[2][4][4] = {};
    for (int c = 0; c < 8; c++) {
        CP_WAIT0();
        __syncthreads();
        if (c < 7) {
            int b = (c + 1) & 1;
            for (int j = tid; j < 2048; j += 512) {
                int o = j >> 3, kv = j & 7;
                cp16(wts_u + (unsigned)(b * 10240 + o * 40 + kv * 4) * 4,
                     g_w1p + (size_t)o * HID_ + (c + 1) * 32 + kv * 4);
            }
            CP_COMMIT();
        }
        const float* wb = wts + (c & 1) * 10240;
        #pragma unroll
        for (int kk = 0; kk < 4; kk++) {
            int kg = c * 32 + kk * 8;
            int kb = kk * 8;
            float2 aA[2], aB[2];
            #pragma unroll
            for (int mt = 0; mt < 2; mt++) {
                aA[mt] = *(float2*)(xsm + (m0 + mt * 16 + row) * 264 + kg + 2 * quad);
                aB[mt] = *(float2*)(xsm + (m0 + mt * 16 + row + 8) * 264 + kg + 2 * quad);
            }
            #pragma unroll
            for (int nt = 0; nt < 4; nt++) {
                float2 bv = *(float2*)(wb + (n0 + nt * 8 + row) * 40 + kb + 2 * quad);
                mma_tf32(acc[0][nt], aA[0].x, aB[0].x, aA[0].y, aB[0].y, bv.x, bv.y);
                mma_tf32(acc[1][nt], aA[1].x, aB[1].x, aA[1].y, aB[1].y, bv.x, bv.y);
            }
        }
    }
    // bias + exact GELU -> y1s[p][perm(o)], tf32-rounded
    #pragma unroll
    for (int mt = 0; mt < 2; mt++) {
        #pragma unroll
        for (int nt = 0; nt < 4; nt++) {
            int col = n0 + nt * 8 + 2 * quad;
            int p0 = perm8(col), p1 = perm8(col + 1);
            float bb0 = b1[col], bb1 = b1[col + 1];
            int r = m0 + mt * 16 + row;
            float v0 = acc[mt][nt][0] + bb0;
            float v1 = acc[mt][nt][1] + bb1;
            float v2 = acc[mt][nt][2] + bb0;
            float v3 = acc[mt][nt][3] + bb1;
            y1s[r * 264 + p0]       = tfr(0.5f * v0 * (1.0f + erff(v0 * 0.70710678118654752f)));
            y1s[r * 264 + p1]       = tfr(0.5f * v1 * (1.0f + erff(v1 * 0.70710678118654752f)));
            y1s[(r + 8) * 264 + p0] = tfr(0.5f * v2 * (1.0f + erff(v2 * 0.70710678118654752f)));
            y1s[(r + 8) * 264 + p1] = tfr(0.5f * v3 * (1.0f + erff(v3 * 0.70710678118654752f)));
        }
    }
    __syncthreads();

    // ---- GEMM2: OUT(64x128) = Y1 @ W2^T : warp tile m16 x n32, k-chunks of 32, double-buffered ----
    int m0b = (warp & 3) * 16;
    int n0b = (warp >> 2) * 32;
    for (int j = tid; j < 1024; j += 512) {
        int o = j >> 3, kv = j & 7;
        cp16(wts_u + (unsigned)(o * 40 + kv * 4) * 4,
             g_w2p + (size_t)o * HID_ + kv * 4);
    }
    CP_COMMIT();

    float ac2[4][4] = {};
    for (int c = 0; c < 8; c++) {
        CP_WAIT0();
        __syncthreads();
        if (c < 7) {
            int b = (c + 1) & 1;
            for (int j = tid; j < 1024; j += 512) {
                int o = j >> 3, kv = j & 7;
                cp16(wts_u + (unsigned)(b * 10240 + o * 40 + kv * 4) * 4,
                     g_w2p + (size_t)o * HID_ + (c + 1) * 32 + kv * 4);
            }
            CP_COMMIT();
        }
        const float* wb = wts + (c & 1) * 10240;
        #pragma unroll
        for (int kk = 0; kk < 4; kk++) {
            int kg = c * 32 + kk * 8;
            int kb = kk * 8;
            float2 aA = *(float2*)(y1s + (m0b + row) * 264 + kg + 2 * quad);
            float2 aB = *(float2*)(y1s + (m0b + row + 8) * 264 + kg + 2 * quad);
            #pragma unroll
            for (int nt = 0; nt < 4; nt++) {
                float2 bv = *(float2*)(wb + (n0b + nt * 8 + row) * 40 + kb + 2 * quad);
                mma_tf32(ac2[nt], aA.x, aB.x, aA.y, aB.y, bv.x, bv.y);
            }
        }
    }

    // ---- epilogue: + b2, write (bs, o, l) ----
    float* og = out + (size_t)bs * OUTC_ * L_;
    int l = l0 + m0b + row;
    #pragma unroll
    for (int nt = 0; nt < 4; nt++) {
        int col = n0b + nt * 8 + 2 * quad;
        float bb0 = b2[col], bb1 = b2[col + 1];
        og[(size_t)col * L_ + l]           = ac2[nt][0] + bb0;
        og[(size_t)(col + 1) * L_ + l]     = ac2[nt][1] + bb1;
        og[(size_t)col * L_ + l + 8]       = ac2[nt][2] + bb0;
        og[(size_t)(col + 1) * L_ + l + 8] = ac2[nt][3] + bb1;
    }
}

// ---------------- launch ----------------
extern "C" void kernel_launch(void* const* d_in, const int* in_sizes, int n_in,
                              void* d_out, int out_size) {
    const float* x      = (const float*)d_in[0];
    const float* qk_w   = (const float*)d_in[1];
    const float* v_w    = (const float*)d_in[2];
    const float* cpb_w1 = (const float*)d_in[3];
    const float* cpb_b1 = (const float*)d_in[4];
    const float* cpb_w2 = (const float*)d_in[5];
    const float* sa_b   = (const float*)d_in[6];
    const float* mlp_b1 = (const float*)d_in[8];
    const float* mlp_b2 = (const float*)d_in[10];
    float* out = (float*)d_out;

    const int SMEM_QKV = (64 * 136 + 2 * 64 * 72 + 64 * 72) * 4;               // 90112
    const int SMEM_ATT = (128 * 72 + 2 * 64 * 72 + 128 * 72) * 4;              // 110592
    const int SMEM_MLP = (64 * 264 * 2 + 2 * 256 * 40) * 4;                    // 217088

    cudaFuncSetAttribute(qkv_kernel,  cudaFuncAttributeMaxDynamicSharedMemorySize, SMEM_QKV);
    cudaFuncSetAttribute(attn_kernel, cudaFuncAttributeMaxDynamicSharedMemorySize, SMEM_ATT);
    cudaFuncSetAttribute(mlp_kernel,  cudaFuncAttributeMaxDynamicSharedMemorySize, SMEM_MLP);

    prep_kernel<<<640, 256>>>(qk_w, v_w, (const float*)d_in[7], (const float*)d_in[9]);
    cpb_lut_kernel<<<9, 256>>>(cpb_w1, cpb_b1, cpb_w2);
    cpb_fill_kernel<<<(L_ * L_) / 256, 256>>>();
    qkv_kernel<<<dim3(9, BS_), 256, SMEM_QKV>>>(x);
    attn_kernel<<<576, 256, SMEM_ATT>>>(sa_b);
    mlp_kernel<<<BS_ * 9, 512, SMEM_MLP>>>(mlp_b1, mlp_b2, out);
}

// round 15
// speedup vs baseline: 1.7342x; 1.0673x over previous
#include <cuda_runtime.h>
#include <cuda_bf16.h>
#include <math.h>

#define B_     2
#define S_     32
#define BS_    64
#define C_     128
#define HGT    24
#define WID    24
#define L_     576
#define HEADS_ 2
#define QKD_   64
#define VD_    128
#define HID_   256
#define OUTC_  128

// ---------------- scratch (static device globals; no allocation) ----------------
__device__ float2 g_lut[47 * 47];                     // cpb values by (dy+23, dx+23)
__device__ float g_q[BS_ * HEADS_ * L_ * QKD_];       // [bs,h][l][d-interleaved], tf32
__device__ float g_k[BS_ * HEADS_ * L_ * QKD_];       // [bs,h][l][d-interleaved], tf32
__device__ float g_v[BS_ * HEADS_ * VD_ * L_];        // [bs,h][d][l NATURAL], tf32
__device__ float g_att[BS_ * L_ * HID_];              // [bs][l][ch-interleaved], tf32
// pre-permuted + tf32-rounded weights (k-dim interleaved within 8-blocks)
__device__ float g_wqk[2 * C_ * C_];                  // 256 x 128
__device__ float g_wv [HID_ * C_];                    // 256 x 128
__device__ float g_w1p[HID_ * HID_];                  // 256 x 256
__device__ float g_w2p[OUTC_ * HID_];                 // 128 x 256

// ---------------- helpers ----------------
__device__ __forceinline__ int perm8(int i) {
    return (i & ~7) | (((i & 3) << 1) | ((i >> 2) & 1));
}
__device__ __forceinline__ unsigned f2tf(float f) {
    unsigned r;
    asm("cvt.rna.tf32.f32 %0, %1;" : "=r"(r) : "f"(f));
    return r;
}
__device__ __forceinline__ float tfr(float f) { return __uint_as_float(f2tf(f)); }
__device__ __forceinline__ void mma_tf32(float c[4],
                                         float a0, float a1, float a2, float a3,
                                         float b0, float b1) {
    asm volatile(
        "mma.sync.aligned.m16n8k8.row.col.f32.tf32.tf32.f32 "
        "{%0,%1,%2,%3}, {%4,%5,%6,%7}, {%8,%9}, {%0,%1,%2,%3};"
        : "+f"(c[0]), "+f"(c[1]), "+f"(c[2]), "+f"(c[3])
        : "r"(__float_as_uint(a0)), "r"(__float_as_uint(a1)),
          "r"(__float_as_uint(a2)), "r"(__float_as_uint(a3)),
          "r"(__float_as_uint(b0)), "r"(__float_as_uint(b1)));
}
__device__ __forceinline__ void cp16(unsigned dst, const void* src) {
    asm volatile("cp.async.cg.shared.global [%0], [%1], 16;" :: "r"(dst), "l"(src) : "memory");
}
#define CP_COMMIT() asm volatile("cp.async.commit_group;" ::: "memory")
#define CP_WAIT0()  asm volatile("cp.async.wait_group 0;" ::: "memory")
#define CP_WAIT1()  asm volatile("cp.async.wait_group 1;" ::: "memory")

// ---------------- kernel 0: weight prep (permute k within 8-blocks + tf32 round) ----------------
__global__ void prep_kernel(const float* __restrict__ qk_w, const float* __restrict__ v_w,
                            const float* __restrict__ w1, const float* __restrict__ w2) {
    int idx = blockIdx.x * 256 + threadIdx.x;     // 0 .. 163839
    if (idx < 32768) {
        int o = idx >> 7, k = idx & 127;
        g_wqk[(o << 7) | perm8(k)] = tfr(qk_w[idx]);
    } else if (idx < 65536) {
        int j = idx - 32768; int o = j >> 7, k = j & 127;
        g_wv[(o << 7) | perm8(k)] = tfr(v_w[j]);
    } else if (idx < 131072) {
        int j = idx - 65536; int o = j >> 8, k = j & 255;
        g_w1p[(o << 8) | perm8(k)] = tfr(w1[j]);
    } else {
        int j = idx - 131072; int o = j >> 8, k = j & 255;
        g_w2p[(o << 8) | perm8(k)] = tfr(w2[j]);
    }
}

// ---------------- kernel 1: cpb LUT over the 47x47 distinct (dy,dx) offsets ----------------
__global__ void cpb_lut_kernel(const float* __restrict__ w1,
                               const float* __restrict__ b1,
                               const float* __restrict__ w2) {
    __shared__ float s_w1[256];
    __shared__ float s_b1[128];
    __shared__ float s_w2[256];
    int tid = threadIdx.x;
    s_w1[tid] = w1[tid];
    if (tid < 128) s_b1[tid] = b1[tid];
    s_w2[tid] = w2[tid];
    __syncthreads();

    int idx = blockIdx.x * 256 + tid;      // < 2209
    if (idx >= 47 * 47) return;
    int dy = idx / 47 - 23;
    int dx = idx % 47 - 23;
    float ry = (float)dy * (8.0f / 23.0f);
    float rx = (float)dx * (8.0f / 23.0f);
    ry = copysignf(log2f(1.0f + fabsf(ry)) * (1.0f / 3.0f), ry);
    rx = copysignf(log2f(1.0f + fabsf(rx)) * (1.0f / 3.0f), rx);

    float acc0 = 0.f, acc1 = 0.f;
    #pragma unroll 4
    for (int k = 0; k < 128; k++) {
        float h = fmaxf(0.f, ry * s_w1[2 * k] + rx * s_w1[2 * k + 1] + s_b1[k]);
        acc0 += h * s_w2[k];
        acc1 += h * s_w2[128 + k];
    }
    g_lut[idx] = make_float2(acc0, acc1);
}

// ---------------- kernel 2: QKV projection, A = X^T, cp.async weights ----------------
// Block: (l-tile 64, bs). 256 threads = 8 warps. Warp tile m16(l) x n32(o).
// smem: xs[64][136] (l rows, c-interleaved), ws 2x[64][72] (o rows, c-chunk), outs[64][72]
__global__ void __launch_bounds__(256, 2) qkv_kernel(const float* __restrict__ x) {
    int bs = blockIdx.y;
    int l0 = blockIdx.x * 64;
    extern __shared__ float sm[];
    float* xs   = sm;                   // 64*136
    float* ws   = xs + 64 * 136;        // 2 x 64*72
    float* outs = ws + 2 * 64 * 72;     // 64*72

    unsigned ws_u = (unsigned)__cvta_generic_to_shared(ws);

    int tid = threadIdx.x;
    int warp = tid >> 5, lane = tid & 31;
    int row = lane >> 2, quad = lane & 3;
    int m0 = (warp & 3) * 16;           // l rows
    int n0 = (warp >> 2) * 32;          // o cols

    // stage xs[l][perm8(c)]: c across warp (conflict-free STS), tf32-rounded
    const float* xb = x + (size_t)bs * C_ * L_;
    for (int idx = tid; idx < 128 * 16; idx += 256) {
        int c = idx & 127, lv = idx >> 7;
        float4 v4 = *(const float4*)(xb + (size_t)c * L_ + l0 + lv * 4);
        int pc = perm8(c);
        xs[(lv * 4 + 0) * 136 + pc] = tfr(v4.x);
        xs[(lv * 4 + 1) * 136 + pc] = tfr(v4.y);
        xs[(lv * 4 + 2) * 136 + pc] = tfr(v4.z);
        xs[(lv * 4 + 3) * 136 + pc] = tfr(v4.w);
    }

    // weight stage s = ot*2 + kc: 64 o-rows x 64 c-cols into buf (s&1)
    auto issue_w = [&](int s) {
        int ot = s >> 1, kc = s & 1;
        const float* wsrc = (ot < 4) ? g_wqk + (size_t)ot * 64 * C_
                                     : g_wv  + (size_t)(ot - 4) * 64 * C_;
        unsigned dst = ws_u + (unsigned)((s & 1) * 64 * 72) * 4;
        for (int j = tid; j < 1024; j += 256) {
            int o = j >> 4, kv = j & 15;
            cp16(dst + (unsigned)(o * 72 + kv * 4) * 4,
                 wsrc + (size_t)o * C_ + kc * 64 + kv * 4);
        }
    };

    issue_w(0);
    CP_COMMIT();

    float acc[4][4];
    for (int s = 0; s < 16; s++) {
        int ot = s >> 1, kc = s & 1;
        CP_WAIT0();
        __syncthreads();                 // weights landed; xs ready (s=0); prev buf free
        if (s < 15) { issue_w(s + 1); CP_COMMIT(); }

        if (kc == 0) {
            #pragma unroll
            for (int i = 0; i < 4; i++)
                #pragma unroll
                for (int j = 0; j < 4; j++) acc[i][j] = 0.f;
        }
        const float* wb = ws + (s & 1) * (64 * 72);
        #pragma unroll
        for (int kk = 0; kk < 8; kk++) {
            int kg = kc * 64 + kk * 8;
            int kb = kk * 8;
            float2 aA = *(float2*)(xs + (m0 + row) * 136 + kg + 2 * quad);
            float2 aB = *(float2*)(xs + (m0 + row + 8) * 136 + kg + 2 * quad);
            #pragma unroll
            for (int nt = 0; nt < 4; nt++) {
                float2 bv = *(float2*)(wb + (n0 + nt * 8 + row) * 72 + kb + 2 * quad);
                mma_tf32(acc[nt], aA.x, aB.x, aA.y, aB.y, bv.x, bv.y);
            }
        }

        if (kc == 1) {
            if (ot < 4) {
                // Q/K: direct gmem write [l][perm(d)] (C rows are l)
                float* dst = (ot < 2) ? g_q + (size_t)(bs * 2 + ot) * L_ * QKD_
                                      : g_k + (size_t)(bs * 2 + ot - 2) * L_ * QKD_;
                int l = l0 + m0 + row;
                #pragma unroll
                for (int nt = 0; nt < 4; nt++) {
                    int dc = n0 + nt * 8 + 2 * quad;
                    int p0 = perm8(dc), p1 = perm8(dc + 1);
                    dst[(size_t)l * QKD_ + p0]       = tfr(acc[nt][0]);
                    dst[(size_t)l * QKD_ + p1]       = tfr(acc[nt][1]);
                    dst[(size_t)(l + 8) * QKD_ + p0] = tfr(acc[nt][2]);
                    dst[(size_t)(l + 8) * QKD_ + p1] = tfr(acc[nt][3]);
                }
            } else {
                // V: transpose via outs[d][l] (natural l), then coalesced copy
                #pragma unroll
                for (int nt = 0; nt < 4; nt++) {
                    int dc = n0 + nt * 8 + 2 * quad;
                    outs[dc * 72 + m0 + row]           = tfr(acc[nt][0]);
                    outs[(dc + 1) * 72 + m0 + row]     = tfr(acc[nt][1]);
                    outs[dc * 72 + m0 + row + 8]       = tfr(acc[nt][2]);
                    outs[(dc + 1) * 72 + m0 + row + 8] = tfr(acc[nt][3]);
                }
                __syncthreads();
                int o2 = (ot - 4) * 64;
                int head = o2 >> 7, dof = o2 & 127;
                float* dst = g_v + (size_t)(bs * 2 + head) * VD_ * L_;
                for (int idx = tid; idx < 64 * 16; idx += 256) {
                    int o = idx >> 4, j = idx & 15;
                    *(float4*)(dst + (size_t)(dof + o) * L_ + l0 + j * 4) =
                        *(float4*)(outs + o * 72 + j * 4);
                }
            }
        }
    }
}

// ---------------- kernel 3: flash attention, register P + cp.async K/V pipeline ----------------
// Bias computed from g_lut (47x47) directly. Full tile NDT=16; pair tile NDT=8.
// smem: qs[128][72], ks 2x[64][72] (double-buffered), vt[128][72]
template<int NDT>
__device__ __forceinline__ void attn_tile(int bs, int head, int q0, int m0, int n0v,
                                          float* qs, float* ks, float* vt,
                                          const float* __restrict__ sa_bias) {
    const float* qg = g_q + (size_t)(bs * 2 + head) * L_ * QKD_;
    const float* kg = g_k + (size_t)(bs * 2 + head) * L_ * QKD_;
    const float* vg = g_v + (size_t)(bs * 2 + head) * VD_ * L_;
    const float* lutf = (const float*)g_lut + head;

    unsigned ks_u = (unsigned)__cvta_generic_to_shared(ks);
    unsigned vt_u = (unsigned)__cvta_generic_to_shared(vt);

    int tid = threadIdx.x;
    int lane = tid & 31;
    int row = lane >> 2, quad = lane & 3;

    __syncthreads();   // protect qs/ks/vt from previous tile's readers
    // load q tile [128][64] (d-interleaved), zero-fill rows >= 576
    for (int idx = tid; idx < 128 * 16; idx += 256) {
        int l = idx >> 4, dv = idx & 15;
        float4 v4 = make_float4(0.f, 0.f, 0.f, 0.f);
        if (q0 + l < L_)
            v4 = *(const float4*)(qg + (size_t)(q0 + l) * QKD_ + dv * 4);
        *(float4*)(qs + l * 72 + dv * 4) = v4;
    }

    // prologue: K(0) into ks buf0, V(0) into vt
    for (int j = tid; j < 1024; j += 256) {
        int l = j >> 4, dv = j & 15;
        cp16(ks_u + (unsigned)(l * 72 + dv * 4) * 4, kg + (size_t)l * QKD_ + dv * 4);
    }
    CP_COMMIT();
    for (int j = tid; j < 2048; j += 256) {
        int d = j >> 4, jj = j & 15;
        cp16(vt_u + (unsigned)(d * 72 + jj * 4) * 4, vg + (size_t)d * L_ + jj * 4);
    }
    CP_COMMIT();

    float oac[NDT][4] = {};
    float mr0 = -1e30f, mr1 = -1e30f;
    float lr0 = 0.f, lr1 = 0.f;

    int r0g = q0 + m0 + row;
    int rb0 = (r0g < L_) ? r0g : L_ - 1;
    int rb1 = (r0g + 8 < L_) ? r0g + 8 : L_ - 1;
    int yi0 = rb0 / WID, xi0 = rb0 - (rb0 / WID) * WID;
    int yi1 = rb1 / WID, xi1 = rb1 - (rb1 / WID) * WID;

    for (int kt = 0; kt < 9; kt++) {
        int k0g = kt * 64;
        if (kt > 0) {
            __syncthreads();            // AV(kt-1) done reading vt
            for (int j = tid; j < 2048; j += 256) {
                int d = j >> 4, jj = j & 15;
                cp16(vt_u + (unsigned)(d * 72 + jj * 4) * 4,
                     vg + (size_t)d * L_ + k0g + jj * 4);
            }
            CP_COMMIT();
        }
        CP_WAIT1();                     // K(kt) landed (V(kt) may still fly)
        __syncthreads();

        const float* kb = ks + (kt & 1) * (64 * 72);

        // ---- S = Q K^T : warp m16 x n64 (8 n-tiles), accumulators in regs ----
        float p[8][4] = {};
        #pragma unroll
        for (int kk = 0; kk < 8; kk++) {
            int k0 = kk * 8;
            float2 aA = *(float2*)(qs + (m0 + row) * 72 + k0 + 2 * quad);
            float2 aB = *(float2*)(qs + (m0 + row + 8) * 72 + k0 + 2 * quad);
            #pragma unroll
            for (int nt = 0; nt < 8; nt++) {
                float2 bv = *(float2*)(kb + (nt * 8 + row) * 72 + k0 + 2 * quad);
                mma_tf32(p[nt], aA.x, aB.x, aA.y, aB.y, bv.x, bv.y);
            }
        }
        // scale + bias from LUT
        #pragma unroll
        for (int nt = 0; nt < 8; nt++) {
            int ct = k0g + nt * 8 + 2 * quad;
            int yj0 = ct / WID,        xj0 = ct - yj0 * WID;
            int c1 = ct + 1;
            int yj1 = c1 / WID,        xj1 = c1 - yj1 * WID;
            float b00 = lutf[2 * ((yi0 - yj0 + 23) * 47 + (xi0 - xj0 + 23))];
            float b01 = lutf[2 * ((yi0 - yj1 + 23) * 47 + (xi0 - xj1 + 23))];
            float b10 = lutf[2 * ((yi1 - yj0 + 23) * 47 + (xi1 - xj0 + 23))];
            float b11 = lutf[2 * ((yi1 - yj1 + 23) * 47 + (xi1 - xj1 + 23))];
            p[nt][0] = p[nt][0] * 0.125f + b00;
            p[nt][1] = p[nt][1] * 0.125f + b01;
            p[nt][2] = p[nt][2] * 0.125f + b10;
            p[nt][3] = p[nt][3] * 0.125f + b11;
        }

        // ---- online softmax in registers (row owned by quad: shuffle xor 1,2) ----
        float tm0 = -1e30f, tm1 = -1e30f;
        #pragma unroll
        for (int nt = 0; nt < 8; nt++) {
            tm0 = fmaxf(tm0, fmaxf(p[nt][0], p[nt][1]));
            tm1 = fmaxf(tm1, fmaxf(p[nt][2], p[nt][3]));
        }
        tm0 = fmaxf(tm0, __shfl_xor_sync(0xffffffffu, tm0, 1));
        tm0 = fmaxf(tm0, __shfl_xor_sync(0xffffffffu, tm0, 2));
        tm1 = fmaxf(tm1, __shfl_xor_sync(0xffffffffu, tm1, 1));
        tm1 = fmaxf(tm1, __shfl_xor_sync(0xffffffffu, tm1, 2));
        float mn0 = fmaxf(mr0, tm0), mn1 = fmaxf(mr1, tm1);
        float al0 = __expf(mr0 - mn0), al1 = __expf(mr1 - mn1);
        mr0 = mn0; mr1 = mn1;

        float s0 = 0.f, s1 = 0.f;
        #pragma unroll
        for (int nt = 0; nt < 8; nt++) {
            float e0 = __expf(p[nt][0] - mn0);
            float e1 = __expf(p[nt][1] - mn0);
            float e2 = __expf(p[nt][2] - mn1);
            float e3 = __expf(p[nt][3] - mn1);
            s0 += e0 + e1; s1 += e2 + e3;
            p[nt][0] = tfr(e0); p[nt][1] = tfr(e1);
            p[nt][2] = tfr(e2); p[nt][3] = tfr(e3);
        }
        s0 += __shfl_xor_sync(0xffffffffu, s0, 1);
        s0 += __shfl_xor_sync(0xffffffffu, s0, 2);
        s1 += __shfl_xor_sync(0xffffffffu, s1, 1);
        s1 += __shfl_xor_sync(0xffffffffu, s1, 2);
        lr0 = al0 * lr0 + s0;
        lr1 = al1 * lr1 + s1;

        CP_WAIT0();                     // V(kt) landed
        __syncthreads();                // V visible; all warps past S(kt) (frees other ks buf)
        if (kt < 8) {                   // prefetch K(kt+1) under AV(kt)
            unsigned kdst = ks_u + (unsigned)(((kt + 1) & 1) * 64 * 72) * 4;
            const float* ksrc = kg + (size_t)(k0g + 64) * QKD_;
            for (int j = tid; j < 1024; j += 256) {
                int l = j >> 4, dv = j & 15;
                cp16(kdst + (unsigned)(l * 72 + dv * 4) * 4, ksrc + (size_t)l * QKD_ + dv * 4);
            }
            CP_COMMIT();
        }

        // ---- AV: P (regs) x V (smem, natural keys); rescale then accumulate ----
        #pragma unroll
        for (int dt = 0; dt < NDT; dt++) {
            oac[dt][0] *= al0; oac[dt][1] *= al0;
            oac[dt][2] *= al1; oac[dt][3] *= al1;
        }
        #pragma unroll
        for (int kb2 = 0; kb2 < 8; kb2++) {
            int kc = kb2 * 8 + 2 * quad;
            #pragma unroll
            for (int dt = 0; dt < NDT; dt++) {
                float2 bv = *(float2*)(vt + (n0v + dt * 8 + row) * 72 + kc);
                mma_tf32(oac[dt], p[kb2][0], p[kb2][2], p[kb2][1], p[kb2][3], bv.x, bv.y);
            }
        }
    }
    CP_WAIT0();                         // drain (no pending groups leak across tiles)

    // ---- epilogue: normalize, + sa_bias, ch-interleaved tf32 write (masked) ----
    float inv0 = 1.0f / lr0;
    float inv1 = 1.0f / lr1;
    float* og = g_att + (size_t)bs * L_ * HID_;
    int l = q0 + m0 + row;
    #pragma unroll
    for (int dt = 0; dt < NDT; dt++) {
        int ch = head * 128 + n0v + dt * 8 + 2 * quad;
        int pc0 = perm8(ch), pc1 = perm8(ch + 1);
        float sb0 = sa_bias[ch], sb1 = sa_bias[ch + 1];
        if (l < L_) {
            og[(size_t)l * HID_ + pc0] = tfr(oac[dt][0] * inv0 + sb0);
            og[(size_t)l * HID_ + pc1] = tfr(oac[dt][1] * inv0 + sb1);
        }
        if (l + 8 < L_) {
            og[(size_t)(l + 8) * HID_ + pc0] = tfr(oac[dt][2] * inv1 + sb0);
            og[(size_t)(l + 8) * HID_ + pc1] = tfr(oac[dt][3] * inv1 + sb1);
        }
    }
}

// grid.x = 576: idx 0..63 pair tiles (both heads' qt4 tails, slow-first), 64..575 full tiles
__global__ void __launch_bounds__(256, 2) attn_kernel(const float* __restrict__ sa_bias) {
    extern __shared__ float sm[];
    float* qs = sm;                    // 128*72
    float* ks = qs + 128 * 72;         // 2 x 64*72
    float* vt = ks + 2 * 64 * 72;      // 128*72

    int warp = threadIdx.x >> 5;
    int idx = blockIdx.x;
    if (idx < 64) {
        int m0  = (warp & 3) * 16;
        int n0v = (warp >> 2) * 64;
        attn_tile<8>(idx, 0, 512, m0, n0v, qs, ks, vt, sa_bias);
        attn_tile<8>(idx, 1, 512, m0, n0v, qs, ks, vt, sa_bias);
    } else {
        int t = idx - 64;
        int bh = t >> 2, qt = t & 3;
        attn_tile<16>(bh >> 1, bh & 1, qt * 128, warp * 16, 0, qs, ks, vt, sa_bias);
    }
}

// ---------------- kernel 4: MLP, 1024 threads = 32 warps, cp.async weights ----------------
// smem: xsm[64][264], y1s[64][264], wts 2 x [256][40]
__global__ void __launch_bounds__(1024, 1) mlp_kernel(const float* __restrict__ b1,
                                                      const float* __restrict__ b2,
                                                      float* __restrict__ out) {
    int blk = blockIdx.x;                // 0..575
    int bs = blk / 9;
    int l0 = (blk % 9) * 64;
    extern __shared__ float sm[];
    float* xsm = sm;                     // 64*264
    float* y1s = xsm + 64 * 264;         // 64*264
    float* wts = y1s + 64 * 264;         // 2 x 10240

    unsigned wts_u = (unsigned)__cvta_generic_to_shared(wts);

    int tid = threadIdx.x;
    int warp = tid >> 5, lane = tid & 31;
    int row = lane >> 2, quad = lane & 3;

    const float* ag = g_att + ((size_t)bs * L_ + l0) * HID_;
    for (int idx = tid; idx < 64 * 64; idx += 1024) {
        int p = idx >> 6, iv = idx & 63;
        *(float4*)(xsm + p * 264 + iv * 4) = *(const float4*)(ag + (size_t)p * HID_ + iv * 4);
    }

    // ---- GEMM1: Y1(64x256) = X @ W1^T : warp tile m16 x n32 (4 m-groups x 8 n-groups) ----
    int m0 = (warp & 3) * 16;
    int n0 = (warp >> 2) * 32;
    for (int j = tid; j < 2048; j += 1024) {
        int o = j >> 3, kv = j & 7;
        cp16(wts_u + (unsigned)(o * 40 + kv * 4) * 4,
             g_w1p + (size_t)o * HID_ + kv * 4);
    }
    CP_COMMIT();

    float acc[4][4] = {};
    for (int c = 0; c < 8; c++) {
        CP_WAIT0();
        __syncthreads();
        if (c < 7) {
            int b = (c + 1) & 1;
            for (int j = tid; j < 2048; j += 1024) {
                int o = j >> 3, kv = j & 7;
                cp16(wts_u + (unsigned)(b * 10240 + o * 40 + kv * 4) * 4,
                     g_w1p + (size_t)o * HID_ + (c + 1) * 32 + kv * 4);
            }
            CP_COMMIT();
        }
        const float* wb = wts + (c & 1) * 10240;
        #pragma unroll
        for (int kk = 0; kk < 4; kk++) {
            int kg = c * 32 + kk * 8;
            int kb = kk * 8;
            float2 aA = *(float2*)(xsm + (m0 + row) * 264 + kg + 2 * quad);
            float2 aB = *(float2*)(xsm + (m0 + row + 8) * 264 + kg + 2 * quad);
            #pragma unroll
            for (int nt = 0; nt < 4; nt++) {
                float2 bv = *(float2*)(wb + (n0 + nt * 8 + row) * 40 + kb + 2 * quad);
                mma_tf32(acc[nt], aA.x, aB.x, aA.y, aB.y, bv.x, bv.y);
            }
        }
    }
    // bias + exact GELU -> y1s[p][perm(o)], tf32-rounded
    #pragma unroll
    for (int nt = 0; nt < 4; nt++) {
        int col = n0 + nt * 8 + 2 * quad;
        int p0 = perm8(col), p1 = perm8(col + 1);
        float bb0 = b1[col], bb1 = b1[col + 1];
        int r = m0 + row;
        float v0 = acc[nt][0] + bb0;
        float v1 = acc[nt][1] + bb1;
        float v2 = acc[nt][2] + bb0;
        float v3 = acc[nt][3] + bb1;
        y1s[r * 264 + p0]       = tfr(0.5f * v0 * (1.0f + erff(v0 * 0.70710678118654752f)));
        y1s[r * 264 + p1]       = tfr(0.5f * v1 * (1.0f + erff(v1 * 0.70710678118654752f)));
        y1s[(r + 8) * 264 + p0] = tfr(0.5f * v2 * (1.0f + erff(v2 * 0.70710678118654752f)));
        y1s[(r + 8) * 264 + p1] = tfr(0.5f * v3 * (1.0f + erff(v3 * 0.70710678118654752f)));
    }
    __syncthreads();

    // ---- GEMM2: OUT(64x128) = Y1 @ W2^T : warp tile m16 x n16 (4 m-groups x 8 n-groups) ----
    int m0b = (warp & 3) * 16;
    int n0b = (warp >> 2) * 16;
    for (int j = tid; j < 1024; j += 1024) {
        int o = j >> 3, kv = j & 7;
        cp16(wts_u + (unsigned)(o * 40 + kv * 4) * 4,
             g_w2p + (size_t)o * HID_ + kv * 4);
    }
    CP_COMMIT();

    float ac2[2][4] = {};
    for (int c = 0; c < 8; c++) {
        CP_WAIT0();
        __syncthreads();
        if (c < 7) {
            int b = (c + 1) & 1;
            for (int j = tid; j < 1024; j += 1024) {
                int o = j >> 3, kv = j & 7;
                cp16(wts_u + (unsigned)(b * 10240 + o * 40 + kv * 4) * 4,
                     g_w2p + (size_t)o * HID_ + (c + 1) * 32 + kv * 4);
            }
            CP_COMMIT();
        }
        const float* wb = wts + (c & 1) * 10240;
        #pragma unroll
        for (int kk = 0; kk < 4; kk++) {
            int kg = c * 32 + kk * 8;
            int kb = kk * 8;
            float2 aA = *(float2*)(y1s + (m0b + row) * 264 + kg + 2 * quad);
            float2 aB = *(float2*)(y1s + (m0b + row + 8) * 264 + kg + 2 * quad);
            #pragma unroll
            for (int nt = 0; nt < 2; nt++) {
                float2 bv = *(float2*)(wb + (n0b + nt * 8 + row) * 40 + kb + 2 * quad);
                mma_tf32(ac2[nt], aA.x, aB.x, aA.y, aB.y, bv.x, bv.y);
            }
        }
    }

    // ---- epilogue: + b2, write (bs, o, l) ----
    float* og = out + (size_t)bs * OUTC_ * L_;
    int l = l0 + m0b + row;
    #pragma unroll
    for (int nt = 0; nt < 2; nt++) {
        int col = n0b + nt * 8 + 2 * quad;
        float bb0 = b2[col], bb1 = b2[col + 1];
        og[(size_t)col * L_ + l]           = ac2[nt][0] + bb0;
        og[(size_t)(col + 1) * L_ + l]     = ac2[nt][1] + bb1;
        og[(size_t)col * L_ + l + 8]       = ac2[nt][2] + bb0;
        og[(size_t)(col + 1) * L_ + l + 8] = ac2[nt][3] + bb1;
    }
}

// ---------------- launch ----------------
extern "C" void kernel_launch(void* const* d_in, const int* in_sizes, int n_in,
                              void* d_out, int out_size) {
    const float* x      = (const float*)d_in[0];
    const float* qk_w   = (const float*)d_in[1];
    const float* v_w    = (const float*)d_in[2];
    const float* cpb_w1 = (const float*)d_in[3];
    const float* cpb_b1 = (const float*)d_in[4];
    const float* cpb_w2 = (const float*)d_in[5];
    const float* sa_b   = (const float*)d_in[6];
    const float* mlp_b1 = (const float*)d_in[8];
    const float* mlp_b2 = (const float*)d_in[10];
    float* out = (float*)d_out;

    const int SMEM_QKV = (64 * 136 + 2 * 64 * 72 + 64 * 72) * 4;               // 90112
    const int SMEM_ATT = (128 * 72 + 2 * 64 * 72 + 128 * 72) * 4;              // 110592
    const int SMEM_MLP = (64 * 264 * 2 + 2 * 256 * 40) * 4;                    // 217088

    cudaFuncSetAttribute(qkv_kernel,  cudaFuncAttributeMaxDynamicSharedMemorySize, SMEM_QKV);
    cudaFuncSetAttribute(attn_kernel, cudaFuncAttributeMaxDynamicSharedMemorySize, SMEM_ATT);
    cudaFuncSetAttribute(mlp_kernel,  cudaFuncAttributeMaxDynamicSharedMemorySize, SMEM_MLP);

    prep_kernel<<<640, 256>>>(qk_w, v_w, (const float*)d_in[7], (const float*)d_in[9]);
    cpb_lut_kernel<<<9, 256>>>(cpb_w1, cpb_b1, cpb_w2);
    qkv_kernel<<<dim3(9, BS_), 256, SMEM_QKV>>>(x);
    attn_kernel<<<576, 256, SMEM_ATT>>>(sa_b);
    mlp_kernel<<<BS_ * 9, 1024, SMEM_MLP>>>(mlp_b1, mlp_b2, out);
}

// round 16
// speedup vs baseline: 1.7671x; 1.0190x over previous
#include <cuda_runtime.h>
#include <cuda_bf16.h>
#include <math.h>

#define B_     2
#define S_     32
#define BS_    64
#define C_     128
#define HGT    24
#define WID    24
#define L_     576
#define HEADS_ 2
#define QKD_   64
#define VD_    128
#define HID_   256
#define OUTC_  128

// ---------------- scratch (static device globals; no allocation) ----------------
__device__ float2 g_lut[47 * 47];                     // cpb values by (dy+23, dx+23)
__device__ float g_q[BS_ * HEADS_ * L_ * QKD_];       // [bs,h][l][d-interleaved], tf32
__device__ float g_k[BS_ * HEADS_ * L_ * QKD_];       // [bs,h][l][d-interleaved], tf32
__device__ float g_v[BS_ * HEADS_ * VD_ * L_];        // [bs,h][d][l NATURAL], tf32
__device__ float g_att[BS_ * L_ * HID_];              // [bs][l][ch-interleaved], tf32
// pre-permuted + tf32-rounded weights (k-dim interleaved within 8-blocks)
__device__ float g_wqk[2 * C_ * C_];                  // 256 x 128
__device__ float g_wv [HID_ * C_];                    // 256 x 128
__device__ float g_w1p[HID_ * HID_];                  // 256 x 256
__device__ float g_w2p[OUTC_ * HID_];                 // 128 x 256

// ---------------- helpers ----------------
__device__ __forceinline__ int perm8(int i) {
    return (i & ~7) | (((i & 3) << 1) | ((i >> 2) & 1));
}
__device__ __forceinline__ unsigned f2tf(float f) {
    unsigned r;
    asm("cvt.rna.tf32.f32 %0, %1;" : "=r"(r) : "f"(f));
    return r;
}
__device__ __forceinline__ float tfr(float f) { return __uint_as_float(f2tf(f)); }
__device__ __forceinline__ void mma_tf32(float c[4],
                                         float a0, float a1, float a2, float a3,
                                         float b0, float b1) {
    asm volatile(
        "mma.sync.aligned.m16n8k8.row.col.f32.tf32.tf32.f32 "
        "{%0,%1,%2,%3}, {%4,%5,%6,%7}, {%8,%9}, {%0,%1,%2,%3};"
        : "+f"(c[0]), "+f"(c[1]), "+f"(c[2]), "+f"(c[3])
        : "r"(__float_as_uint(a0)), "r"(__float_as_uint(a1)),
          "r"(__float_as_uint(a2)), "r"(__float_as_uint(a3)),
          "r"(__float_as_uint(b0)), "r"(__float_as_uint(b1)));
}
__device__ __forceinline__ void cp16(unsigned dst, const void* src) {
    asm volatile("cp.async.cg.shared.global [%0], [%1], 16;" :: "r"(dst), "l"(src) : "memory");
}
#define CP_COMMIT() asm volatile("cp.async.commit_group;" ::: "memory")
#define CP_WAIT0()  asm volatile("cp.async.wait_group 0;" ::: "memory")
#define CP_WAIT1()  asm volatile("cp.async.wait_group 1;" ::: "memory")

// ---------------- kernel 0: weight prep (permute k within 8-blocks + tf32 round) ----------------
__global__ void prep_kernel(const float* __restrict__ qk_w, const float* __restrict__ v_w,
                            const float* __restrict__ w1, const float* __restrict__ w2) {
    int idx = blockIdx.x * 256 + threadIdx.x;     // 0 .. 163839
    if (idx < 32768) {
        int o = idx >> 7, k = idx & 127;
        g_wqk[(o << 7) | perm8(k)] = tfr(qk_w[idx]);
    } else if (idx < 65536) {
        int j = idx - 32768; int o = j >> 7, k = j & 127;
        g_wv[(o << 7) | perm8(k)] = tfr(v_w[j]);
    } else if (idx < 131072) {
        int j = idx - 65536; int o = j >> 8, k = j & 255;
        g_w1p[(o << 8) | perm8(k)] = tfr(w1[j]);
    } else {
        int j = idx - 131072; int o = j >> 8, k = j & 255;
        g_w2p[(o << 8) | perm8(k)] = tfr(w2[j]);
    }
}

// ---------------- kernel 1: cpb LUT over the 47x47 distinct (dy,dx) offsets ----------------
__global__ void cpb_lut_kernel(const float* __restrict__ w1,
                               const float* __restrict__ b1,
                               const float* __restrict__ w2) {
    __shared__ float s_w1[256];
    __shared__ float s_b1[128];
    __shared__ float s_w2[256];
    int tid = threadIdx.x;
    s_w1[tid] = w1[tid];
    if (tid < 128) s_b1[tid] = b1[tid];
    s_w2[tid] = w2[tid];
    __syncthreads();

    int idx = blockIdx.x * 256 + tid;      // < 2209
    if (idx >= 47 * 47) return;
    int dy = idx / 47 - 23;
    int dx = idx % 47 - 23;
    float ry = (float)dy * (8.0f / 23.0f);
    float rx = (float)dx * (8.0f / 23.0f);
    ry = copysignf(log2f(1.0f + fabsf(ry)) * (1.0f / 3.0f), ry);
    rx = copysignf(log2f(1.0f + fabsf(rx)) * (1.0f / 3.0f), rx);

    float acc0 = 0.f, acc1 = 0.f;
    #pragma unroll 4
    for (int k = 0; k < 128; k++) {
        float h = fmaxf(0.f, ry * s_w1[2 * k] + rx * s_w1[2 * k + 1] + s_b1[k]);
        acc0 += h * s_w2[k];
        acc1 += h * s_w2[128 + k];
    }
    g_lut[idx] = make_float2(acc0, acc1);
}

// ---------------- kernel 2: QKV projection, A = X^T, cp.async weights ----------------
// Block: (l-tile 64, bs). 256 threads = 8 warps. Warp tile m16(l) x n32(o).
__global__ void __launch_bounds__(256, 2) qkv_kernel(const float* __restrict__ x) {
    int bs = blockIdx.y;
    int l0 = blockIdx.x * 64;
    extern __shared__ float sm[];
    float* xs   = sm;                   // 64*136
    float* ws   = xs + 64 * 136;        // 2 x 64*72
    float* outs = ws + 2 * 64 * 72;     // 64*72

    unsigned ws_u = (unsigned)__cvta_generic_to_shared(ws);

    int tid = threadIdx.x;
    int warp = tid >> 5, lane = tid & 31;
    int row = lane >> 2, quad = lane & 3;
    int m0 = (warp & 3) * 16;           // l rows
    int n0 = (warp >> 2) * 32;          // o cols

    // stage xs[l][perm8(c)]: c across warp (conflict-free STS), tf32-rounded
    const float* xb = x + (size_t)bs * C_ * L_;
    for (int idx = tid; idx < 128 * 16; idx += 256) {
        int c = idx & 127, lv = idx >> 7;
        float4 v4 = *(const float4*)(xb + (size_t)c * L_ + l0 + lv * 4);
        int pc = perm8(c);
        xs[(lv * 4 + 0) * 136 + pc] = tfr(v4.x);
        xs[(lv * 4 + 1) * 136 + pc] = tfr(v4.y);
        xs[(lv * 4 + 2) * 136 + pc] = tfr(v4.z);
        xs[(lv * 4 + 3) * 136 + pc] = tfr(v4.w);
    }

    // weight stage s = ot*2 + kc: 64 o-rows x 64 c-cols into buf (s&1)
    auto issue_w = [&](int s) {
        int ot = s >> 1, kc = s & 1;
        const float* wsrc = (ot < 4) ? g_wqk + (size_t)ot * 64 * C_
                                     : g_wv  + (size_t)(ot - 4) * 64 * C_;
        unsigned dst = ws_u + (unsigned)((s & 1) * 64 * 72) * 4;
        for (int j = tid; j < 1024; j += 256) {
            int o = j >> 4, kv = j & 15;
            cp16(dst + (unsigned)(o * 72 + kv * 4) * 4,
                 wsrc + (size_t)o * C_ + kc * 64 + kv * 4);
        }
    };

    issue_w(0);
    CP_COMMIT();

    float acc[4][4];
    for (int s = 0; s < 16; s++) {
        int ot = s >> 1, kc = s & 1;
        CP_WAIT0();
        __syncthreads();                 // weights landed; xs ready (s=0); prev buf free
        if (s < 15) { issue_w(s + 1); CP_COMMIT(); }

        if (kc == 0) {
            #pragma unroll
            for (int i = 0; i < 4; i++)
                #pragma unroll
                for (int j = 0; j < 4; j++) acc[i][j] = 0.f;
        }
        const float* wb = ws + (s & 1) * (64 * 72);
        #pragma unroll
        for (int kk = 0; kk < 8; kk++) {
            int kg = kc * 64 + kk * 8;
            int kb = kk * 8;
            float2 aA = *(float2*)(xs + (m0 + row) * 136 + kg + 2 * quad);
            float2 aB = *(float2*)(xs + (m0 + row + 8) * 136 + kg + 2 * quad);
            #pragma unroll
            for (int nt = 0; nt < 4; nt++) {
                float2 bv = *(float2*)(wb + (n0 + nt * 8 + row) * 72 + kb + 2 * quad);
                mma_tf32(acc[nt], aA.x, aB.x, aA.y, aB.y, bv.x, bv.y);
            }
        }

        if (kc == 1) {
            if (ot < 4) {
                // Q/K: direct gmem write [l][perm(d)] (C rows are l)
                float* dst = (ot < 2) ? g_q + (size_t)(bs * 2 + ot) * L_ * QKD_
                                      : g_k + (size_t)(bs * 2 + ot - 2) * L_ * QKD_;
                int l = l0 + m0 + row;
                #pragma unroll
                for (int nt = 0; nt < 4; nt++) {
                    int dc = n0 + nt * 8 + 2 * quad;
                    int p0 = perm8(dc), p1 = perm8(dc + 1);
                    dst[(size_t)l * QKD_ + p0]       = tfr(acc[nt][0]);
                    dst[(size_t)l * QKD_ + p1]       = tfr(acc[nt][1]);
                    dst[(size_t)(l + 8) * QKD_ + p0] = tfr(acc[nt][2]);
                    dst[(size_t)(l + 8) * QKD_ + p1] = tfr(acc[nt][3]);
                }
            } else {
                // V: transpose via outs[d][l] (natural l), then coalesced copy
                #pragma unroll
                for (int nt = 0; nt < 4; nt++) {
                    int dc = n0 + nt * 8 + 2 * quad;
                    outs[dc * 72 + m0 + row]           = tfr(acc[nt][0]);
                    outs[(dc + 1) * 72 + m0 + row]     = tfr(acc[nt][1]);
                    outs[dc * 72 + m0 + row + 8]       = tfr(acc[nt][2]);
                    outs[(dc + 1) * 72 + m0 + row + 8] = tfr(acc[nt][3]);
                }
                __syncthreads();
                int o2 = (ot - 4) * 64;
                int head = o2 >> 7, dof = o2 & 127;
                float* dst = g_v + (size_t)(bs * 2 + head) * VD_ * L_;
                for (int idx = tid; idx < 64 * 16; idx += 256) {
                    int o = idx >> 4, j = idx & 15;
                    *(float4*)(dst + (size_t)(dof + o) * L_ + l0 + j * 4) =
                        *(float4*)(outs + o * 72 + j * 4);
                }
            }
        }
    }
}

// ---------------- kernel 3: flash attention, register P + cp.async K/V pipeline ----------------
// Bias from g_lut via linearized index: idx = base(r) - cc(ct), cc(ct+1)=cc(ct)+1 (ct even).
// smem: qs[128][72], ks 2x[64][72] (double-buffered), vt[128][72]
template<int NDT>
__device__ __forceinline__ void attn_tile(int bs, int head, int q0, int m0, int n0v,
                                          float* qs, float* ks, float* vt,
                                          const float* __restrict__ sa_bias) {
    const float* qg = g_q + (size_t)(bs * 2 + head) * L_ * QKD_;
    const float* kg = g_k + (size_t)(bs * 2 + head) * L_ * QKD_;
    const float* vg = g_v + (size_t)(bs * 2 + head) * VD_ * L_;
    const float* lutf = (const float*)g_lut + head;

    unsigned ks_u = (unsigned)__cvta_generic_to_shared(ks);
    unsigned vt_u = (unsigned)__cvta_generic_to_shared(vt);

    int tid = threadIdx.x;
    int lane = tid & 31;
    int row = lane >> 2, quad = lane & 3;

    __syncthreads();   // protect qs/ks/vt from previous tile's readers
    // load q tile [128][64] (d-interleaved), zero-fill rows >= 576
    for (int idx = tid; idx < 128 * 16; idx += 256) {
        int l = idx >> 4, dv = idx & 15;
        float4 v4 = make_float4(0.f, 0.f, 0.f, 0.f);
        if (q0 + l < L_)
            v4 = *(const float4*)(qg + (size_t)(q0 + l) * QKD_ + dv * 4);
        *(float4*)(qs + l * 72 + dv * 4) = v4;
    }

    // prologue: K(0) into ks buf0, V(0) into vt
    for (int j = tid; j < 1024; j += 256) {
        int l = j >> 4, dv = j & 15;
        cp16(ks_u + (unsigned)(l * 72 + dv * 4) * 4, kg + (size_t)l * QKD_ + dv * 4);
    }
    CP_COMMIT();
    for (int j = tid; j < 2048; j += 256) {
        int d = j >> 4, jj = j & 15;
        cp16(vt_u + (unsigned)(d * 72 + jj * 4) * 4, vg + (size_t)d * L_ + jj * 4);
    }
    CP_COMMIT();

    float oac[NDT][4] = {};
    float mr0 = -1e30f, mr1 = -1e30f;
    float lr0 = 0.f, lr1 = 0.f;

    int r0g = q0 + m0 + row;
    int rb0 = (r0g < L_) ? r0g : L_ - 1;
    int rb1 = (r0g + 8 < L_) ? r0g + 8 : L_ - 1;
    // base(r) = r + 23*(r/24) + 23*48  so that base - cc(ct) = (yi-yj+23)*47 + (xi-xj+23)
    int base0 = rb0 + 23 * (rb0 / WID) + 1104;
    int base1 = rb1 + 23 * (rb1 / WID) + 1104;

    for (int kt = 0; kt < 9; kt++) {
        int k0g = kt * 64;
        if (kt > 0) {
            __syncthreads();            // AV(kt-1) done reading vt
            for (int j = tid; j < 2048; j += 256) {
                int d = j >> 4, jj = j & 15;
                cp16(vt_u + (unsigned)(d * 72 + jj * 4) * 4,
                     vg + (size_t)d * L_ + k0g + jj * 4);
            }
            CP_COMMIT();
        }
        CP_WAIT1();                     // K(kt) landed (V(kt) may still fly)
        __syncthreads();

        const float* kb = ks + (kt & 1) * (64 * 72);

        // ---- S = Q K^T : warp m16 x n64 (8 n-tiles), accumulators in regs ----
        float p[8][4] = {};
        #pragma unroll
        for (int kk = 0; kk < 8; kk++) {
            int k0 = kk * 8;
            float2 aA = *(float2*)(qs + (m0 + row) * 72 + k0 + 2 * quad);
            float2 aB = *(float2*)(qs + (m0 + row + 8) * 72 + k0 + 2 * quad);
            #pragma unroll
            for (int nt = 0; nt < 8; nt++) {
                float2 bv = *(float2*)(kb + (nt * 8 + row) * 72 + k0 + 2 * quad);
                mma_tf32(p[nt], aA.x, aB.x, aA.y, aB.y, bv.x, bv.y);
            }
        }
        // scale + bias from LUT (linearized index)
        #pragma unroll
        for (int nt = 0; nt < 8; nt++) {
            int ct = k0g + nt * 8 + 2 * quad;       // even, so cc(ct+1)=cc+1
            int cc = ct + 23 * (ct / WID);
            float b00 = lutf[2 * (base0 - cc)];
            float b01 = lutf[2 * (base0 - cc - 1)];
            float b10 = lutf[2 * (base1 - cc)];
            float b11 = lutf[2 * (base1 - cc - 1)];
            p[nt][0] = p[nt][0] * 0.125f + b00;
            p[nt][1] = p[nt][1] * 0.125f + b01;
            p[nt][2] = p[nt][2] * 0.125f + b10;
            p[nt][3] = p[nt][3] * 0.125f + b11;
        }

        // ---- online softmax in registers (row owned by quad: shuffle xor 1,2) ----
        float tm0 = -1e30f, tm1 = -1e30f;
        #pragma unroll
        for (int nt = 0; nt < 8; nt++) {
            tm0 = fmaxf(tm0, fmaxf(p[nt][0], p[nt][1]));
            tm1 = fmaxf(tm1, fmaxf(p[nt][2], p[nt][3]));
        }
        tm0 = fmaxf(tm0, __shfl_xor_sync(0xffffffffu, tm0, 1));
        tm0 = fmaxf(tm0, __shfl_xor_sync(0xffffffffu, tm0, 2));
        tm1 = fmaxf(tm1, __shfl_xor_sync(0xffffffffu, tm1, 1));
        tm1 = fmaxf(tm1, __shfl_xor_sync(0xffffffffu, tm1, 2));
        float mn0 = fmaxf(mr0, tm0), mn1 = fmaxf(mr1, tm1);
        float al0 = __expf(mr0 - mn0), al1 = __expf(mr1 - mn1);
        mr0 = mn0; mr1 = mn1;

        float s0 = 0.f, s1 = 0.f;
        #pragma unroll
        for (int nt = 0; nt < 8; nt++) {
            float e0 = __expf(p[nt][0] - mn0);
            float e1 = __expf(p[nt][1] - mn0);
            float e2 = __expf(p[nt][2] - mn1);
            float e3 = __expf(p[nt][3] - mn1);
            s0 += e0 + e1; s1 += e2 + e3;
            p[nt][0] = tfr(e0); p[nt][1] = tfr(e1);
            p[nt][2] = tfr(e2); p[nt][3] = tfr(e3);
        }
        s0 += __shfl_xor_sync(0xffffffffu, s0, 1);
        s0 += __shfl_xor_sync(0xffffffffu, s0, 2);
        s1 += __shfl_xor_sync(0xffffffffu, s1, 1);
        s1 += __shfl_xor_sync(0xffffffffu, s1, 2);
        lr0 = al0 * lr0 + s0;
        lr1 = al1 * lr1 + s1;

        CP_WAIT0();                     // V(kt) landed
        __syncthreads();                // V visible; all warps past S(kt) (frees other ks buf)
        if (kt < 8) {                   // prefetch K(kt+1) under AV(kt)
            unsigned kdst = ks_u + (unsigned)(((kt + 1) & 1) * 64 * 72) * 4;
            const float* ksrc = kg + (size_t)(k0g + 64) * QKD_;
            for (int j = tid; j < 1024; j += 256) {
                int l = j >> 4, dv = j & 15;
                cp16(kdst + (unsigned)(l * 72 + dv * 4) * 4, ksrc + (size_t)l * QKD_ + dv * 4);
            }
            CP_COMMIT();
        }

        // ---- AV: P (regs) x V (smem, natural keys); rescale then accumulate ----
        #pragma unroll
        for (int dt = 0; dt < NDT; dt++) {
            oac[dt][0] *= al0; oac[dt][1] *= al0;
            oac[dt][2] *= al1; oac[dt][3] *= al1;
        }
        #pragma unroll
        for (int kb2 = 0; kb2 < 8; kb2++) {
            int kc = kb2 * 8 + 2 * quad;
            #pragma unroll
            for (int dt = 0; dt < NDT; dt++) {
                float2 bv = *(float2*)(vt + (n0v + dt * 8 + row) * 72 + kc);
                mma_tf32(oac[dt], p[kb2][0], p[kb2][2], p[kb2][1], p[kb2][3], bv.x, bv.y);
            }
        }
    }
    CP_WAIT0();                         // drain (no pending groups leak across tiles)

    // ---- epilogue: normalize, + sa_bias, ch-interleaved tf32 write (masked) ----
    float inv0 = 1.0f / lr0;
    float inv1 = 1.0f / lr1;
    float* og = g_att + (size_t)bs * L_ * HID_;
    int l = q0 + m0 + row;
    #pragma unroll
    for (int dt = 0; dt < NDT; dt++) {
        int ch = head * 128 + n0v + dt * 8 + 2 * quad;
        int pc0 = perm8(ch), pc1 = perm8(ch + 1);
        float sb0 = sa_bias[ch], sb1 = sa_bias[ch + 1];
        if (l < L_) {
            og[(size_t)l * HID_ + pc0] = tfr(oac[dt][0] * inv0 + sb0);
            og[(size_t)l * HID_ + pc1] = tfr(oac[dt][1] * inv0 + sb1);
        }
        if (l + 8 < L_) {
            og[(size_t)(l + 8) * HID_ + pc0] = tfr(oac[dt][2] * inv1 + sb0);
            og[(size_t)(l + 8) * HID_ + pc1] = tfr(oac[dt][3] * inv1 + sb1);
        }
    }
}

// grid.x = 576: idx 0..63 pair tiles (both heads' qt4 tails, slow-first), 64..575 full tiles
__global__ void __launch_bounds__(256, 2) attn_kernel(const float* __restrict__ sa_bias) {
    extern __shared__ float sm[];
    float* qs = sm;                    // 128*72
    float* ks = qs + 128 * 72;         // 2 x 64*72
    float* vt = ks + 2 * 64 * 72;      // 128*72

    int warp = threadIdx.x >> 5;
    int idx = blockIdx.x;
    if (idx < 64) {
        int m0  = (warp & 3) * 16;
        int n0v = (warp >> 2) * 64;
        attn_tile<8>(idx, 0, 512, m0, n0v, qs, ks, vt, sa_bias);
        attn_tile<8>(idx, 1, 512, m0, n0v, qs, ks, vt, sa_bias);
    } else {
        int t = idx - 64;
        int bh = t >> 2, qt = t & 3;
        attn_tile<16>(bh >> 1, bh & 1, qt * 128, warp * 16, 0, qs, ks, vt, sa_bias);
    }
}

// ---------------- kernel 4: MLP, cp.async double-buffered weights, 512 threads (R11/R14) ----------------
// smem: xsm[64][264], y1s[64][264], wts 2 x [256][40]
__global__ void mlp_kernel(const float* __restrict__ b1, const float* __restrict__ b2,
                           float* __restrict__ out) {
    int blk = blockIdx.x;                // 0..575
    int bs = blk / 9;
    int l0 = (blk % 9) * 64;
    extern __shared__ float sm[];
    float* xsm = sm;                     // 64*264
    float* y1s = xsm + 64 * 264;         // 64*264
    float* wts = y1s + 64 * 264;         // 2 x 10240

    unsigned wts_u = (unsigned)__cvta_generic_to_shared(wts);

    int tid = threadIdx.x;
    int warp = tid >> 5, lane = tid & 31;
    int row = lane >> 2, quad = lane & 3;

    const float* ag = g_att + ((size_t)bs * L_ + l0) * HID_;
    for (int idx = tid; idx < 64 * 64; idx += 512) {
        int p = idx >> 6, iv = idx & 63;
        *(float4*)(xsm + p * 264 + iv * 4) = *(const float4*)(ag + (size_t)p * HID_ + iv * 4);
    }

    // ---- GEMM1: Y1(64x256) = X @ W1^T : warp tile m32 x n32, k-chunks of 32, double-buffered ----
    int m0 = (warp & 1) * 32;
    int n0 = (warp >> 1) * 32;
    for (int j = tid; j < 2048; j += 512) {
        int o = j >> 3, kv = j & 7;
        cp16(wts_u + (unsigned)(o * 40 + kv * 4) * 4,
             g_w1p + (size_t)o * HID_ + kv * 4);
    }
    CP_COMMIT();

    float acc[2][4][4] = {};
    for (int c = 0; c < 8; c++) {
        CP_WAIT0();
        __syncthreads();
        if (c < 7) {
            int b = (c + 1) & 1;
            for (int j = tid; j < 2048; j += 512) {
                int o = j >> 3, kv = j & 7;
                cp16(wts_u + (unsigned)(b * 10240 + o * 40 + kv * 4) * 4,
                     g_w1p + (size_t)o * HID_ + (c + 1) * 32 + kv * 4);
            }
            CP_COMMIT();
        }
        const float* wb = wts + (c & 1) * 10240;
        #pragma unroll
        for (int kk = 0; kk < 4; kk++) {
            int kg = c * 32 + kk * 8;
            int kb = kk * 8;
            float2 aA[2], aB[2];
            #pragma unroll
            for (int mt = 0; mt < 2; mt++) {
                aA[mt] = *(float2*)(xsm + (m0 + mt * 16 + row) * 264 + kg + 2 * quad);
                aB[mt] = *(float2*)(xsm + (m0 + mt * 16 + row + 8) * 264 + kg + 2 * quad);
            }
            #pragma unroll
            for (int nt = 0; nt < 4; nt++) {
                float2 bv = *(float2*)(wb + (n0 + nt * 8 + row) * 40 + kb + 2 * quad);
                mma_tf32(acc[0][nt], aA[0].x, aB[0].x, aA[0].y, aB[0].y, bv.x, bv.y);
                mma_tf32(acc[1][nt], aA[1].x, aB[1].x, aA[1].y, aB[1].y, bv.x, bv.y);
            }
        }
    }
    // bias + exact GELU -> y1s[p][perm(o)], tf32-rounded
    #pragma unroll
    for (int mt = 0; mt < 2; mt++) {
        #pragma unroll
        for (int nt = 0; nt < 4; nt++) {
            int col = n0 + nt * 8 + 2 * quad;
            int p0 = perm8(col), p1 = perm8(col + 1);
            float bb0 = b1[col], bb1 = b1[col + 1];
            int r = m0 + mt * 16 + row;
            float v0 = acc[mt][nt][0] + bb0;
            float v1 = acc[mt][nt][1] + bb1;
            float v2 = acc[mt][nt][2] + bb0;
            float v3 = acc[mt][nt][3] + bb1;
            y1s[r * 264 + p0]       = tfr(0.5f * v0 * (1.0f + erff(v0 * 0.70710678118654752f)));
            y1s[r * 264 + p1]       = tfr(0.5f * v1 * (1.0f + erff(v1 * 0.70710678118654752f)));
            y1s[(r + 8) * 264 + p0] = tfr(0.5f * v2 * (1.0f + erff(v2 * 0.70710678118654752f)));
            y1s[(r + 8) * 264 + p1] = tfr(0.5f * v3 * (1.0f + erff(v3 * 0.70710678118654752f)));
        }
    }
    __syncthreads();

    // ---- GEMM2: OUT(64x128) = Y1 @ W2^T : warp tile m16 x n32, k-chunks of 32, double-buffered ----
    int m0b = (warp & 3) * 16;
    int n0b = (warp >> 2) * 32;
    for (int j = tid; j < 1024; j += 512) {
        int o = j >> 3, kv = j & 7;
        cp16(wts_u + (unsigned)(o * 40 + kv * 4) * 4,
             g_w2p + (size_t)o * HID_ + kv * 4);
    }
    CP_COMMIT();

    float ac2[4][4] = {};
    for (int c = 0; c < 8; c++) {
        CP_WAIT0();
        __syncthreads();
        if (c < 7) {
            int b = (c + 1) & 1;
            for (int j = tid; j < 1024; j += 512) {
                int o = j >> 3, kv = j & 7;
                cp16(wts_u + (unsigned)(b * 10240 + o * 40 + kv * 4) * 4,
                     g_w2p + (size_t)o * HID_ + (c + 1) * 32 + kv * 4);
            }
            CP_COMMIT();
        }
        const float* wb = wts + (c & 1) * 10240;
        #pragma unroll
        for (int kk = 0; kk < 4; kk++) {
            int kg = c * 32 + kk * 8;
            int kb = kk * 8;
            float2 aA = *(float2*)(y1s + (m0b + row) * 264 + kg + 2 * quad);
            float2 aB = *(float2*)(y1s + (m0b + row + 8) * 264 + kg + 2 * quad);
            #pragma unroll
            for (int nt = 0; nt < 4; nt++) {
                float2 bv = *(float2*)(wb + (n0b + nt * 8 + row) * 40 + kb + 2 * quad);
                mma_tf32(ac2[nt], aA.x, aB.x, aA.y, aB.y, bv.x, bv.y);
            }
        }
    }

    // ---- epilogue: + b2, write (bs, o, l) ----
    float* og = out + (size_t)bs * OUTC_ * L_;
    int l = l0 + m0b + row;
    #pragma unroll
    for (int nt = 0; nt < 4; nt++) {
        int col = n0b + nt * 8 + 2 * quad;
        float bb0 = b2[col], bb1 = b2[col + 1];
        og[(size_t)col * L_ + l]           = ac2[nt][0] + bb0;
        og[(size_t)(col + 1) * L_ + l]     = ac2[nt][1] + bb1;
        og[(size_t)col * L_ + l + 8]       = ac2[nt][2] + bb0;
        og[(size_t)(col + 1) * L_ + l + 8] = ac2[nt][3] + bb1;
    }
}

// ---------------- launch ----------------
extern "C" void kernel_launch(void* const* d_in, const int* in_sizes, int n_in,
                              void* d_out, int out_size) {
    const float* x      = (const float*)d_in[0];
    const float* qk_w   = (const float*)d_in[1];
    const float* v_w    = (const float*)d_in[2];
    const float* cpb_w1 = (const float*)d_in[3];
    const float* cpb_b1 = (const float*)d_in[4];
    const float* cpb_w2 = (const float*)d_in[5];
    const float* sa_b   = (const float*)d_in[6];
    const float* mlp_b1 = (const float*)d_in[8];
    const float* mlp_b2 = (const float*)d_in[10];
    float* out = (float*)d_out;

    const int SMEM_QKV = (64 * 136 + 2 * 64 * 72 + 64 * 72) * 4;               // 90112
    const int SMEM_ATT = (128 * 72 + 2 * 64 * 72 + 128 * 72) * 4;              // 110592
    const int SMEM_MLP = (64 * 264 * 2 + 2 * 256 * 40) * 4;                    // 217088

    cudaFuncSetAttribute(qkv_kernel,  cudaFuncAttributeMaxDynamicSharedMemorySize, SMEM_QKV);
    cudaFuncSetAttribute(attn_kernel, cudaFuncAttributeMaxDynamicSharedMemorySize, SMEM_ATT);
    cudaFuncSetAttribute(mlp_kernel,  cudaFuncAttributeMaxDynamicSharedMemorySize, SMEM_MLP);

    prep_kernel<<<640, 256>>>(qk_w, v_w, (const float*)d_in[7], (const float*)d_in[9]);
    cpb_lut_kernel<<<9, 256>>>(cpb_w1, cpb_b1, cpb_w2);
    qkv_kernel<<<dim3(9, BS_), 256, SMEM_QKV>>>(x);
    attn_kernel<<<576, 256, SMEM_ATT>>>(sa_b);
    mlp_kernel<<<BS_ * 9, 512, SMEM_MLP>>>(mlp_b1, mlp_b2, out);
}